// round 6
// baseline (speedup 1.0000x reference)
#include <cuda_runtime.h>
#include <cuda_bf16.h>
#include <cstdint>

#define HWP 3600
#define NBATCH 2
#define CDIM 256
#define KNN 64
#define M_TOTAL (NBATCH*HWP)   // 7200
#define MPAD 7296              // padded rows (multiple of 128)

// ---------------- scratch (device globals; no allocation allowed) ----------
__device__ float g_m[MPAD*CDIM];        // relu(mlp(h)) fp32
__device__ float g_tmp[MPAD*CDIM];      // h @ Wa^T fp32
__device__ float g_h[MPAD*CDIM];        // fp32 h (for final readout)
__device__ __nv_bfloat16 g_Ah[MPAD*CDIM], g_Al[MPAD*CDIM];   // h split
__device__ __nv_bfloat16 g_Mh[MPAD*CDIM], g_Ml[MPAD*CDIM];   // msg split
__device__ __nv_bfloat16 g_Wmh[CDIM*CDIM], g_Wml[CDIM*CDIM]; // mlp_w split
__device__ __nv_bfloat16 g_Wah[CDIM*CDIM], g_Wal[CDIM*CDIM]; // rnn_w[:, :C]
__device__ __nv_bfloat16 g_Wbh[CDIM*CDIM], g_Wbl[CDIM*CDIM]; // rnn_w[:, C:]
__device__ int   g_idx[M_TOTAL*KNN];

__device__ __forceinline__ float4 ld4(const float* p){ return *reinterpret_cast<const float4*>(p); }
__device__ __forceinline__ void st4(float* p, float4 v){ *reinterpret_cast<float4*>(p) = v; }

__device__ __forceinline__ void bsplit(float v, __nv_bfloat16& h, __nv_bfloat16& l){
    h = __float2bfloat16(v);
    l = __float2bfloat16(v - __bfloat162float(h));
}

__device__ __forceinline__ uint32_t smem_u32(const void* p) {
    uint32_t a;
    asm("{ .reg .u64 t; cvta.to.shared.u64 t, %1; cvt.u32.u64 %0, t; }" : "=r"(a) : "l"(p));
    return a;
}

// ---------------- mma.sync helpers (suffix-neutral PTX, tensor pipe) -------
__device__ __forceinline__ void ldmat4(uint32_t r[4], uint32_t addr){
    asm volatile("ldmatrix.sync.aligned.m8n8.x4.shared.b16 {%0,%1,%2,%3}, [%4];"
        : "=r"(r[0]), "=r"(r[1]), "=r"(r[2]), "=r"(r[3]) : "r"(addr));
}
__device__ __forceinline__ void mma16816(float c[4], const uint32_t a[4],
                                         uint32_t b0, uint32_t b1){
    asm volatile("mma.sync.aligned.m16n8k16.row.col.f32.bf16.bf16.f32 "
        "{%0,%1,%2,%3}, {%4,%5,%6,%7}, {%8,%9}, {%0,%1,%2,%3};"
        : "+f"(c[0]), "+f"(c[1]), "+f"(c[2]), "+f"(c[3])
        : "r"(a[0]), "r"(a[1]), "r"(a[2]), "r"(a[3]), "r"(b0), "r"(b1));
}

// smem tile layout: padded stride 72 bf16 (144B = 9 x 16B -> conflict-free)
#define ASTRIDE 72
#define OFF_AH  0
#define OFF_AL  18432
#define OFF_BH  36864
#define OFF_BL  46080
#define GEMM_SMEM 55296

// ---- 128x64x256 tile: bf16 3-term split via mma.sync, fp32 accumulate -----
__device__ void tile_mma(const __nv_bfloat16* __restrict__ Ah,
                         const __nv_bfloat16* __restrict__ Al,
                         const __nv_bfloat16* __restrict__ Bh,
                         const __nv_bfloat16* __restrict__ Bl,
                         int m0, float acc[2][4][4])
{
    extern __shared__ char smem[];
    const uint32_t sb = smem_u32(smem);
    const int tid = threadIdx.x;
    const int lane = tid & 31;
    const int wid = tid >> 5;
    const int wm = wid & 3;        // m32 section
    const int wn = wid >> 2;       // n32 section

    #pragma unroll
    for (int mt = 0; mt < 2; ++mt)
        #pragma unroll
        for (int nt = 0; nt < 4; ++nt)
            #pragma unroll
            for (int q = 0; q < 4; ++q) acc[mt][nt][q] = 0.f;

    const uint32_t aoff = (uint32_t)(((lane & 15)*ASTRIDE + (lane >> 4)*8) * 2);
    const uint32_t boff = (uint32_t)((((lane & 7) + ((lane >> 4) << 3))*ASTRIDE
                                      + ((lane >> 3) & 1)*8) * 2);

    #pragma unroll 1
    for (int kc = 0; kc < 4; ++kc) {
        #pragma unroll
        for (int i = 0; i < 12; ++i) {
            int v = tid + i*256;
            const uint4* src;
            uint32_t dst;
            if (v < 1024) {
                int row = v >> 3, c8 = v & 7;
                src = (const uint4*)(Ah + (m0 + row)*CDIM + kc*64 + c8*8);
                dst = OFF_AH + (uint32_t)(row*ASTRIDE + c8*8)*2;
            } else if (v < 2048) {
                int u = v - 1024, row = u >> 3, c8 = u & 7;
                src = (const uint4*)(Al + (m0 + row)*CDIM + kc*64 + c8*8);
                dst = OFF_AL + (uint32_t)(row*ASTRIDE + c8*8)*2;
            } else if (v < 2560) {
                int u = v - 2048, row = u >> 3, c8 = u & 7;
                src = (const uint4*)(Bh + row*CDIM + kc*64 + c8*8);
                dst = OFF_BH + (uint32_t)(row*ASTRIDE + c8*8)*2;
            } else {
                int u = v - 2560, row = u >> 3, c8 = u & 7;
                src = (const uint4*)(Bl + row*CDIM + kc*64 + c8*8);
                dst = OFF_BL + (uint32_t)(row*ASTRIDE + c8*8)*2;
            }
            *(uint4*)(smem + dst) = *src;
        }
        __syncthreads();

        #pragma unroll
        for (int ks = 0; ks < 4; ++ks) {
            const uint32_t abase = (uint32_t)((wm*32*ASTRIDE + ks*16) * 2);
            const uint32_t bbase = (uint32_t)((wn*32*ASTRIDE + ks*16) * 2);
            const uint32_t mstep = (uint32_t)(16*ASTRIDE*2);

            uint32_t ah0[4], ah1[4], al0[4], al1[4];
            ldmat4(ah0, sb + OFF_AH + abase + aoff);
            ldmat4(ah1, sb + OFF_AH + abase + mstep + aoff);
            ldmat4(al0, sb + OFF_AL + abase + aoff);
            ldmat4(al1, sb + OFF_AL + abase + mstep + aoff);

            uint32_t bhA[4], bhB[4], blA[4], blB[4];
            ldmat4(bhA, sb + OFF_BH + bbase + boff);
            ldmat4(bhB, sb + OFF_BH + bbase + mstep + boff);
            ldmat4(blA, sb + OFF_BL + bbase + boff);
            ldmat4(blB, sb + OFF_BL + bbase + mstep + boff);

            mma16816(acc[0][0], ah0, bhA[0], bhA[1]);
            mma16816(acc[0][1], ah0, bhA[2], bhA[3]);
            mma16816(acc[0][2], ah0, bhB[0], bhB[1]);
            mma16816(acc[0][3], ah0, bhB[2], bhB[3]);
            mma16816(acc[1][0], ah1, bhA[0], bhA[1]);
            mma16816(acc[1][1], ah1, bhA[2], bhA[3]);
            mma16816(acc[1][2], ah1, bhB[0], bhB[1]);
            mma16816(acc[1][3], ah1, bhB[2], bhB[3]);

            mma16816(acc[0][0], ah0, blA[0], blA[1]);
            mma16816(acc[0][1], ah0, blA[2], blA[3]);
            mma16816(acc[0][2], ah0, blB[0], blB[1]);
            mma16816(acc[0][3], ah0, blB[2], blB[3]);
            mma16816(acc[1][0], ah1, blA[0], blA[1]);
            mma16816(acc[1][1], ah1, blA[2], blA[3]);
            mma16816(acc[1][2], ah1, blB[0], blB[1]);
            mma16816(acc[1][3], ah1, blB[2], blB[3]);

            mma16816(acc[0][0], al0, bhA[0], bhA[1]);
            mma16816(acc[0][1], al0, bhA[2], bhA[3]);
            mma16816(acc[0][2], al0, bhB[0], bhB[1]);
            mma16816(acc[0][3], al0, bhB[2], bhB[3]);
            mma16816(acc[1][0], al1, bhA[0], bhA[1]);
            mma16816(acc[1][1], al1, bhA[2], bhA[3]);
            mma16816(acc[1][2], al1, bhB[0], bhB[1]);
            mma16816(acc[1][3], al1, bhB[2], bhB[3]);
        }
        __syncthreads();
    }
}

// GEMM1: by 0..3 -> m = relu(h Wmlp^T + b);  by 4..7 -> tmp = h Wa^T
__global__ void __launch_bounds__(256) gemm1_kernel(const float* __restrict__ mlp_b,
                                                    float* __restrict__ m_out,
                                                    float* __restrict__ tmp_out)
{
    int m0 = blockIdx.x * 128;
    int by = blockIdx.y;
    bool is_m = by < 4;
    int d0 = (is_m ? by : by - 4) * 64;
    const __nv_bfloat16* Bh = (is_m ? g_Wmh : g_Wah) + d0*CDIM;
    const __nv_bfloat16* Bl = (is_m ? g_Wml : g_Wal) + d0*CDIM;

    float acc[2][4][4];
    tile_mma(g_Ah, g_Al, Bh, Bl, m0, acc);

    int lane = threadIdx.x & 31, wid = threadIdx.x >> 5;
    int wm = wid & 3, wn = wid >> 2;
    int g = lane >> 2, t = lane & 3;

    #pragma unroll
    for (int mt = 0; mt < 2; ++mt) {
        #pragma unroll
        for (int nt = 0; nt < 4; ++nt) {
            int nl = wn*32 + nt*8 + t*2;
            int n = d0 + nl;
            float bx = 0.f, byv = 0.f;
            if (is_m) { bx = mlp_b[n]; byv = mlp_b[n+1]; }
            #pragma unroll
            for (int half = 0; half < 2; ++half) {
                int m = m0 + wm*32 + mt*16 + g + half*8;
                if (m >= M_TOTAL) continue;
                float vx = acc[mt][nt][half*2+0];
                float vy = acc[mt][nt][half*2+1];
                if (is_m) {
                    vx = fmaxf(vx + bx, 0.f);
                    vy = fmaxf(vy + byv, 0.f);
                    *(float2*)(m_out + m*CDIM + n) = make_float2(vx, vy);
                } else {
                    *(float2*)(tmp_out + m*CDIM + n) = make_float2(vx, vy);
                }
            }
        }
    }
}

// GEMM3: h' = relu(tmp + msg Wb^T + b_rnn); writes fp32 h and bf16 split
__global__ void __launch_bounds__(256) gemm3_kernel(const float* __restrict__ rnn_b,
                                                    const float* __restrict__ tmp,
                                                    float* __restrict__ h_out)
{
    int m0 = blockIdx.x * 128;
    int d0 = blockIdx.y * 64;

    float acc[2][4][4];
    tile_mma(g_Mh, g_Ml, g_Wbh + d0*CDIM, g_Wbl + d0*CDIM, m0, acc);

    int lane = threadIdx.x & 31, wid = threadIdx.x >> 5;
    int wm = wid & 3, wn = wid >> 2;
    int g = lane >> 2, t = lane & 3;

    #pragma unroll
    for (int mt = 0; mt < 2; ++mt) {
        #pragma unroll
        for (int nt = 0; nt < 4; ++nt) {
            int n = d0 + wn*32 + nt*8 + t*2;
            float bx = rnn_b[n], byv = rnn_b[n+1];
            #pragma unroll
            for (int half = 0; half < 2; ++half) {
                int m = m0 + wm*32 + mt*16 + g + half*8;
                if (m >= M_TOTAL) continue;
                float2 tv = *(const float2*)(tmp + m*CDIM + n);
                float vx = fmaxf(acc[mt][nt][half*2+0] + tv.x + bx, 0.f);
                float vy = fmaxf(acc[mt][nt][half*2+1] + tv.y + byv, 0.f);
                *(float2*)(h_out + m*CDIM + n) = make_float2(vx, vy);
                __nv_bfloat16 hx, lx, hy, ly;
                bsplit(vx, hx, lx); bsplit(vy, hy, ly);
                *(__nv_bfloat162*)(g_Ah + m*CDIM + n) = __nv_bfloat162(hx, hy);
                *(__nv_bfloat162*)(g_Al + m*CDIM + n) = __nv_bfloat162(lx, ly);
            }
        }
    }
}

// ---------------- weight conversion (once per call) ------------------------
__global__ void __launch_bounds__(256) wconv_kernel(const float* __restrict__ mlp_w,
                                                    const float* __restrict__ rnn_w)
{
    int e = blockIdx.x * 256 + threadIdx.x;   // < 256*768
    if (e < CDIM*CDIM) {
        __nv_bfloat16 h, l; bsplit(mlp_w[e], h, l);
        g_Wmh[e] = h; g_Wml[e] = l;
    } else {
        int u = e - CDIM*CDIM;                 // < 256*512
        int r = u >> 9, c = u & 511;
        __nv_bfloat16 h, l; bsplit(rnn_w[u], h, l);
        if (c < CDIM) { g_Wah[r*CDIM + c] = h; g_Wal[r*CDIM + c] = l; }
        else          { g_Wbh[r*CDIM + c - CDIM] = h; g_Wbl[r*CDIM + c - CDIM] = l; }
    }
}

// zero padded rows of bf16 operand arrays
__global__ void __launch_bounds__(256) pad_kernel()
{
    int e = blockIdx.x * 256 + threadIdx.x;   // < 96*256
    int o = (M_TOTAL + (e >> 8))*CDIM + (e & 255);
    g_Ah[o] = __float2bfloat16(0.f); g_Al[o] = __float2bfloat16(0.f);
    g_Mh[o] = __float2bfloat16(0.f); g_Ml[o] = __float2bfloat16(0.f);
}

// ---------------- init: out[:, :256] = cnn; Ah/Al = bf16 split of NHWC h0 --
__global__ void __launch_bounds__(256) init_kernel(const float* __restrict__ cnn,
                                                   float* __restrict__ out)
{
    int e = blockIdx.x * 256 + threadIdx.x;
    int s = e % HWP;
    int c = (e / HWP) & (CDIM-1);
    int n = e / (HWP*CDIM);
    float v = cnn[e];
    out[(n*(2*CDIM) + c)*HWP + s] = v;
    __nv_bfloat16 h, l; bsplit(v, h, l);
    int o = (n*HWP + s)*CDIM + c;
    g_Ah[o] = h; g_Al[o] = l;
}

__global__ void __launch_bounds__(256) final_kernel(const float* __restrict__ h,
                                                    float* __restrict__ out)
{
    int e = blockIdx.x * 256 + threadIdx.x;
    int s = e % HWP;
    int c = (e / HWP) & (CDIM-1);
    int n = e / (HWP*CDIM);
    out[(n*(2*CDIM) + CDIM + c)*HWP + s] = h[(n*HWP + s)*CDIM + c];
}

// ---------------- KNN v3: warp-per-row exponent radix select ---------------
// 8 warps/block, each warp owns ROWS_PW rows end-to-end. No block barriers
// in steady state; ballot/popc positions instead of atomics; warp-local
// 23-bit search within the critical exponent bin; warp-local 31-bit
// recompute fallback (correct for any data).
#define ROWS_PW 3
#define KNN_CAP 512
// dynamic smem layout (bytes)
#define KS_PTS   0                       // float4[3600]            57600
#define KS_HIST  57600                   // int[8][256]              8192
#define KS_CV    65792                   // unsigned[8][KNN_CAP]    16384
#define KS_CI    82176                   // int[8][KNN_CAP]         16384
#define KS_TIE   98560                   // int[8][32]               1024
#define KNN_SMEM 99584

__global__ void __launch_bounds__(256) knn_kernel(const float* __restrict__ pts,
                                                  int* __restrict__ idx_out)
{
    extern __shared__ char sm[];
    float4*   sp   = (float4*)(sm + KS_PTS);
    int*      hist = (int*)(sm + KS_HIST);
    unsigned* cv   = (unsigned*)(sm + KS_CV);
    int*      ci   = (int*)(sm + KS_CI);
    int*      tie  = (int*)(sm + KS_TIE);

    const int b = blockIdx.x;
    const int n = b / (HWP / (8*ROWS_PW));          // 150 blocks per batch
    const int rb = (b % (HWP / (8*ROWS_PW))) * (8*ROWS_PW);
    const int tid = threadIdx.x, lane = tid & 31, wid = tid >> 5;
    const unsigned ltm = (1u << lane) - 1u;

    int*      whist = hist + wid*256;
    unsigned* wcv   = cv + wid*KNN_CAP;
    int*      wci   = ci + wid*KNN_CAP;
    int*      wtie  = tie + wid*32;

    const float* p = pts + n*3*HWP;
    for (int i = tid; i < HWP; i += 256) {
        float x = p[i], y = p[i + HWP], z = p[i + 2*HWP];
        sp[i] = make_float4(x, y, z, fmaf(z, z, fmaf(y, y, x*x)));
    }
    __syncthreads();

    for (int r = 0; r < ROWS_PW; ++r) {
        const int row = rb + wid*ROWS_PW + r;
        const float4 q = sp[row];

        // zero warp histogram
        #pragma unroll
        for (int i = 0; i < 8; ++i) whist[lane*8 + i] = 0;
        __syncwarp();

        // pass 1: exponent histogram (pads -> bin 255, harmless)
        for (int base = 0; base < HWP; base += 32) {
            int j = base + lane;
            unsigned bits = 0x7f800000u;
            if (j < HWP) {
                float4 pj = sp[j];
                float dot = fmaf(q.z, pj.z, fmaf(q.y, pj.y, q.x*pj.x));
                bits = __float_as_uint(fmaxf(q.w + pj.w - 2.0f*dot, 0.0f));
            }
            unsigned e = bits >> 23;
            unsigned mask = __match_any_sync(0xffffffffu, e);
            if (lane == (unsigned)(__ffs(mask) - 1)) atomicAdd(&whist[e], __popc(mask));
        }
        __syncwarp();

        // warp scan over 256 bins -> critical bin + count below
        int E = 0;
        {
            int basebin = lane*8, loc[8], ssum = 0;
            #pragma unroll
            for (int j2 = 0; j2 < 8; ++j2) { loc[j2] = whist[basebin + j2]; ssum += loc[j2]; }
            int pre = ssum;
            #pragma unroll
            for (int o = 1; o < 32; o <<= 1) {
                int v = __shfl_up_sync(0xffffffffu, pre, o);
                if (lane >= (unsigned)o) pre += v;
            }
            int excl = pre - ssum;
            int ec = 0;
            if (excl < KNN && excl + ssum >= KNN) {
                int cum = excl;
                #pragma unroll
                for (int j2 = 0; j2 < 8; ++j2) {
                    if (cum + loc[j2] >= KNN) { ec = basebin + j2; break; }
                    cum += loc[j2];
                }
            }
            E = __reduce_max_sync(0xffffffffu, ec);
        }

        int* outp = idx_out + (n*HWP + row)*KNN;

        // pass 2: recompute; winners (e<E) straight out, candidates (e==E) compact
        int outcnt = 0, ccnt = 0;
        for (int base = 0; base < HWP; base += 32) {
            int j = base + lane;
            unsigned bits = 0x7f800000u;
            if (j < HWP) {
                float4 pj = sp[j];
                float dot = fmaf(q.z, pj.z, fmaf(q.y, pj.y, q.x*pj.x));
                bits = __float_as_uint(fmaxf(q.w + pj.w - 2.0f*dot, 0.0f));
            }
            int e = (int)(bits >> 23);
            bool v = j < HWP;
            unsigned mw = __ballot_sync(0xffffffffu, v && e < E);
            if (v && e < E) outp[outcnt + __popc(mw & ltm)] = j;
            outcnt += __popc(mw);
            unsigned mc = __ballot_sync(0xffffffffu, v && e == E);
            if (v && e == E) {
                int pos = ccnt + __popc(mc & ltm);
                if (pos < KNN_CAP) { wcv[pos] = bits; wci[pos] = j; }
            }
            ccnt += __popc(mc);
        }
        __syncwarp();

        int Kp = KNN - outcnt;
        if (ccnt == Kp) {
            for (int i = lane; i < ccnt; i += 32) outp[outcnt + i] = wci[i];
        } else if (ccnt <= KNN_CAP) {
            // warp-local 23-bit search within the critical bin
            unsigned T = ((unsigned)E) << 23;
            for (int bit = 22; bit >= 0; --bit) {
                unsigned cnd = T | (1u << bit);
                int cnt = 0;
                for (int i = lane; i < ccnt; i += 32) cnt += (wcv[i] < cnd) ? 1 : 0;
                cnt = __reduce_add_sync(0xffffffffu, cnt);
                if (cnt < Kp) T = cnd;
            }
            int oc = outcnt, tc = 0;
            for (int ib = 0; ib < ccnt; ib += 32) {
                int i = ib + lane;
                bool v = i < ccnt;
                unsigned bv = v ? wcv[i] : 0xffffffffu;
                unsigned mw = __ballot_sync(0xffffffffu, v && bv < T);
                if (v && bv < T) outp[oc + __popc(mw & ltm)] = wci[i];
                oc += __popc(mw);
                unsigned mt = __ballot_sync(0xffffffffu, v && bv == T);
                if (v && bv == T) {
                    int tp = tc + __popc(mt & ltm);
                    if (tp < 32) wtie[tp] = wci[i];
                }
                tc += __popc(mt);
            }
            __syncwarp();
            if (lane == 0) {
                int slots = KNN - oc;
                int en = tc < 32 ? tc : 32;
                for (int q2 = 0; q2 < slots; ++q2) {     // lowest-index tie fill
                    int best = 0x7fffffff, bi = 0;
                    for (int e2 = 0; e2 < en; ++e2)
                        if (wtie[e2] < best) { best = wtie[e2]; bi = e2; }
                    wtie[bi] = 0x7fffffff;
                    outp[oc + q2] = best;
                }
            }
        } else {
            // fallback: warp-local 31-bit search with recompute (rare, correct)
            unsigned T = 0;
            for (int bit = 30; bit >= 0; --bit) {
                unsigned cnd = T | (1u << bit);
                int cnt = 0;
                for (int base = 0; base < HWP; base += 32) {
                    int j = base + lane;
                    if (j < HWP) {
                        float4 pj = sp[j];
                        float dot = fmaf(q.z, pj.z, fmaf(q.y, pj.y, q.x*pj.x));
                        unsigned bits = __float_as_uint(fmaxf(q.w + pj.w - 2.0f*dot, 0.0f));
                        cnt += (bits < cnd) ? 1 : 0;
                    }
                }
                cnt = __reduce_add_sync(0xffffffffu, cnt);
                if (cnt < KNN) T = cnd;
            }
            int oc = 0, tc = 0;
            for (int base = 0; base < HWP; base += 32) {
                int j = base + lane;
                unsigned bits = 0xffffffffu;
                if (j < HWP) {
                    float4 pj = sp[j];
                    float dot = fmaf(q.z, pj.z, fmaf(q.y, pj.y, q.x*pj.x));
                    bits = __float_as_uint(fmaxf(q.w + pj.w - 2.0f*dot, 0.0f));
                }
                bool v = j < HWP;
                unsigned mw = __ballot_sync(0xffffffffu, v && bits < T);
                if (v && bits < T) outp[oc + __popc(mw & ltm)] = j;
                oc += __popc(mw);
                unsigned mt = __ballot_sync(0xffffffffu, v && bits == T);
                if (v && bits == T) {
                    int tp = tc + __popc(mt & ltm);
                    if (tp < 32) wtie[tp] = j;
                }
                tc += __popc(mt);
            }
            __syncwarp();
            if (lane == 0) {
                int slots = KNN - oc;
                int en = tc < 32 ? tc : 32;
                for (int q2 = 0; q2 < slots; ++q2) {
                    int best = 0x7fffffff, bi = 0;
                    for (int e2 = 0; e2 < en; ++e2)
                        if (wtie[e2] < best) { best = wtie[e2]; bi = e2; }
                    wtie[bi] = 0x7fffffff;
                    outp[oc + q2] = best;
                }
            }
        }
        __syncwarp();
    }
}

// ---------------- gather-mean: msg = mean_k m[idx]; emits bf16 split -------
__global__ void __launch_bounds__(512) gather_mean_kernel(const float* __restrict__ m,
                                                          const int* __restrict__ idx)
{
    __shared__ int sidx[8*KNN];
    int tid = threadIdx.x;
    int s0 = blockIdx.x * 8;
    sidx[tid] = idx[s0*KNN + tid];
    __syncthreads();

    int lp = tid >> 6;
    int c4 = tid & 63;
    int s  = s0 + lp;
    int base = (s / HWP) * HWP;
    const float4* m4 = reinterpret_cast<const float4*>(m);
    const int* ip = sidx + lp*KNN;

    float4 a0 = make_float4(0,0,0,0), a1 = a0, a2 = a0, a3 = a0;
    #pragma unroll
    for (int k = 0; k < KNN; k += 4) {
        int j0 = ip[k], j1 = ip[k+1], j2 = ip[k+2], j3 = ip[k+3];
        float4 v0 = m4[(size_t)(base + j0)*64 + c4];
        float4 v1 = m4[(size_t)(base + j1)*64 + c4];
        float4 v2 = m4[(size_t)(base + j2)*64 + c4];
        float4 v3 = m4[(size_t)(base + j3)*64 + c4];
        a0.x += v0.x; a0.y += v0.y; a0.z += v0.z; a0.w += v0.w;
        a1.x += v1.x; a1.y += v1.y; a1.z += v1.z; a1.w += v1.w;
        a2.x += v2.x; a2.y += v2.y; a2.z += v2.z; a2.w += v2.w;
        a3.x += v3.x; a3.y += v3.y; a3.z += v3.z; a3.w += v3.w;
    }
    const float inv = 1.0f / 64.0f;
    float4 r;
    r.x = (a0.x + a1.x + a2.x + a3.x) * inv;
    r.y = (a0.y + a1.y + a2.y + a3.y) * inv;
    r.z = (a0.z + a1.z + a2.z + a3.z) * inv;
    r.w = (a0.w + a1.w + a2.w + a3.w) * inv;

    __nv_bfloat16 hx, lx, hy, ly, hz, lz, hw, lw;
    bsplit(r.x, hx, lx); bsplit(r.y, hy, ly);
    bsplit(r.z, hz, lz); bsplit(r.w, hw, lw);
    int o = s*CDIM + c4*4;
    *(__nv_bfloat162*)(g_Mh + o)     = __nv_bfloat162(hx, hy);
    *(__nv_bfloat162*)(g_Mh + o + 2) = __nv_bfloat162(hz, hw);
    *(__nv_bfloat162*)(g_Ml + o)     = __nv_bfloat162(lx, ly);
    *(__nv_bfloat162*)(g_Ml + o + 2) = __nv_bfloat162(lz, lw);
}

// ---------------- launcher --------------------------------------------------
extern "C" void kernel_launch(void* const* d_in, const int* in_sizes, int n_in,
                              void* d_out, int out_size)
{
    const float* cnn   = (const float*)d_in[0];
    const float* pts   = (const float*)d_in[1];
    const float* mlp_w = (const float*)d_in[2];
    const float* mlp_b = (const float*)d_in[3];
    const float* rnn_w = (const float*)d_in[4];
    const float* rnn_b = (const float*)d_in[5];
    float* out = (float*)d_out;

    float *m, *tmp, *h;
    int* idx;
    cudaGetSymbolAddress((void**)&m,   g_m);
    cudaGetSymbolAddress((void**)&tmp, g_tmp);
    cudaGetSymbolAddress((void**)&h,   g_h);
    cudaGetSymbolAddress((void**)&idx, g_idx);

    cudaFuncSetAttribute(gemm1_kernel, cudaFuncAttributeMaxDynamicSharedMemorySize, GEMM_SMEM);
    cudaFuncSetAttribute(gemm3_kernel, cudaFuncAttributeMaxDynamicSharedMemorySize, GEMM_SMEM);
    cudaFuncSetAttribute(knn_kernel,   cudaFuncAttributeMaxDynamicSharedMemorySize, KNN_SMEM);

    wconv_kernel<<<768, 256>>>(mlp_w, rnn_w);
    init_kernel<<<(NBATCH*CDIM*HWP)/256, 256>>>(cnn, out);
    pad_kernel<<<96, 256>>>();
    knn_kernel<<<NBATCH*(HWP/(8*ROWS_PW)), 256, KNN_SMEM>>>(pts, idx);

    for (int it = 0; it < 3; ++it) {
        gemm1_kernel<<<dim3(MPAD/128, 8), 256, GEMM_SMEM>>>(mlp_b, m, tmp);
        gather_mean_kernel<<<M_TOTAL/8, 512>>>(m, idx);
        gemm3_kernel<<<dim3(MPAD/128, 4), 256, GEMM_SMEM>>>(rnn_b, tmp, h);
    }
    final_kernel<<<(NBATCH*CDIM*HWP)/256, 256>>>(h, out);
}

// round 7
// speedup vs baseline: 1.4872x; 1.4872x over previous
#include <cuda_runtime.h>
#include <cuda_bf16.h>
#include <cstdint>

#define HWP 3600
#define NBATCH 2
#define CDIM 256
#define KNN 64
#define M_TOTAL (NBATCH*HWP)   // 7200
#define MPAD 7296              // padded rows (multiple of 128)

// ---------------- scratch (device globals; no allocation allowed) ----------
__device__ float g_m[MPAD*CDIM];        // relu(mlp(h)) fp32
__device__ float g_tmp[MPAD*CDIM];      // h @ Wa^T fp32
__device__ float g_h[MPAD*CDIM];        // fp32 h (for final readout)
__device__ __nv_bfloat16 g_Ah[MPAD*CDIM], g_Al[MPAD*CDIM];   // h split
__device__ __nv_bfloat16 g_Mh[MPAD*CDIM], g_Ml[MPAD*CDIM];   // msg split
__device__ __nv_bfloat16 g_Wmh[CDIM*CDIM], g_Wml[CDIM*CDIM]; // mlp_w split
__device__ __nv_bfloat16 g_Wah[CDIM*CDIM], g_Wal[CDIM*CDIM]; // rnn_w[:, :C]
__device__ __nv_bfloat16 g_Wbh[CDIM*CDIM], g_Wbl[CDIM*CDIM]; // rnn_w[:, C:]
__device__ int   g_idx[M_TOTAL*KNN];

__device__ __forceinline__ float4 ld4(const float* p){ return *reinterpret_cast<const float4*>(p); }
__device__ __forceinline__ void st4(float* p, float4 v){ *reinterpret_cast<float4*>(p) = v; }

__device__ __forceinline__ void bsplit(float v, __nv_bfloat16& h, __nv_bfloat16& l){
    h = __float2bfloat16(v);
    l = __float2bfloat16(v - __bfloat162float(h));
}

__device__ __forceinline__ uint32_t smem_u32(const void* p) {
    uint32_t a;
    asm("{ .reg .u64 t; cvta.to.shared.u64 t, %1; cvt.u32.u64 %0, t; }" : "=r"(a) : "l"(p));
    return a;
}

// ---------------- mma.sync helpers (suffix-neutral PTX, tensor pipe) -------
__device__ __forceinline__ void ldmat4(uint32_t r[4], uint32_t addr){
    asm volatile("ldmatrix.sync.aligned.m8n8.x4.shared.b16 {%0,%1,%2,%3}, [%4];"
        : "=r"(r[0]), "=r"(r[1]), "=r"(r[2]), "=r"(r[3]) : "r"(addr));
}
__device__ __forceinline__ void mma16816(float c[4], const uint32_t a[4],
                                         uint32_t b0, uint32_t b1){
    asm volatile("mma.sync.aligned.m16n8k16.row.col.f32.bf16.bf16.f32 "
        "{%0,%1,%2,%3}, {%4,%5,%6,%7}, {%8,%9}, {%0,%1,%2,%3};"
        : "+f"(c[0]), "+f"(c[1]), "+f"(c[2]), "+f"(c[3])
        : "r"(a[0]), "r"(a[1]), "r"(a[2]), "r"(a[3]), "r"(b0), "r"(b1));
}

// smem tile layout: padded stride 72 bf16 (144B = 9 x 16B -> conflict-free)
#define ASTRIDE 72
#define OFF_AH  0
#define OFF_AL  18432
#define OFF_BH  36864
#define OFF_BL  46080
#define GEMM_SMEM 55296

// ---- 128x64x256 tile: bf16 3-term split via mma.sync, fp32 accumulate -----
__device__ void tile_mma(const __nv_bfloat16* __restrict__ Ah,
                         const __nv_bfloat16* __restrict__ Al,
                         const __nv_bfloat16* __restrict__ Bh,
                         const __nv_bfloat16* __restrict__ Bl,
                         int m0, float acc[2][4][4])
{
    extern __shared__ char smem[];
    const uint32_t sb = smem_u32(smem);
    const int tid = threadIdx.x;
    const int lane = tid & 31;
    const int wid = tid >> 5;
    const int wm = wid & 3;        // m32 section
    const int wn = wid >> 2;       // n32 section

    #pragma unroll
    for (int mt = 0; mt < 2; ++mt)
        #pragma unroll
        for (int nt = 0; nt < 4; ++nt)
            #pragma unroll
            for (int q = 0; q < 4; ++q) acc[mt][nt][q] = 0.f;

    const uint32_t aoff = (uint32_t)(((lane & 15)*ASTRIDE + (lane >> 4)*8) * 2);
    const uint32_t boff = (uint32_t)((((lane & 7) + ((lane >> 4) << 3))*ASTRIDE
                                      + ((lane >> 3) & 1)*8) * 2);

    #pragma unroll 1
    for (int kc = 0; kc < 4; ++kc) {
        #pragma unroll
        for (int i = 0; i < 12; ++i) {
            int v = tid + i*256;
            const uint4* src;
            uint32_t dst;
            if (v < 1024) {
                int row = v >> 3, c8 = v & 7;
                src = (const uint4*)(Ah + (m0 + row)*CDIM + kc*64 + c8*8);
                dst = OFF_AH + (uint32_t)(row*ASTRIDE + c8*8)*2;
            } else if (v < 2048) {
                int u = v - 1024, row = u >> 3, c8 = u & 7;
                src = (const uint4*)(Al + (m0 + row)*CDIM + kc*64 + c8*8);
                dst = OFF_AL + (uint32_t)(row*ASTRIDE + c8*8)*2;
            } else if (v < 2560) {
                int u = v - 2048, row = u >> 3, c8 = u & 7;
                src = (const uint4*)(Bh + row*CDIM + kc*64 + c8*8);
                dst = OFF_BH + (uint32_t)(row*ASTRIDE + c8*8)*2;
            } else {
                int u = v - 2560, row = u >> 3, c8 = u & 7;
                src = (const uint4*)(Bl + row*CDIM + kc*64 + c8*8);
                dst = OFF_BL + (uint32_t)(row*ASTRIDE + c8*8)*2;
            }
            *(uint4*)(smem + dst) = *src;
        }
        __syncthreads();

        #pragma unroll
        for (int ks = 0; ks < 4; ++ks) {
            const uint32_t abase = (uint32_t)((wm*32*ASTRIDE + ks*16) * 2);
            const uint32_t bbase = (uint32_t)((wn*32*ASTRIDE + ks*16) * 2);
            const uint32_t mstep = (uint32_t)(16*ASTRIDE*2);

            uint32_t ah0[4], ah1[4], al0[4], al1[4];
            ldmat4(ah0, sb + OFF_AH + abase + aoff);
            ldmat4(ah1, sb + OFF_AH + abase + mstep + aoff);
            ldmat4(al0, sb + OFF_AL + abase + aoff);
            ldmat4(al1, sb + OFF_AL + abase + mstep + aoff);

            uint32_t bhA[4], bhB[4], blA[4], blB[4];
            ldmat4(bhA, sb + OFF_BH + bbase + boff);
            ldmat4(bhB, sb + OFF_BH + bbase + mstep + boff);
            ldmat4(blA, sb + OFF_BL + bbase + boff);
            ldmat4(blB, sb + OFF_BL + bbase + mstep + boff);

            mma16816(acc[0][0], ah0, bhA[0], bhA[1]);
            mma16816(acc[0][1], ah0, bhA[2], bhA[3]);
            mma16816(acc[0][2], ah0, bhB[0], bhB[1]);
            mma16816(acc[0][3], ah0, bhB[2], bhB[3]);
            mma16816(acc[1][0], ah1, bhA[0], bhA[1]);
            mma16816(acc[1][1], ah1, bhA[2], bhA[3]);
            mma16816(acc[1][2], ah1, bhB[0], bhB[1]);
            mma16816(acc[1][3], ah1, bhB[2], bhB[3]);

            mma16816(acc[0][0], ah0, blA[0], blA[1]);
            mma16816(acc[0][1], ah0, blA[2], blA[3]);
            mma16816(acc[0][2], ah0, blB[0], blB[1]);
            mma16816(acc[0][3], ah0, blB[2], blB[3]);
            mma16816(acc[1][0], ah1, blA[0], blA[1]);
            mma16816(acc[1][1], ah1, blA[2], blA[3]);
            mma16816(acc[1][2], ah1, blB[0], blB[1]);
            mma16816(acc[1][3], ah1, blB[2], blB[3]);

            mma16816(acc[0][0], al0, bhA[0], bhA[1]);
            mma16816(acc[0][1], al0, bhA[2], bhA[3]);
            mma16816(acc[0][2], al0, bhB[0], bhB[1]);
            mma16816(acc[0][3], al0, bhB[2], bhB[3]);
            mma16816(acc[1][0], al1, bhA[0], bhA[1]);
            mma16816(acc[1][1], al1, bhA[2], bhA[3]);
            mma16816(acc[1][2], al1, bhB[0], bhB[1]);
            mma16816(acc[1][3], al1, bhB[2], bhB[3]);
        }
        __syncthreads();
    }
}

// GEMM1: by 0..3 -> m = relu(h Wmlp^T + b);  by 4..7 -> tmp = h Wa^T
__global__ void __launch_bounds__(256) gemm1_kernel(const float* __restrict__ mlp_b,
                                                    float* __restrict__ m_out,
                                                    float* __restrict__ tmp_out)
{
    int m0 = blockIdx.x * 128;
    int by = blockIdx.y;
    bool is_m = by < 4;
    int d0 = (is_m ? by : by - 4) * 64;
    const __nv_bfloat16* Bh = (is_m ? g_Wmh : g_Wah) + d0*CDIM;
    const __nv_bfloat16* Bl = (is_m ? g_Wml : g_Wal) + d0*CDIM;

    float acc[2][4][4];
    tile_mma(g_Ah, g_Al, Bh, Bl, m0, acc);

    int lane = threadIdx.x & 31, wid = threadIdx.x >> 5;
    int wm = wid & 3, wn = wid >> 2;
    int g = lane >> 2, t = lane & 3;

    #pragma unroll
    for (int mt = 0; mt < 2; ++mt) {
        #pragma unroll
        for (int nt = 0; nt < 4; ++nt) {
            int nl = wn*32 + nt*8 + t*2;
            int n = d0 + nl;
            float bx = 0.f, byv = 0.f;
            if (is_m) { bx = mlp_b[n]; byv = mlp_b[n+1]; }
            #pragma unroll
            for (int half = 0; half < 2; ++half) {
                int m = m0 + wm*32 + mt*16 + g + half*8;
                if (m >= M_TOTAL) continue;
                float vx = acc[mt][nt][half*2+0];
                float vy = acc[mt][nt][half*2+1];
                if (is_m) {
                    vx = fmaxf(vx + bx, 0.f);
                    vy = fmaxf(vy + byv, 0.f);
                    *(float2*)(m_out + m*CDIM + n) = make_float2(vx, vy);
                } else {
                    *(float2*)(tmp_out + m*CDIM + n) = make_float2(vx, vy);
                }
            }
        }
    }
}

// GEMM3: h' = relu(tmp + msg Wb^T + b_rnn); writes fp32 h and bf16 split
__global__ void __launch_bounds__(256) gemm3_kernel(const float* __restrict__ rnn_b,
                                                    const float* __restrict__ tmp,
                                                    float* __restrict__ h_out)
{
    int m0 = blockIdx.x * 128;
    int d0 = blockIdx.y * 64;

    float acc[2][4][4];
    tile_mma(g_Mh, g_Ml, g_Wbh + d0*CDIM, g_Wbl + d0*CDIM, m0, acc);

    int lane = threadIdx.x & 31, wid = threadIdx.x >> 5;
    int wm = wid & 3, wn = wid >> 2;
    int g = lane >> 2, t = lane & 3;

    #pragma unroll
    for (int mt = 0; mt < 2; ++mt) {
        #pragma unroll
        for (int nt = 0; nt < 4; ++nt) {
            int n = d0 + wn*32 + nt*8 + t*2;
            float bx = rnn_b[n], byv = rnn_b[n+1];
            #pragma unroll
            for (int half = 0; half < 2; ++half) {
                int m = m0 + wm*32 + mt*16 + g + half*8;
                if (m >= M_TOTAL) continue;
                float2 tv = *(const float2*)(tmp + m*CDIM + n);
                float vx = fmaxf(acc[mt][nt][half*2+0] + tv.x + bx, 0.f);
                float vy = fmaxf(acc[mt][nt][half*2+1] + tv.y + byv, 0.f);
                *(float2*)(h_out + m*CDIM + n) = make_float2(vx, vy);
                __nv_bfloat16 hx, lx, hy, ly;
                bsplit(vx, hx, lx); bsplit(vy, hy, ly);
                *(__nv_bfloat162*)(g_Ah + m*CDIM + n) = __nv_bfloat162(hx, hy);
                *(__nv_bfloat162*)(g_Al + m*CDIM + n) = __nv_bfloat162(lx, ly);
            }
        }
    }
}

// ---------------- weight conversion (once per call) ------------------------
__global__ void __launch_bounds__(256) wconv_kernel(const float* __restrict__ mlp_w,
                                                    const float* __restrict__ rnn_w)
{
    int e = blockIdx.x * 256 + threadIdx.x;   // < 256*768
    if (e < CDIM*CDIM) {
        __nv_bfloat16 h, l; bsplit(mlp_w[e], h, l);
        g_Wmh[e] = h; g_Wml[e] = l;
    } else {
        int u = e - CDIM*CDIM;                 // < 256*512
        int r = u >> 9, c = u & 511;
        __nv_bfloat16 h, l; bsplit(rnn_w[u], h, l);
        if (c < CDIM) { g_Wah[r*CDIM + c] = h; g_Wal[r*CDIM + c] = l; }
        else          { g_Wbh[r*CDIM + c - CDIM] = h; g_Wbl[r*CDIM + c - CDIM] = l; }
    }
}

// zero padded rows of bf16 operand arrays
__global__ void __launch_bounds__(256) pad_kernel()
{
    int e = blockIdx.x * 256 + threadIdx.x;   // < 96*256
    int o = (M_TOTAL + (e >> 8))*CDIM + (e & 255);
    g_Ah[o] = __float2bfloat16(0.f); g_Al[o] = __float2bfloat16(0.f);
    g_Mh[o] = __float2bfloat16(0.f); g_Ml[o] = __float2bfloat16(0.f);
}

// ---------------- init: out[:, :256] = cnn; Ah/Al = bf16 split of NHWC h0 --
__global__ void __launch_bounds__(256) init_kernel(const float* __restrict__ cnn,
                                                   float* __restrict__ out)
{
    int e = blockIdx.x * 256 + threadIdx.x;
    int s = e % HWP;
    int c = (e / HWP) & (CDIM-1);
    int n = e / (HWP*CDIM);
    float v = cnn[e];
    out[(n*(2*CDIM) + c)*HWP + s] = v;
    __nv_bfloat16 h, l; bsplit(v, h, l);
    int o = (n*HWP + s)*CDIM + c;
    g_Ah[o] = h; g_Al[o] = l;
}

__global__ void __launch_bounds__(256) final_kernel(const float* __restrict__ h,
                                                    float* __restrict__ out)
{
    int e = blockIdx.x * 256 + threadIdx.x;
    int s = e % HWP;
    int c = (e / HWP) & (CDIM-1);
    int n = e / (HWP*CDIM);
    out[(n*(2*CDIM) + CDIM + c)*HWP + s] = h[(n*HWP + s)*CDIM + c];
}

// ---------------- KNN v4: block phase-A + warp-parallel phase-B search -----
#define KNN_BR 12
#define CAP 256
// dynamic smem layout (bytes)
#define KPX    0                        // float[3600]  14400
#define KPY    14400
#define KPZ    28800                    // end 43200
#define KHIST  43200                    // int[256]      1024
#define KCV    44224                    // u32[12][CAP] 12288
#define KCI    56512                    // int[12][CAP] 12288
#define KTIE   68800                    // int[12][32]   1536
#define KOCNT  70336                    // int[12]
#define KCCNT  70384                    // int[12]
#define KECRIT 70432                    // int[12]
#define KFLAG  70480                    // int[12]
#define KWS    70528                    // int[2][8]
#define KSC    70592                    // int[4]
#define KNN_SMEM 70656

__global__ void __launch_bounds__(256) knn_kernel(const float* __restrict__ pts,
                                                  int* __restrict__ idx_out)
{
    extern __shared__ char sm[];
    float* px = (float*)(sm + KPX);
    float* py = (float*)(sm + KPY);
    float* pz = (float*)(sm + KPZ);
    int* hist = (int*)(sm + KHIST);
    unsigned* cv = (unsigned*)(sm + KCV);
    int* ci = (int*)(sm + KCI);
    int* tiebuf = (int*)(sm + KTIE);
    int* ocnt  = (int*)(sm + KOCNT);
    int* ccnt  = (int*)(sm + KCCNT);
    int* ecrit = (int*)(sm + KECRIT);
    int* flag  = (int*)(sm + KFLAG);
    int* ws    = (int*)(sm + KWS);
    int* sc    = (int*)(sm + KSC);

    int gb = blockIdx.x;
    int n  = gb / (HWP/KNN_BR);
    int g  = gb % (HWP/KNN_BR);
    int tid = threadIdx.x;
    int lane = tid & 31, wid = tid >> 5;
    const unsigned ltm = (1u << lane) - 1u;

    const float* p = pts + n*3*HWP;
    for (int i = tid; i < HWP; i += 256) {
        px[i] = p[i];
        py[i] = p[i + HWP];
        pz[i] = p[i + 2*HWP];
    }
    if (tid < KNN_BR) { ocnt[tid] = 0; ccnt[tid] = 0; flag[tid] = 0; }
    __syncthreads();

    // ---------------- Phase A: per-row histogram + compaction --------------
    for (int r = 0; r < KNN_BR; ++r) {
        int row = g*KNN_BR + r;
        float qx = px[row], qy = py[row], qz = pz[row];
        float qs = fmaf(qz, qz, fmaf(qy, qy, qx*qx));

        unsigned d[15];
        #pragma unroll
        for (int t = 0; t < 15; ++t) {
            int j = t*256 + tid;
            if (j < HWP) {
                float x = px[j], y = py[j], z = pz[j];
                float sj  = fmaf(z, z, fmaf(y, y, x*x));
                float dot = fmaf(qz, z, fmaf(qy, y, qx*x));
                d[t] = __float_as_uint(fmaxf(qs + sj - 2.0f*dot, 0.0f));
            } else {
                d[t] = 0x7f800000u;   // pad -> bin 255
            }
        }

        hist[tid] = 0;
        __syncthreads();                              // B1

        #pragma unroll
        for (int t = 0; t < 15; ++t) {
            unsigned e = d[t] >> 23;
            unsigned mask = __match_any_sync(0xffffffffu, e);
            if (lane == (unsigned)(__ffs(mask) - 1)) atomicAdd(&hist[e], __popc(mask));
        }
        __syncthreads();                              // B2

        if (wid == 0) {
            int base = lane*8, loc[8], ssum = 0;
            #pragma unroll
            for (int j2 = 0; j2 < 8; ++j2) { loc[j2] = hist[base+j2]; ssum += loc[j2]; }
            int pre = ssum;
            #pragma unroll
            for (int o = 1; o < 32; o <<= 1) {
                int v = __shfl_up_sync(0xffffffffu, pre, o);
                if (lane >= (unsigned)o) pre += v;
            }
            int excl = pre - ssum;
            if (excl < KNN && excl + ssum >= KNN) {   // unique crossing lane
                int cum = excl;
                #pragma unroll
                for (int j2 = 0; j2 < 8; ++j2) {
                    if (cum + loc[j2] >= KNN) { ecrit[r] = base + j2; break; }
                    cum += loc[j2];
                }
            }
        }
        __syncthreads();                              // B3
        int E = ecrit[r];

        int* outp = idx_out + (n*HWP + row)*KNN;
        unsigned* wcv = cv + r*CAP;
        int* wci = ci + r*CAP;

        #pragma unroll
        for (int t = 0; t < 15; ++t) {
            int e = (int)(d[t] >> 23);
            int j = t*256 + tid;
            if (e < E) {
                int pos = atomicAdd(&ocnt[r], 1);
                outp[pos] = j;
            } else if (e == E && j < HWP) {
                int pos = atomicAdd(&ccnt[r], 1);
                if (pos < CAP) { wcv[pos] = d[t]; wci[pos] = j; }
            }
        }
        // no barrier needed before next row's hist zeroing (compact never reads hist)
    }
    __syncthreads();                                  // phase boundary

    // ---------------- Phase B: warp-parallel per-row search ----------------
    for (int r = wid; r < KNN_BR; r += 8) {
        int row = g*KNN_BR + r;
        int* outp = idx_out + (n*HWP + row)*KNN;
        unsigned* wcv = cv + r*CAP;
        int* wci = ci + r*CAP;
        int* wtie = tiebuf + r*32;

        int oc0 = ocnt[r], cc = ccnt[r];
        int Kp = KNN - oc0;

        if (cc > CAP) {
            if (lane == 0) flag[r] = 1;
            continue;
        }
        if (cc == Kp) {
            for (int i = lane; i < cc; i += 32) outp[oc0 + i] = wci[i];
            continue;
        }
        // warp-local 23-bit search within critical bin
        unsigned T = ((unsigned)ecrit[r]) << 23;
        for (int bit = 22; bit >= 0; --bit) {
            unsigned cnd = T | (1u << bit);
            int cnt = 0;
            for (int i = lane; i < cc; i += 32) cnt += (wcv[i] < cnd) ? 1 : 0;
            cnt = __reduce_add_sync(0xffffffffu, cnt);
            if (cnt < Kp) T = cnd;
        }
        int oc = oc0, tc = 0;
        for (int ib = 0; ib < cc; ib += 32) {
            int i = ib + lane;
            bool v = i < cc;
            unsigned bv = v ? wcv[i] : 0xffffffffu;
            unsigned mw = __ballot_sync(0xffffffffu, v && bv < T);
            if (v && bv < T) outp[oc + __popc(mw & ltm)] = wci[i];
            oc += __popc(mw);
            unsigned mt = __ballot_sync(0xffffffffu, v && bv == T);
            if (v && bv == T) {
                int tp = tc + __popc(mt & ltm);
                if (tp < 32) wtie[tp] = wci[i];
            }
            tc += __popc(mt);
        }
        __syncwarp();
        if (lane == 0) {
            int slots = KNN - oc;
            int en = tc < 32 ? tc : 32;
            for (int q2 = 0; q2 < slots; ++q2) {      // lowest-index tie fill
                int best = 0x7fffffff, bi = 0;
                for (int e2 = 0; e2 < en; ++e2)
                    if (wtie[e2] < best) { best = wtie[e2]; bi = e2; }
                wtie[bi] = 0x7fffffff;
                outp[oc + q2] = best;
            }
        }
    }
    __syncthreads();

    // ---------------- fallback: block-wide 31-bit search (rare) ------------
    for (int r = 0; r < KNN_BR; ++r) {
        if (!flag[r]) continue;
        int row = g*KNN_BR + r;
        float qx = px[row], qy = py[row], qz = pz[row];
        float qs = fmaf(qz, qz, fmaf(qy, qy, qx*qx));

        unsigned d[15];
        #pragma unroll
        for (int t = 0; t < 15; ++t) {
            int j = t*256 + tid;
            if (j < HWP) {
                float x = px[j], y = py[j], z = pz[j];
                float sj  = fmaf(z, z, fmaf(y, y, x*x));
                float dot = fmaf(qz, z, fmaf(qy, y, qx*x));
                d[t] = __float_as_uint(fmaxf(qs + sj - 2.0f*dot, 0.0f));
            } else {
                d[t] = 0xffffffffu;
            }
        }
        if (tid == 0) { sc[0] = 0; sc[1] = 0; }
        __syncthreads();

        unsigned T = 0;
        for (int bit = 30; bit >= 0; --bit) {
            unsigned cnd = T | (1u << bit);
            int cc2 = 0;
            #pragma unroll
            for (int t = 0; t < 15; ++t) cc2 += (d[t] < cnd) ? 1 : 0;
            cc2 = __reduce_add_sync(0xffffffffu, cc2);
            int par = bit & 1;
            if (lane == 0) ws[par*8 + wid] = cc2;
            __syncthreads();
            int tot = 0;
            #pragma unroll
            for (int w = 0; w < 8; ++w) tot += ws[par*8 + w];
            if (tot < KNN) T = cnd;
        }
        __syncthreads();

        int* outp = idx_out + (n*HWP + row)*KNN;
        int* wtie = tiebuf + r*32;
        #pragma unroll
        for (int t = 0; t < 15; ++t) {
            int j = t*256 + tid;
            unsigned dv = d[t];
            if (dv < T) { int pos = atomicAdd(&sc[0], 1); outp[pos] = j; }
            else if (dv == T && j < HWP) { int pos = atomicAdd(&sc[1], 1); if (pos < 32) wtie[pos] = j; }
        }
        __syncthreads();
        if (tid == 0) {
            int slots = KNN - sc[0];
            int en = sc[1] < 32 ? sc[1] : 32;
            for (int q2 = 0; q2 < slots; ++q2) {
                int best = 0x7fffffff, bi = 0;
                for (int e2 = 0; e2 < en; ++e2)
                    if (wtie[e2] < best) { best = wtie[e2]; bi = e2; }
                wtie[bi] = 0x7fffffff;
                outp[sc[0] + q2] = best;
            }
        }
        __syncthreads();
    }
}

// ---------------- gather-mean: msg = mean_k m[idx]; emits bf16 split -------
__global__ void __launch_bounds__(512) gather_mean_kernel(const float* __restrict__ m,
                                                          const int* __restrict__ idx)
{
    __shared__ int sidx[8*KNN];
    int tid = threadIdx.x;
    int s0 = blockIdx.x * 8;
    sidx[tid] = idx[s0*KNN + tid];
    __syncthreads();

    int lp = tid >> 6;
    int c4 = tid & 63;
    int s  = s0 + lp;
    int base = (s / HWP) * HWP;
    const float4* m4 = reinterpret_cast<const float4*>(m);
    const int* ip = sidx + lp*KNN;

    float4 a0 = make_float4(0,0,0,0), a1 = a0, a2 = a0, a3 = a0;
    #pragma unroll
    for (int k = 0; k < KNN; k += 4) {
        int j0 = ip[k], j1 = ip[k+1], j2 = ip[k+2], j3 = ip[k+3];
        float4 v0 = m4[(size_t)(base + j0)*64 + c4];
        float4 v1 = m4[(size_t)(base + j1)*64 + c4];
        float4 v2 = m4[(size_t)(base + j2)*64 + c4];
        float4 v3 = m4[(size_t)(base + j3)*64 + c4];
        a0.x += v0.x; a0.y += v0.y; a0.z += v0.z; a0.w += v0.w;
        a1.x += v1.x; a1.y += v1.y; a1.z += v1.z; a1.w += v1.w;
        a2.x += v2.x; a2.y += v2.y; a2.z += v2.z; a2.w += v2.w;
        a3.x += v3.x; a3.y += v3.y; a3.z += v3.z; a3.w += v3.w;
    }
    const float inv = 1.0f / 64.0f;
    float4 r;
    r.x = (a0.x + a1.x + a2.x + a3.x) * inv;
    r.y = (a0.y + a1.y + a2.y + a3.y) * inv;
    r.z = (a0.z + a1.z + a2.z + a3.z) * inv;
    r.w = (a0.w + a1.w + a2.w + a3.w) * inv;

    __nv_bfloat16 hx, lx, hy, ly, hz, lz, hw, lw;
    bsplit(r.x, hx, lx); bsplit(r.y, hy, ly);
    bsplit(r.z, hz, lz); bsplit(r.w, hw, lw);
    int o = s*CDIM + c4*4;
    *(__nv_bfloat162*)(g_Mh + o)     = __nv_bfloat162(hx, hy);
    *(__nv_bfloat162*)(g_Mh + o + 2) = __nv_bfloat162(hz, hw);
    *(__nv_bfloat162*)(g_Ml + o)     = __nv_bfloat162(lx, ly);
    *(__nv_bfloat162*)(g_Ml + o + 2) = __nv_bfloat162(lz, lw);
}

// ---------------- launcher --------------------------------------------------
extern "C" void kernel_launch(void* const* d_in, const int* in_sizes, int n_in,
                              void* d_out, int out_size)
{
    const float* cnn   = (const float*)d_in[0];
    const float* pts   = (const float*)d_in[1];
    const float* mlp_w = (const float*)d_in[2];
    const float* mlp_b = (const float*)d_in[3];
    const float* rnn_w = (const float*)d_in[4];
    const float* rnn_b = (const float*)d_in[5];
    float* out = (float*)d_out;

    float *m, *tmp, *h;
    int* idx;
    cudaGetSymbolAddress((void**)&m,   g_m);
    cudaGetSymbolAddress((void**)&tmp, g_tmp);
    cudaGetSymbolAddress((void**)&h,   g_h);
    cudaGetSymbolAddress((void**)&idx, g_idx);

    cudaFuncSetAttribute(gemm1_kernel, cudaFuncAttributeMaxDynamicSharedMemorySize, GEMM_SMEM);
    cudaFuncSetAttribute(gemm3_kernel, cudaFuncAttributeMaxDynamicSharedMemorySize, GEMM_SMEM);
    cudaFuncSetAttribute(knn_kernel,   cudaFuncAttributeMaxDynamicSharedMemorySize, KNN_SMEM);

    wconv_kernel<<<768, 256>>>(mlp_w, rnn_w);
    init_kernel<<<(NBATCH*CDIM*HWP)/256, 256>>>(cnn, out);
    pad_kernel<<<96, 256>>>();
    knn_kernel<<<NBATCH*(HWP/KNN_BR), 256, KNN_SMEM>>>(pts, idx);

    for (int it = 0; it < 3; ++it) {
        gemm1_kernel<<<dim3(MPAD/128, 8), 256, GEMM_SMEM>>>(mlp_b, m, tmp);
        gather_mean_kernel<<<M_TOTAL/8, 512>>>(m, idx);
        gemm3_kernel<<<dim3(MPAD/128, 4), 256, GEMM_SMEM>>>(rnn_b, tmp, h);
    }
    final_kernel<<<(NBATCH*CDIM*HWP)/256, 256>>>(h, out);
}

// round 8
// speedup vs baseline: 1.4944x; 1.0049x over previous
#include <cuda_runtime.h>
#include <cuda_bf16.h>
#include <cstdint>

#define HWP 3600
#define NBATCH 2
#define CDIM 256
#define KNN 64
#define M_TOTAL (NBATCH*HWP)   // 7200
#define MPAD 7296              // padded rows (multiple of 128)

// ---------------- scratch (device globals; no allocation allowed) ----------
__device__ float g_m[MPAD*CDIM];        // relu(mlp(h)) fp32
__device__ float g_tmp[MPAD*CDIM];      // h @ Wa^T fp32
__device__ float g_h[MPAD*CDIM];        // fp32 h (for final readout)
__device__ __nv_bfloat16 g_Ah[MPAD*CDIM], g_Al[MPAD*CDIM];   // h split
__device__ __nv_bfloat16 g_Mh[MPAD*CDIM], g_Ml[MPAD*CDIM];   // msg split
__device__ __nv_bfloat16 g_Wmh[CDIM*CDIM], g_Wml[CDIM*CDIM]; // mlp_w split
__device__ __nv_bfloat16 g_Wah[CDIM*CDIM], g_Wal[CDIM*CDIM]; // rnn_w[:, :C]
__device__ __nv_bfloat16 g_Wbh[CDIM*CDIM], g_Wbl[CDIM*CDIM]; // rnn_w[:, C:]
__device__ int   g_idx[M_TOTAL*KNN];

__device__ __forceinline__ float4 ld4(const float* p){ return *reinterpret_cast<const float4*>(p); }
__device__ __forceinline__ void st4(float* p, float4 v){ *reinterpret_cast<float4*>(p) = v; }

__device__ __forceinline__ void bsplit(float v, __nv_bfloat16& h, __nv_bfloat16& l){
    h = __float2bfloat16(v);
    l = __float2bfloat16(v - __bfloat162float(h));
}

__device__ __forceinline__ uint32_t smem_u32(const void* p) {
    uint32_t a;
    asm("{ .reg .u64 t; cvta.to.shared.u64 t, %1; cvt.u32.u64 %0, t; }" : "=r"(a) : "l"(p));
    return a;
}

// ---------------- mma.sync helpers (suffix-neutral PTX, tensor pipe) -------
__device__ __forceinline__ void ldmat4(uint32_t r[4], uint32_t addr){
    asm volatile("ldmatrix.sync.aligned.m8n8.x4.shared.b16 {%0,%1,%2,%3}, [%4];"
        : "=r"(r[0]), "=r"(r[1]), "=r"(r[2]), "=r"(r[3]) : "r"(addr));
}
__device__ __forceinline__ void mma16816(float c[4], const uint32_t a[4],
                                         uint32_t b0, uint32_t b1){
    asm volatile("mma.sync.aligned.m16n8k16.row.col.f32.bf16.bf16.f32 "
        "{%0,%1,%2,%3}, {%4,%5,%6,%7}, {%8,%9}, {%0,%1,%2,%3};"
        : "+f"(c[0]), "+f"(c[1]), "+f"(c[2]), "+f"(c[3])
        : "r"(a[0]), "r"(a[1]), "r"(a[2]), "r"(a[3]), "r"(b0), "r"(b1));
}

// smem tile layout: padded stride 72 bf16 (144B = 9 x 16B -> conflict-free)
#define ASTRIDE 72
#define OFF_AH  0
#define OFF_AL  18432
#define OFF_BH  36864
#define OFF_BL  46080
#define GEMM_SMEM 55296

// ---- 128x64x256 tile: bf16 3-term split via mma.sync, fp32 accumulate -----
__device__ void tile_mma(const __nv_bfloat16* __restrict__ Ah,
                         const __nv_bfloat16* __restrict__ Al,
                         const __nv_bfloat16* __restrict__ Bh,
                         const __nv_bfloat16* __restrict__ Bl,
                         int m0, float acc[2][4][4])
{
    extern __shared__ char smem[];
    const uint32_t sb = smem_u32(smem);
    const int tid = threadIdx.x;
    const int lane = tid & 31;
    const int wid = tid >> 5;
    const int wm = wid & 3;        // m32 section
    const int wn = wid >> 2;       // n32 section

    #pragma unroll
    for (int mt = 0; mt < 2; ++mt)
        #pragma unroll
        for (int nt = 0; nt < 4; ++nt)
            #pragma unroll
            for (int q = 0; q < 4; ++q) acc[mt][nt][q] = 0.f;

    const uint32_t aoff = (uint32_t)(((lane & 15)*ASTRIDE + (lane >> 4)*8) * 2);
    const uint32_t boff = (uint32_t)((((lane & 7) + ((lane >> 4) << 3))*ASTRIDE
                                      + ((lane >> 3) & 1)*8) * 2);

    #pragma unroll 1
    for (int kc = 0; kc < 4; ++kc) {
        #pragma unroll
        for (int i = 0; i < 12; ++i) {
            int v = tid + i*256;
            const uint4* src;
            uint32_t dst;
            if (v < 1024) {
                int row = v >> 3, c8 = v & 7;
                src = (const uint4*)(Ah + (m0 + row)*CDIM + kc*64 + c8*8);
                dst = OFF_AH + (uint32_t)(row*ASTRIDE + c8*8)*2;
            } else if (v < 2048) {
                int u = v - 1024, row = u >> 3, c8 = u & 7;
                src = (const uint4*)(Al + (m0 + row)*CDIM + kc*64 + c8*8);
                dst = OFF_AL + (uint32_t)(row*ASTRIDE + c8*8)*2;
            } else if (v < 2560) {
                int u = v - 2048, row = u >> 3, c8 = u & 7;
                src = (const uint4*)(Bh + row*CDIM + kc*64 + c8*8);
                dst = OFF_BH + (uint32_t)(row*ASTRIDE + c8*8)*2;
            } else {
                int u = v - 2560, row = u >> 3, c8 = u & 7;
                src = (const uint4*)(Bl + row*CDIM + kc*64 + c8*8);
                dst = OFF_BL + (uint32_t)(row*ASTRIDE + c8*8)*2;
            }
            *(uint4*)(smem + dst) = *src;
        }
        __syncthreads();

        #pragma unroll
        for (int ks = 0; ks < 4; ++ks) {
            const uint32_t abase = (uint32_t)((wm*32*ASTRIDE + ks*16) * 2);
            const uint32_t bbase = (uint32_t)((wn*32*ASTRIDE + ks*16) * 2);
            const uint32_t mstep = (uint32_t)(16*ASTRIDE*2);

            uint32_t ah0[4], ah1[4], al0[4], al1[4];
            ldmat4(ah0, sb + OFF_AH + abase + aoff);
            ldmat4(ah1, sb + OFF_AH + abase + mstep + aoff);
            ldmat4(al0, sb + OFF_AL + abase + aoff);
            ldmat4(al1, sb + OFF_AL + abase + mstep + aoff);

            uint32_t bhA[4], bhB[4], blA[4], blB[4];
            ldmat4(bhA, sb + OFF_BH + bbase + boff);
            ldmat4(bhB, sb + OFF_BH + bbase + mstep + boff);
            ldmat4(blA, sb + OFF_BL + bbase + boff);
            ldmat4(blB, sb + OFF_BL + bbase + mstep + boff);

            mma16816(acc[0][0], ah0, bhA[0], bhA[1]);
            mma16816(acc[0][1], ah0, bhA[2], bhA[3]);
            mma16816(acc[0][2], ah0, bhB[0], bhB[1]);
            mma16816(acc[0][3], ah0, bhB[2], bhB[3]);
            mma16816(acc[1][0], ah1, bhA[0], bhA[1]);
            mma16816(acc[1][1], ah1, bhA[2], bhA[3]);
            mma16816(acc[1][2], ah1, bhB[0], bhB[1]);
            mma16816(acc[1][3], ah1, bhB[2], bhB[3]);

            mma16816(acc[0][0], ah0, blA[0], blA[1]);
            mma16816(acc[0][1], ah0, blA[2], blA[3]);
            mma16816(acc[0][2], ah0, blB[0], blB[1]);
            mma16816(acc[0][3], ah0, blB[2], blB[3]);
            mma16816(acc[1][0], ah1, blA[0], blA[1]);
            mma16816(acc[1][1], ah1, blA[2], blA[3]);
            mma16816(acc[1][2], ah1, blB[0], blB[1]);
            mma16816(acc[1][3], ah1, blB[2], blB[3]);

            mma16816(acc[0][0], al0, bhA[0], bhA[1]);
            mma16816(acc[0][1], al0, bhA[2], bhA[3]);
            mma16816(acc[0][2], al0, bhB[0], bhB[1]);
            mma16816(acc[0][3], al0, bhB[2], bhB[3]);
            mma16816(acc[1][0], al1, bhA[0], bhA[1]);
            mma16816(acc[1][1], al1, bhA[2], bhA[3]);
            mma16816(acc[1][2], al1, bhB[0], bhB[1]);
            mma16816(acc[1][3], al1, bhB[2], bhB[3]);
        }
        __syncthreads();
    }
}

// GEMM1: by 0..3 -> m = relu(h Wmlp^T + b);  by 4..7 -> tmp = h Wa^T
__global__ void __launch_bounds__(256) gemm1_kernel(const float* __restrict__ mlp_b,
                                                    float* __restrict__ m_out,
                                                    float* __restrict__ tmp_out)
{
    int m0 = blockIdx.x * 128;
    int by = blockIdx.y;
    bool is_m = by < 4;
    int d0 = (is_m ? by : by - 4) * 64;
    const __nv_bfloat16* Bh = (is_m ? g_Wmh : g_Wah) + d0*CDIM;
    const __nv_bfloat16* Bl = (is_m ? g_Wml : g_Wal) + d0*CDIM;

    float acc[2][4][4];
    tile_mma(g_Ah, g_Al, Bh, Bl, m0, acc);

    int lane = threadIdx.x & 31, wid = threadIdx.x >> 5;
    int wm = wid & 3, wn = wid >> 2;
    int g = lane >> 2, t = lane & 3;

    #pragma unroll
    for (int mt = 0; mt < 2; ++mt) {
        #pragma unroll
        for (int nt = 0; nt < 4; ++nt) {
            int nl = wn*32 + nt*8 + t*2;
            int n = d0 + nl;
            float bx = 0.f, byv = 0.f;
            if (is_m) { bx = mlp_b[n]; byv = mlp_b[n+1]; }
            #pragma unroll
            for (int half = 0; half < 2; ++half) {
                int m = m0 + wm*32 + mt*16 + g + half*8;
                if (m >= M_TOTAL) continue;
                float vx = acc[mt][nt][half*2+0];
                float vy = acc[mt][nt][half*2+1];
                if (is_m) {
                    vx = fmaxf(vx + bx, 0.f);
                    vy = fmaxf(vy + byv, 0.f);
                    *(float2*)(m_out + m*CDIM + n) = make_float2(vx, vy);
                } else {
                    *(float2*)(tmp_out + m*CDIM + n) = make_float2(vx, vy);
                }
            }
        }
    }
}

// GEMM3: h' = relu(tmp + msg Wb^T + b_rnn); writes fp32 h and bf16 split
__global__ void __launch_bounds__(256) gemm3_kernel(const float* __restrict__ rnn_b,
                                                    const float* __restrict__ tmp,
                                                    float* __restrict__ h_out)
{
    int m0 = blockIdx.x * 128;
    int d0 = blockIdx.y * 64;

    float acc[2][4][4];
    tile_mma(g_Mh, g_Ml, g_Wbh + d0*CDIM, g_Wbl + d0*CDIM, m0, acc);

    int lane = threadIdx.x & 31, wid = threadIdx.x >> 5;
    int wm = wid & 3, wn = wid >> 2;
    int g = lane >> 2, t = lane & 3;

    #pragma unroll
    for (int mt = 0; mt < 2; ++mt) {
        #pragma unroll
        for (int nt = 0; nt < 4; ++nt) {
            int n = d0 + wn*32 + nt*8 + t*2;
            float bx = rnn_b[n], byv = rnn_b[n+1];
            #pragma unroll
            for (int half = 0; half < 2; ++half) {
                int m = m0 + wm*32 + mt*16 + g + half*8;
                if (m >= M_TOTAL) continue;
                float2 tv = *(const float2*)(tmp + m*CDIM + n);
                float vx = fmaxf(acc[mt][nt][half*2+0] + tv.x + bx, 0.f);
                float vy = fmaxf(acc[mt][nt][half*2+1] + tv.y + byv, 0.f);
                *(float2*)(h_out + m*CDIM + n) = make_float2(vx, vy);
                __nv_bfloat16 hx, lx, hy, ly;
                bsplit(vx, hx, lx); bsplit(vy, hy, ly);
                *(__nv_bfloat162*)(g_Ah + m*CDIM + n) = __nv_bfloat162(hx, hy);
                *(__nv_bfloat162*)(g_Al + m*CDIM + n) = __nv_bfloat162(lx, ly);
            }
        }
    }
}

// ---------------- weight conversion (once per call) ------------------------
__global__ void __launch_bounds__(256) wconv_kernel(const float* __restrict__ mlp_w,
                                                    const float* __restrict__ rnn_w)
{
    int e = blockIdx.x * 256 + threadIdx.x;   // < 256*768
    if (e < CDIM*CDIM) {
        __nv_bfloat16 h, l; bsplit(mlp_w[e], h, l);
        g_Wmh[e] = h; g_Wml[e] = l;
    } else {
        int u = e - CDIM*CDIM;                 // < 256*512
        int r = u >> 9, c = u & 511;
        __nv_bfloat16 h, l; bsplit(rnn_w[u], h, l);
        if (c < CDIM) { g_Wah[r*CDIM + c] = h; g_Wal[r*CDIM + c] = l; }
        else          { g_Wbh[r*CDIM + c - CDIM] = h; g_Wbl[r*CDIM + c - CDIM] = l; }
    }
}

// zero padded rows of bf16 operand arrays
__global__ void __launch_bounds__(256) pad_kernel()
{
    int e = blockIdx.x * 256 + threadIdx.x;   // < 96*256
    int o = (M_TOTAL + (e >> 8))*CDIM + (e & 255);
    g_Ah[o] = __float2bfloat16(0.f); g_Al[o] = __float2bfloat16(0.f);
    g_Mh[o] = __float2bfloat16(0.f); g_Ml[o] = __float2bfloat16(0.f);
}

// ---------------- init: out[:, :256] = cnn; Ah/Al = bf16 split of NHWC h0 --
__global__ void __launch_bounds__(256) init_kernel(const float* __restrict__ cnn,
                                                   float* __restrict__ out)
{
    int e = blockIdx.x * 256 + threadIdx.x;
    int s = e % HWP;
    int c = (e / HWP) & (CDIM-1);
    int n = e / (HWP*CDIM);
    float v = cnn[e];
    out[(n*(2*CDIM) + c)*HWP + s] = v;
    __nv_bfloat16 h, l; bsplit(v, h, l);
    int o = (n*HWP + s)*CDIM + c;
    g_Ah[o] = h; g_Al[o] = l;
}

__global__ void __launch_bounds__(256) final_kernel(const float* __restrict__ h,
                                                    float* __restrict__ out)
{
    int e = blockIdx.x * 256 + threadIdx.x;
    int s = e % HWP;
    int c = (e / HWP) & (CDIM-1);
    int n = e / (HWP*CDIM);
    out[(n*(2*CDIM) + CDIM + c)*HWP + s] = h[(n*HWP + s)*CDIM + c];
}

// ---------------- KNN v5: candidate-major phase-A, 8 rows/block ------------
#define KNN_BR 8
#define CAP 256
// dynamic smem layout (bytes)
#define KPX    0                        // float[3600]  14400
#define KPY    14400
#define KPZ    28800                    // end 43200
#define KHIST  43200                    // int[8][256]   8192
#define KCV    51392                    // u32[8][CAP]   8192
#define KCI    59584                    // int[8][CAP]   8192
#define KTIE   67776                    // int[8][32]    1024
#define KOCNT  68800                    // int[8]
#define KCCNT  68832                    // int[8]
#define KECRIT 68864                    // int[8]
#define KFLAG  68896                    // int[8]
#define KWS    68928                    // int[2][8]
#define KSC    68992                    // int[4]
#define KNN_SMEM 69120

__global__ void __launch_bounds__(256) knn_kernel(const float* __restrict__ pts,
                                                  int* __restrict__ idx_out)
{
    extern __shared__ char sm[];
    float* px = (float*)(sm + KPX);
    float* py = (float*)(sm + KPY);
    float* pz = (float*)(sm + KPZ);
    int* hist = (int*)(sm + KHIST);
    unsigned* cv = (unsigned*)(sm + KCV);
    int* ci = (int*)(sm + KCI);
    int* tiebuf = (int*)(sm + KTIE);
    int* ocnt  = (int*)(sm + KOCNT);
    int* ccnt  = (int*)(sm + KCCNT);
    int* ecrit = (int*)(sm + KECRIT);
    int* flag  = (int*)(sm + KFLAG);
    int* ws    = (int*)(sm + KWS);
    int* sc    = (int*)(sm + KSC);

    int gb = blockIdx.x;
    int n  = gb / (HWP/KNN_BR);
    int g  = gb % (HWP/KNN_BR);
    int tid = threadIdx.x;
    int lane = tid & 31, wid = tid >> 5;
    const unsigned ltm = (1u << lane) - 1u;

    const float* p = pts + n*3*HWP;
    for (int i = tid; i < HWP; i += 256) {
        px[i] = p[i];
        py[i] = p[i + HWP];
        pz[i] = p[i + 2*HWP];
    }
    #pragma unroll
    for (int i = 0; i < KNN_BR; ++i) hist[i*256 + tid] = 0;
    if (tid < KNN_BR) { ocnt[tid] = 0; ccnt[tid] = 0; flag[tid] = 0; }
    __syncthreads();                                   // B0

    // query coords in registers
    float qx[KNN_BR], qy[KNN_BR], qz[KNN_BR], qs[KNN_BR];
    #pragma unroll
    for (int r = 0; r < KNN_BR; ++r) {
        int row = g*KNN_BR + r;
        qx[r] = px[row]; qy[r] = py[row]; qz[r] = pz[row];
        qs[r] = fmaf(qz[r], qz[r], fmaf(qy[r], qy[r], qx[r]*qx[r]));
    }

    // ---- pass 1: candidate-major, build 8 histograms ----------------------
    #pragma unroll 1
    for (int t = 0; t < 15; ++t) {
        int j = t*256 + tid;
        bool v = j < HWP;
        float x = 0.f, y = 0.f, z = 0.f, sj = 0.f;
        if (v) { x = px[j]; y = py[j]; z = pz[j]; sj = fmaf(z, z, fmaf(y, y, x*x)); }
        #pragma unroll
        for (int r = 0; r < KNN_BR; ++r) {
            unsigned bits = 0x7f800000u;
            if (v) {
                float dot = fmaf(qz[r], z, fmaf(qy[r], y, qx[r]*x));
                bits = __float_as_uint(fmaxf(qs[r] + sj - 2.0f*dot, 0.0f));
            }
            unsigned e = bits >> 23;
            unsigned mask = __match_any_sync(0xffffffffu, e);
            if (lane == (unsigned)(__ffs(mask) - 1)) atomicAdd(&hist[r*256 + e], __popc(mask));
        }
    }
    __syncthreads();                                   // B1

    // ---- scan: warp w scans hist[w] ----------------------------------------
    if (wid < KNN_BR) {
        int* h8 = hist + wid*256;
        int basebin = lane*8, loc[8], ssum = 0;
        #pragma unroll
        for (int j2 = 0; j2 < 8; ++j2) { loc[j2] = h8[basebin + j2]; ssum += loc[j2]; }
        int pre = ssum;
        #pragma unroll
        for (int o = 1; o < 32; o <<= 1) {
            int v2 = __shfl_up_sync(0xffffffffu, pre, o);
            if (lane >= (unsigned)o) pre += v2;
        }
        int excl = pre - ssum;
        int ec = 0;
        if (excl < KNN && excl + ssum >= KNN) {        // unique crossing lane
            int cum = excl;
            #pragma unroll
            for (int j2 = 0; j2 < 8; ++j2) {
                if (cum + loc[j2] >= KNN) { ec = basebin + j2; break; }
                cum += loc[j2];
            }
        }
        ec = __reduce_max_sync(0xffffffffu, ec);
        if (lane == 0) ecrit[wid] = ec;
    }
    __syncthreads();                                   // B2

    int Ereg[KNN_BR];
    #pragma unroll
    for (int r = 0; r < KNN_BR; ++r) Ereg[r] = ecrit[r];

    // ---- pass 2: recompute, ballot-aggregated compaction -------------------
    #pragma unroll 1
    for (int t = 0; t < 15; ++t) {
        int j = t*256 + tid;
        bool v = j < HWP;
        float x = 0.f, y = 0.f, z = 0.f, sj = 0.f;
        if (v) { x = px[j]; y = py[j]; z = pz[j]; sj = fmaf(z, z, fmaf(y, y, x*x)); }
        #pragma unroll
        for (int r = 0; r < KNN_BR; ++r) {
            unsigned bits = 0x7f800000u;
            if (v) {
                float dot = fmaf(qz[r], z, fmaf(qy[r], y, qx[r]*x));
                bits = __float_as_uint(fmaxf(qs[r] + sj - 2.0f*dot, 0.0f));
            }
            int e = (int)(bits >> 23);
            bool win = v && e < Ereg[r];
            unsigned mw = __ballot_sync(0xffffffffu, win);
            if (mw) {
                int src = __ffs(mw) - 1;
                int base = 0;
                if (lane == (unsigned)src) base = atomicAdd(&ocnt[r], __popc(mw));
                base = __shfl_sync(0xffffffffu, base, src);
                if (win) idx_out[(n*HWP + g*KNN_BR + r)*KNN + base + __popc(mw & ltm)] = j;
            }
            bool cand = v && e == Ereg[r];
            unsigned mc = __ballot_sync(0xffffffffu, cand);
            if (mc) {
                int src = __ffs(mc) - 1;
                int base = 0;
                if (lane == (unsigned)src) base = atomicAdd(&ccnt[r], __popc(mc));
                base = __shfl_sync(0xffffffffu, base, src);
                if (cand) {
                    int pos = base + __popc(mc & ltm);
                    if (pos < CAP) { cv[r*CAP + pos] = bits; ci[r*CAP + pos] = j; }
                }
            }
        }
    }
    __syncthreads();                                   // B3

    // ---- phase B: one row per warp ------------------------------------------
    if (wid < KNN_BR) {
        int r = wid;
        int row = g*KNN_BR + r;
        int* outp = idx_out + (n*HWP + row)*KNN;
        unsigned* wcv = cv + r*CAP;
        int* wci = ci + r*CAP;
        int* wtie = tiebuf + r*32;

        int oc0 = ocnt[r], cc = ccnt[r];
        int Kp = KNN - oc0;

        if (cc > CAP) {
            if (lane == 0) flag[r] = 1;
        } else if (cc == Kp) {
            for (int i = lane; i < cc; i += 32) outp[oc0 + i] = wci[i];
        } else {
            unsigned T = ((unsigned)Ereg[r]) << 23;
            for (int bit = 22; bit >= 0; --bit) {
                unsigned cnd = T | (1u << bit);
                int cnt = 0;
                for (int i = lane; i < cc; i += 32) cnt += (wcv[i] < cnd) ? 1 : 0;
                cnt = __reduce_add_sync(0xffffffffu, cnt);
                if (cnt < Kp) T = cnd;
            }
            int oc = oc0, tc = 0;
            for (int ib = 0; ib < cc; ib += 32) {
                int i = ib + lane;
                bool v = i < cc;
                unsigned bv = v ? wcv[i] : 0xffffffffu;
                unsigned mw = __ballot_sync(0xffffffffu, v && bv < T);
                if (v && bv < T) outp[oc + __popc(mw & ltm)] = wci[i];
                oc += __popc(mw);
                unsigned mt = __ballot_sync(0xffffffffu, v && bv == T);
                if (v && bv == T) {
                    int tp = tc + __popc(mt & ltm);
                    if (tp < 32) wtie[tp] = wci[i];
                }
                tc += __popc(mt);
            }
            __syncwarp();
            if (lane == 0) {
                int slots = KNN - oc;
                int en = tc < 32 ? tc : 32;
                for (int q2 = 0; q2 < slots; ++q2) {   // lowest-index tie fill
                    int best = 0x7fffffff, bi = 0;
                    for (int e2 = 0; e2 < en; ++e2)
                        if (wtie[e2] < best) { best = wtie[e2]; bi = e2; }
                    wtie[bi] = 0x7fffffff;
                    outp[oc + q2] = best;
                }
            }
        }
    }
    __syncthreads();

    // ---- fallback: block-wide 31-bit search (rare) --------------------------
    for (int r = 0; r < KNN_BR; ++r) {
        if (!flag[r]) continue;
        int row = g*KNN_BR + r;
        float fqx = qx[r], fqy = qy[r], fqz = qz[r], fqs = qs[r];

        unsigned d[15];
        #pragma unroll
        for (int t = 0; t < 15; ++t) {
            int j = t*256 + tid;
            if (j < HWP) {
                float x = px[j], y = py[j], z = pz[j];
                float sj  = fmaf(z, z, fmaf(y, y, x*x));
                float dot = fmaf(fqz, z, fmaf(fqy, y, fqx*x));
                d[t] = __float_as_uint(fmaxf(fqs + sj - 2.0f*dot, 0.0f));
            } else {
                d[t] = 0xffffffffu;
            }
        }
        if (tid == 0) { sc[0] = 0; sc[1] = 0; }
        __syncthreads();

        unsigned T = 0;
        for (int bit = 30; bit >= 0; --bit) {
            unsigned cnd = T | (1u << bit);
            int cc2 = 0;
            #pragma unroll
            for (int t = 0; t < 15; ++t) cc2 += (d[t] < cnd) ? 1 : 0;
            cc2 = __reduce_add_sync(0xffffffffu, cc2);
            int par = bit & 1;
            if (lane == 0) ws[par*8 + wid] = cc2;
            __syncthreads();
            int tot = 0;
            #pragma unroll
            for (int w = 0; w < 8; ++w) tot += ws[par*8 + w];
            if (tot < KNN) T = cnd;
        }
        __syncthreads();

        int* outp = idx_out + (n*HWP + row)*KNN;
        int* wtie = tiebuf + r*32;
        #pragma unroll
        for (int t = 0; t < 15; ++t) {
            int j = t*256 + tid;
            unsigned dv = d[t];
            if (dv < T) { int pos = atomicAdd(&sc[0], 1); outp[pos] = j; }
            else if (dv == T && j < HWP) { int pos = atomicAdd(&sc[1], 1); if (pos < 32) wtie[pos] = j; }
        }
        __syncthreads();
        if (tid == 0) {
            int slots = KNN - sc[0];
            int en = sc[1] < 32 ? sc[1] : 32;
            for (int q2 = 0; q2 < slots; ++q2) {
                int best = 0x7fffffff, bi = 0;
                for (int e2 = 0; e2 < en; ++e2)
                    if (wtie[e2] < best) { best = wtie[e2]; bi = e2; }
                wtie[bi] = 0x7fffffff;
                outp[sc[0] + q2] = best;
            }
        }
        __syncthreads();
    }
}

// ---------------- gather-mean: msg = mean_k m[idx]; emits bf16 split -------
__global__ void __launch_bounds__(512) gather_mean_kernel(const float* __restrict__ m,
                                                          const int* __restrict__ idx)
{
    __shared__ int sidx[8*KNN];
    int tid = threadIdx.x;
    int s0 = blockIdx.x * 8;
    sidx[tid] = idx[s0*KNN + tid];
    __syncthreads();

    int lp = tid >> 6;
    int c4 = tid & 63;
    int s  = s0 + lp;
    int base = (s / HWP) * HWP;
    const float4* m4 = reinterpret_cast<const float4*>(m);
    const int* ip = sidx + lp*KNN;

    float4 a0 = make_float4(0,0,0,0), a1 = a0, a2 = a0, a3 = a0;
    #pragma unroll
    for (int k = 0; k < KNN; k += 4) {
        int j0 = ip[k], j1 = ip[k+1], j2 = ip[k+2], j3 = ip[k+3];
        float4 v0 = m4[(size_t)(base + j0)*64 + c4];
        float4 v1 = m4[(size_t)(base + j1)*64 + c4];
        float4 v2 = m4[(size_t)(base + j2)*64 + c4];
        float4 v3 = m4[(size_t)(base + j3)*64 + c4];
        a0.x += v0.x; a0.y += v0.y; a0.z += v0.z; a0.w += v0.w;
        a1.x += v1.x; a1.y += v1.y; a1.z += v1.z; a1.w += v1.w;
        a2.x += v2.x; a2.y += v2.y; a2.z += v2.z; a2.w += v2.w;
        a3.x += v3.x; a3.y += v3.y; a3.z += v3.z; a3.w += v3.w;
    }
    const float inv = 1.0f / 64.0f;
    float4 r;
    r.x = (a0.x + a1.x + a2.x + a3.x) * inv;
    r.y = (a0.y + a1.y + a2.y + a3.y) * inv;
    r.z = (a0.z + a1.z + a2.z + a3.z) * inv;
    r.w = (a0.w + a1.w + a2.w + a3.w) * inv;

    __nv_bfloat16 hx, lx, hy, ly, hz, lz, hw, lw;
    bsplit(r.x, hx, lx); bsplit(r.y, hy, ly);
    bsplit(r.z, hz, lz); bsplit(r.w, hw, lw);
    int o = s*CDIM + c4*4;
    *(__nv_bfloat162*)(g_Mh + o)     = __nv_bfloat162(hx, hy);
    *(__nv_bfloat162*)(g_Mh + o + 2) = __nv_bfloat162(hz, hw);
    *(__nv_bfloat162*)(g_Ml + o)     = __nv_bfloat162(lx, ly);
    *(__nv_bfloat162*)(g_Ml + o + 2) = __nv_bfloat162(lz, lw);
}

// ---------------- launcher --------------------------------------------------
extern "C" void kernel_launch(void* const* d_in, const int* in_sizes, int n_in,
                              void* d_out, int out_size)
{
    const float* cnn   = (const float*)d_in[0];
    const float* pts   = (const float*)d_in[1];
    const float* mlp_w = (const float*)d_in[2];
    const float* mlp_b = (const float*)d_in[3];
    const float* rnn_w = (const float*)d_in[4];
    const float* rnn_b = (const float*)d_in[5];
    float* out = (float*)d_out;

    float *m, *tmp, *h;
    int* idx;
    cudaGetSymbolAddress((void**)&m,   g_m);
    cudaGetSymbolAddress((void**)&tmp, g_tmp);
    cudaGetSymbolAddress((void**)&h,   g_h);
    cudaGetSymbolAddress((void**)&idx, g_idx);

    cudaFuncSetAttribute(gemm1_kernel, cudaFuncAttributeMaxDynamicSharedMemorySize, GEMM_SMEM);
    cudaFuncSetAttribute(gemm3_kernel, cudaFuncAttributeMaxDynamicSharedMemorySize, GEMM_SMEM);
    cudaFuncSetAttribute(knn_kernel,   cudaFuncAttributeMaxDynamicSharedMemorySize, KNN_SMEM);

    wconv_kernel<<<768, 256>>>(mlp_w, rnn_w);
    init_kernel<<<(NBATCH*CDIM*HWP)/256, 256>>>(cnn, out);
    pad_kernel<<<96, 256>>>();
    knn_kernel<<<NBATCH*(HWP/KNN_BR), 256, KNN_SMEM>>>(pts, idx);

    for (int it = 0; it < 3; ++it) {
        gemm1_kernel<<<dim3(MPAD/128, 8), 256, GEMM_SMEM>>>(mlp_b, m, tmp);
        gather_mean_kernel<<<M_TOTAL/8, 512>>>(m, idx);
        gemm3_kernel<<<dim3(MPAD/128, 4), 256, GEMM_SMEM>>>(rnn_b, tmp, h);
    }
    final_kernel<<<(NBATCH*CDIM*HWP)/256, 256>>>(h, out);
}

// round 9
// speedup vs baseline: 1.6203x; 1.0842x over previous
#include <cuda_runtime.h>
#include <cuda_fp16.h>
#include <cstdint>

#define HWP 3600
#define NBATCH 2
#define CDIM 256
#define KNN 64
#define M_TOTAL (NBATCH*HWP)   // 7200
#define MPAD 7296              // padded rows (multiple of 128)

// ---------------- scratch (device globals; no allocation allowed) ----------
__device__ float g_m[MPAD*CDIM];        // relu(mlp(h)) fp32
__device__ float g_tmp[MPAD*CDIM];      // h @ Wa^T fp32
__device__ float g_h[MPAD*CDIM];        // fp32 h (for final readout)
__device__ __half g_Ah[MPAD*CDIM], g_Al[MPAD*CDIM];   // h split (fp16 hi/lo)
__device__ __half g_Mh[MPAD*CDIM], g_Ml[MPAD*CDIM];   // msg split
__device__ __half g_Wmh[CDIM*CDIM];                   // mlp_w hi
__device__ __half g_Wah[CDIM*CDIM];                   // rnn_w[:, :C] hi
__device__ __half g_Wbh[CDIM*CDIM];                   // rnn_w[:, C:] hi
__device__ int   g_idx[M_TOTAL*KNN];

__device__ __forceinline__ float4 ld4(const float* p){ return *reinterpret_cast<const float4*>(p); }
__device__ __forceinline__ void st4(float* p, float4 v){ *reinterpret_cast<float4*>(p) = v; }

// fp16 hi/lo split: v ~= h + l with combined 22-bit mantissa
__device__ __forceinline__ void hsplit(float v, __half& h, __half& l){
    h = __float2half_rn(v);
    l = __float2half_rn(v - __half2float(h));
}

__device__ __forceinline__ uint32_t smem_u32(const void* p) {
    uint32_t a;
    asm("{ .reg .u64 t; cvta.to.shared.u64 t, %1; cvt.u32.u64 %0, t; }" : "=r"(a) : "l"(p));
    return a;
}

// ---------------- mma.sync helpers (suffix-neutral PTX, tensor pipe) -------
__device__ __forceinline__ void ldmat4(uint32_t r[4], uint32_t addr){
    asm volatile("ldmatrix.sync.aligned.m8n8.x4.shared.b16 {%0,%1,%2,%3}, [%4];"
        : "=r"(r[0]), "=r"(r[1]), "=r"(r[2]), "=r"(r[3]) : "r"(addr));
}
__device__ __forceinline__ void mma16816(float c[4], const uint32_t a[4],
                                         uint32_t b0, uint32_t b1){
    asm volatile("mma.sync.aligned.m16n8k16.row.col.f32.f16.f16.f32 "
        "{%0,%1,%2,%3}, {%4,%5,%6,%7}, {%8,%9}, {%0,%1,%2,%3};"
        : "+f"(c[0]), "+f"(c[1]), "+f"(c[2]), "+f"(c[3])
        : "r"(a[0]), "r"(a[1]), "r"(a[2]), "r"(a[3]), "r"(b0), "r"(b1));
}

// smem tile layout: padded stride 72 fp16 (144B = 9 x 16B -> conflict-free)
#define ASTRIDE 72
#define OFF_AH  0
#define OFF_AL  18432
#define OFF_BH  36864
#define GEMM_SMEM 46080

// ---- 128x64x256 tile: fp16 2-term split via mma.sync, fp32 accumulate -----
// D = (Ah + Al) @ Bh^T ; error ~2^-11 per product (well under 1e-3 budget)
__device__ void tile_mma(const __half* __restrict__ Ah,
                         const __half* __restrict__ Al,
                         const __half* __restrict__ Bh,
                         int m0, float acc[2][4][4])
{
    extern __shared__ char smem[];
    const uint32_t sb = smem_u32(smem);
    const int tid = threadIdx.x;
    const int lane = tid & 31;
    const int wid = tid >> 5;
    const int wm = wid & 3;        // m32 section
    const int wn = wid >> 2;       // n32 section

    #pragma unroll
    for (int mt = 0; mt < 2; ++mt)
        #pragma unroll
        for (int nt = 0; nt < 4; ++nt)
            #pragma unroll
            for (int q = 0; q < 4; ++q) acc[mt][nt][q] = 0.f;

    const uint32_t aoff = (uint32_t)(((lane & 15)*ASTRIDE + (lane >> 4)*8) * 2);
    const uint32_t boff = (uint32_t)((((lane & 7) + ((lane >> 4) << 3))*ASTRIDE
                                      + ((lane >> 3) & 1)*8) * 2);

    #pragma unroll 1
    for (int kc = 0; kc < 4; ++kc) {
        #pragma unroll
        for (int i = 0; i < 10; ++i) {
            int v = tid + i*256;
            const uint4* src;
            uint32_t dst;
            if (v < 1024) {
                int row = v >> 3, c8 = v & 7;
                src = (const uint4*)(Ah + (m0 + row)*CDIM + kc*64 + c8*8);
                dst = OFF_AH + (uint32_t)(row*ASTRIDE + c8*8)*2;
            } else if (v < 2048) {
                int u = v - 1024, row = u >> 3, c8 = u & 7;
                src = (const uint4*)(Al + (m0 + row)*CDIM + kc*64 + c8*8);
                dst = OFF_AL + (uint32_t)(row*ASTRIDE + c8*8)*2;
            } else {
                int u = v - 2048, row = u >> 3, c8 = u & 7;
                src = (const uint4*)(Bh + row*CDIM + kc*64 + c8*8);
                dst = OFF_BH + (uint32_t)(row*ASTRIDE + c8*8)*2;
            }
            *(uint4*)(smem + dst) = *src;
        }
        __syncthreads();

        #pragma unroll
        for (int ks = 0; ks < 4; ++ks) {
            const uint32_t abase = (uint32_t)((wm*32*ASTRIDE + ks*16) * 2);
            const uint32_t bbase = (uint32_t)((wn*32*ASTRIDE + ks*16) * 2);
            const uint32_t mstep = (uint32_t)(16*ASTRIDE*2);

            uint32_t ah0[4], ah1[4], al0[4], al1[4];
            ldmat4(ah0, sb + OFF_AH + abase + aoff);
            ldmat4(ah1, sb + OFF_AH + abase + mstep + aoff);
            ldmat4(al0, sb + OFF_AL + abase + aoff);
            ldmat4(al1, sb + OFF_AL + abase + mstep + aoff);

            uint32_t bhA[4], bhB[4];
            ldmat4(bhA, sb + OFF_BH + bbase + boff);
            ldmat4(bhB, sb + OFF_BH + bbase + mstep + boff);

            mma16816(acc[0][0], ah0, bhA[0], bhA[1]);
            mma16816(acc[0][1], ah0, bhA[2], bhA[3]);
            mma16816(acc[0][2], ah0, bhB[0], bhB[1]);
            mma16816(acc[0][3], ah0, bhB[2], bhB[3]);
            mma16816(acc[1][0], ah1, bhA[0], bhA[1]);
            mma16816(acc[1][1], ah1, bhA[2], bhA[3]);
            mma16816(acc[1][2], ah1, bhB[0], bhB[1]);
            mma16816(acc[1][3], ah1, bhB[2], bhB[3]);

            mma16816(acc[0][0], al0, bhA[0], bhA[1]);
            mma16816(acc[0][1], al0, bhA[2], bhA[3]);
            mma16816(acc[0][2], al0, bhB[0], bhB[1]);
            mma16816(acc[0][3], al0, bhB[2], bhB[3]);
            mma16816(acc[1][0], al1, bhA[0], bhA[1]);
            mma16816(acc[1][1], al1, bhA[2], bhA[3]);
            mma16816(acc[1][2], al1, bhB[0], bhB[1]);
            mma16816(acc[1][3], al1, bhB[2], bhB[3]);
        }
        __syncthreads();
    }
}

// GEMM1: by 0..3 -> m = relu(h Wmlp^T + b);  by 4..7 -> tmp = h Wa^T
__global__ void __launch_bounds__(256) gemm1_kernel(const float* __restrict__ mlp_b,
                                                    float* __restrict__ m_out,
                                                    float* __restrict__ tmp_out)
{
    int m0 = blockIdx.x * 128;
    int by = blockIdx.y;
    bool is_m = by < 4;
    int d0 = (is_m ? by : by - 4) * 64;
    const __half* Bh = (is_m ? g_Wmh : g_Wah) + d0*CDIM;

    float acc[2][4][4];
    tile_mma(g_Ah, g_Al, Bh, m0, acc);

    int lane = threadIdx.x & 31, wid = threadIdx.x >> 5;
    int wm = wid & 3, wn = wid >> 2;
    int g = lane >> 2, t = lane & 3;

    #pragma unroll
    for (int mt = 0; mt < 2; ++mt) {
        #pragma unroll
        for (int nt = 0; nt < 4; ++nt) {
            int nl = wn*32 + nt*8 + t*2;
            int n = d0 + nl;
            float bx = 0.f, byv = 0.f;
            if (is_m) { bx = mlp_b[n]; byv = mlp_b[n+1]; }
            #pragma unroll
            for (int half = 0; half < 2; ++half) {
                int m = m0 + wm*32 + mt*16 + g + half*8;
                if (m >= M_TOTAL) continue;
                float vx = acc[mt][nt][half*2+0];
                float vy = acc[mt][nt][half*2+1];
                if (is_m) {
                    vx = fmaxf(vx + bx, 0.f);
                    vy = fmaxf(vy + byv, 0.f);
                    *(float2*)(m_out + m*CDIM + n) = make_float2(vx, vy);
                } else {
                    *(float2*)(tmp_out + m*CDIM + n) = make_float2(vx, vy);
                }
            }
        }
    }
}

// GEMM3: h' = relu(tmp + msg Wb^T + b_rnn); writes fp32 h and fp16 split
__global__ void __launch_bounds__(256) gemm3_kernel(const float* __restrict__ rnn_b,
                                                    const float* __restrict__ tmp,
                                                    float* __restrict__ h_out)
{
    int m0 = blockIdx.x * 128;
    int d0 = blockIdx.y * 64;

    float acc[2][4][4];
    tile_mma(g_Mh, g_Ml, g_Wbh + d0*CDIM, m0, acc);

    int lane = threadIdx.x & 31, wid = threadIdx.x >> 5;
    int wm = wid & 3, wn = wid >> 2;
    int g = lane >> 2, t = lane & 3;

    #pragma unroll
    for (int mt = 0; mt < 2; ++mt) {
        #pragma unroll
        for (int nt = 0; nt < 4; ++nt) {
            int n = d0 + wn*32 + nt*8 + t*2;
            float bx = rnn_b[n], byv = rnn_b[n+1];
            #pragma unroll
            for (int half = 0; half < 2; ++half) {
                int m = m0 + wm*32 + mt*16 + g + half*8;
                if (m >= M_TOTAL) continue;
                float2 tv = *(const float2*)(tmp + m*CDIM + n);
                float vx = fmaxf(acc[mt][nt][half*2+0] + tv.x + bx, 0.f);
                float vy = fmaxf(acc[mt][nt][half*2+1] + tv.y + byv, 0.f);
                *(float2*)(h_out + m*CDIM + n) = make_float2(vx, vy);
                __half hx, lx, hy, ly;
                hsplit(vx, hx, lx); hsplit(vy, hy, ly);
                *(__half2*)(g_Ah + m*CDIM + n) = __halves2half2(hx, hy);
                *(__half2*)(g_Al + m*CDIM + n) = __halves2half2(lx, ly);
            }
        }
    }
}

// ---------------- weight conversion (once per call) ------------------------
__global__ void __launch_bounds__(256) wconv_kernel(const float* __restrict__ mlp_w,
                                                    const float* __restrict__ rnn_w)
{
    int e = blockIdx.x * 256 + threadIdx.x;   // < 256*768
    if (e < CDIM*CDIM) {
        g_Wmh[e] = __float2half_rn(mlp_w[e]);
    } else {
        int u = e - CDIM*CDIM;                 // < 256*512
        int r = u >> 9, c = u & 511;
        __half h = __float2half_rn(rnn_w[u]);
        if (c < CDIM) g_Wah[r*CDIM + c] = h;
        else          g_Wbh[r*CDIM + c - CDIM] = h;
    }
}

// zero padded rows of fp16 operand arrays
__global__ void __launch_bounds__(256) pad_kernel()
{
    int e = blockIdx.x * 256 + threadIdx.x;   // < 96*256
    int o = (M_TOTAL + (e >> 8))*CDIM + (e & 255);
    g_Ah[o] = __float2half(0.f); g_Al[o] = __float2half(0.f);
    g_Mh[o] = __float2half(0.f); g_Ml[o] = __float2half(0.f);
}

// ---------------- init: out[:, :256] = cnn; Ah/Al = fp16 split of NHWC h0 --
__global__ void __launch_bounds__(256) init_kernel(const float* __restrict__ cnn,
                                                   float* __restrict__ out)
{
    int e = blockIdx.x * 256 + threadIdx.x;
    int s = e % HWP;
    int c = (e / HWP) & (CDIM-1);
    int n = e / (HWP*CDIM);
    float v = cnn[e];
    out[(n*(2*CDIM) + c)*HWP + s] = v;
    __half h, l; hsplit(v, h, l);
    int o = (n*HWP + s)*CDIM + c;
    g_Ah[o] = h; g_Al[o] = l;
}

__global__ void __launch_bounds__(256) final_kernel(const float* __restrict__ h,
                                                    float* __restrict__ out)
{
    int e = blockIdx.x * 256 + threadIdx.x;
    int s = e % HWP;
    int c = (e / HWP) & (CDIM-1);
    int n = e / (HWP*CDIM);
    out[(n*(2*CDIM) + CDIM + c)*HWP + s] = h[(n*HWP + s)*CDIM + c];
}

// ---------------- KNN v5: candidate-major phase-A, 8 rows/block ------------
#define KNN_BR 8
#define CAP 256
// dynamic smem layout (bytes)
#define KPX    0                        // float[3600]  14400
#define KPY    14400
#define KPZ    28800                    // end 43200
#define KHIST  43200                    // int[8][256]   8192
#define KCV    51392                    // u32[8][CAP]   8192
#define KCI    59584                    // int[8][CAP]   8192
#define KTIE   67776                    // int[8][32]    1024
#define KOCNT  68800                    // int[8]
#define KCCNT  68832                    // int[8]
#define KECRIT 68864                    // int[8]
#define KFLAG  68896                    // int[8]
#define KWS    68928                    // int[2][8]
#define KSC    68992                    // int[4]
#define KNN_SMEM 69120

__global__ void __launch_bounds__(256) knn_kernel(const float* __restrict__ pts,
                                                  int* __restrict__ idx_out)
{
    extern __shared__ char sm[];
    float* px = (float*)(sm + KPX);
    float* py = (float*)(sm + KPY);
    float* pz = (float*)(sm + KPZ);
    int* hist = (int*)(sm + KHIST);
    unsigned* cv = (unsigned*)(sm + KCV);
    int* ci = (int*)(sm + KCI);
    int* tiebuf = (int*)(sm + KTIE);
    int* ocnt  = (int*)(sm + KOCNT);
    int* ccnt  = (int*)(sm + KCCNT);
    int* ecrit = (int*)(sm + KECRIT);
    int* flag  = (int*)(sm + KFLAG);
    int* ws    = (int*)(sm + KWS);
    int* sc    = (int*)(sm + KSC);

    int gb = blockIdx.x;
    int n  = gb / (HWP/KNN_BR);
    int g  = gb % (HWP/KNN_BR);
    int tid = threadIdx.x;
    int lane = tid & 31, wid = tid >> 5;
    const unsigned ltm = (1u << lane) - 1u;

    const float* p = pts + n*3*HWP;
    for (int i = tid; i < HWP; i += 256) {
        px[i] = p[i];
        py[i] = p[i + HWP];
        pz[i] = p[i + 2*HWP];
    }
    #pragma unroll
    for (int i = 0; i < KNN_BR; ++i) hist[i*256 + tid] = 0;
    if (tid < KNN_BR) { ocnt[tid] = 0; ccnt[tid] = 0; flag[tid] = 0; }
    __syncthreads();                                   // B0

    // query coords in registers
    float qx[KNN_BR], qy[KNN_BR], qz[KNN_BR], qs[KNN_BR];
    #pragma unroll
    for (int r = 0; r < KNN_BR; ++r) {
        int row = g*KNN_BR + r;
        qx[r] = px[row]; qy[r] = py[row]; qz[r] = pz[row];
        qs[r] = fmaf(qz[r], qz[r], fmaf(qy[r], qy[r], qx[r]*qx[r]));
    }

    // ---- pass 1: candidate-major, build 8 histograms ----------------------
    #pragma unroll 1
    for (int t = 0; t < 15; ++t) {
        int j = t*256 + tid;
        bool v = j < HWP;
        float x = 0.f, y = 0.f, z = 0.f, sj = 0.f;
        if (v) { x = px[j]; y = py[j]; z = pz[j]; sj = fmaf(z, z, fmaf(y, y, x*x)); }
        #pragma unroll
        for (int r = 0; r < KNN_BR; ++r) {
            unsigned bits = 0x7f800000u;
            if (v) {
                float dot = fmaf(qz[r], z, fmaf(qy[r], y, qx[r]*x));
                bits = __float_as_uint(fmaxf(qs[r] + sj - 2.0f*dot, 0.0f));
            }
            unsigned e = bits >> 23;
            unsigned mask = __match_any_sync(0xffffffffu, e);
            if (lane == (unsigned)(__ffs(mask) - 1)) atomicAdd(&hist[r*256 + e], __popc(mask));
        }
    }
    __syncthreads();                                   // B1

    // ---- scan: warp w scans hist[w] ----------------------------------------
    if (wid < KNN_BR) {
        int* h8 = hist + wid*256;
        int basebin = lane*8, loc[8], ssum = 0;
        #pragma unroll
        for (int j2 = 0; j2 < 8; ++j2) { loc[j2] = h8[basebin + j2]; ssum += loc[j2]; }
        int pre = ssum;
        #pragma unroll
        for (int o = 1; o < 32; o <<= 1) {
            int v2 = __shfl_up_sync(0xffffffffu, pre, o);
            if (lane >= (unsigned)o) pre += v2;
        }
        int excl = pre - ssum;
        int ec = 0;
        if (excl < KNN && excl + ssum >= KNN) {        // unique crossing lane
            int cum = excl;
            #pragma unroll
            for (int j2 = 0; j2 < 8; ++j2) {
                if (cum + loc[j2] >= KNN) { ec = basebin + j2; break; }
                cum += loc[j2];
            }
        }
        ec = __reduce_max_sync(0xffffffffu, ec);
        if (lane == 0) ecrit[wid] = ec;
    }
    __syncthreads();                                   // B2

    int Ereg[KNN_BR];
    #pragma unroll
    for (int r = 0; r < KNN_BR; ++r) Ereg[r] = ecrit[r];

    // ---- pass 2: recompute, ballot-aggregated compaction -------------------
    #pragma unroll 1
    for (int t = 0; t < 15; ++t) {
        int j = t*256 + tid;
        bool v = j < HWP;
        float x = 0.f, y = 0.f, z = 0.f, sj = 0.f;
        if (v) { x = px[j]; y = py[j]; z = pz[j]; sj = fmaf(z, z, fmaf(y, y, x*x)); }
        #pragma unroll
        for (int r = 0; r < KNN_BR; ++r) {
            unsigned bits = 0x7f800000u;
            if (v) {
                float dot = fmaf(qz[r], z, fmaf(qy[r], y, qx[r]*x));
                bits = __float_as_uint(fmaxf(qs[r] + sj - 2.0f*dot, 0.0f));
            }
            int e = (int)(bits >> 23);
            bool win = v && e < Ereg[r];
            unsigned mw = __ballot_sync(0xffffffffu, win);
            if (mw) {
                int src = __ffs(mw) - 1;
                int base = 0;
                if (lane == (unsigned)src) base = atomicAdd(&ocnt[r], __popc(mw));
                base = __shfl_sync(0xffffffffu, base, src);
                if (win) idx_out[(n*HWP + g*KNN_BR + r)*KNN + base + __popc(mw & ltm)] = j;
            }
            bool cand = v && e == Ereg[r];
            unsigned mc = __ballot_sync(0xffffffffu, cand);
            if (mc) {
                int src = __ffs(mc) - 1;
                int base = 0;
                if (lane == (unsigned)src) base = atomicAdd(&ccnt[r], __popc(mc));
                base = __shfl_sync(0xffffffffu, base, src);
                if (cand) {
                    int pos = base + __popc(mc & ltm);
                    if (pos < CAP) { cv[r*CAP + pos] = bits; ci[r*CAP + pos] = j; }
                }
            }
        }
    }
    __syncthreads();                                   // B3

    // ---- phase B: one row per warp ------------------------------------------
    if (wid < KNN_BR) {
        int r = wid;
        int row = g*KNN_BR + r;
        int* outp = idx_out + (n*HWP + row)*KNN;
        unsigned* wcv = cv + r*CAP;
        int* wci = ci + r*CAP;
        int* wtie = tiebuf + r*32;

        int oc0 = ocnt[r], cc = ccnt[r];
        int Kp = KNN - oc0;

        if (cc > CAP) {
            if (lane == 0) flag[r] = 1;
        } else if (cc == Kp) {
            for (int i = lane; i < cc; i += 32) outp[oc0 + i] = wci[i];
        } else {
            unsigned T = ((unsigned)Ereg[r]) << 23;
            for (int bit = 22; bit >= 0; --bit) {
                unsigned cnd = T | (1u << bit);
                int cnt = 0;
                for (int i = lane; i < cc; i += 32) cnt += (wcv[i] < cnd) ? 1 : 0;
                cnt = __reduce_add_sync(0xffffffffu, cnt);
                if (cnt < Kp) T = cnd;
            }
            int oc = oc0, tc = 0;
            for (int ib = 0; ib < cc; ib += 32) {
                int i = ib + lane;
                bool v = i < cc;
                unsigned bv = v ? wcv[i] : 0xffffffffu;
                unsigned mw = __ballot_sync(0xffffffffu, v && bv < T);
                if (v && bv < T) outp[oc + __popc(mw & ltm)] = wci[i];
                oc += __popc(mw);
                unsigned mt = __ballot_sync(0xffffffffu, v && bv == T);
                if (v && bv == T) {
                    int tp = tc + __popc(mt & ltm);
                    if (tp < 32) wtie[tp] = wci[i];
                }
                tc += __popc(mt);
            }
            __syncwarp();
            if (lane == 0) {
                int slots = KNN - oc;
                int en = tc < 32 ? tc : 32;
                for (int q2 = 0; q2 < slots; ++q2) {   // lowest-index tie fill
                    int best = 0x7fffffff, bi = 0;
                    for (int e2 = 0; e2 < en; ++e2)
                        if (wtie[e2] < best) { best = wtie[e2]; bi = e2; }
                    wtie[bi] = 0x7fffffff;
                    outp[oc + q2] = best;
                }
            }
        }
    }
    __syncthreads();

    // ---- fallback: block-wide 31-bit search (rare) --------------------------
    for (int r = 0; r < KNN_BR; ++r) {
        if (!flag[r]) continue;
        int row = g*KNN_BR + r;
        float fqx = qx[r], fqy = qy[r], fqz = qz[r], fqs = qs[r];

        unsigned d[15];
        #pragma unroll
        for (int t = 0; t < 15; ++t) {
            int j = t*256 + tid;
            if (j < HWP) {
                float x = px[j], y = py[j], z = pz[j];
                float sj  = fmaf(z, z, fmaf(y, y, x*x));
                float dot = fmaf(fqz, z, fmaf(fqy, y, fqx*x));
                d[t] = __float_as_uint(fmaxf(fqs + sj - 2.0f*dot, 0.0f));
            } else {
                d[t] = 0xffffffffu;
            }
        }
        if (tid == 0) { sc[0] = 0; sc[1] = 0; }
        __syncthreads();

        unsigned T = 0;
        for (int bit = 30; bit >= 0; --bit) {
            unsigned cnd = T | (1u << bit);
            int cc2 = 0;
            #pragma unroll
            for (int t = 0; t < 15; ++t) cc2 += (d[t] < cnd) ? 1 : 0;
            cc2 = __reduce_add_sync(0xffffffffu, cc2);
            int par = bit & 1;
            if (lane == 0) ws[par*8 + wid] = cc2;
            __syncthreads();
            int tot = 0;
            #pragma unroll
            for (int w = 0; w < 8; ++w) tot += ws[par*8 + w];
            if (tot < KNN) T = cnd;
        }
        __syncthreads();

        int* outp = idx_out + (n*HWP + row)*KNN;
        int* wtie = tiebuf + r*32;
        #pragma unroll
        for (int t = 0; t < 15; ++t) {
            int j = t*256 + tid;
            unsigned dv = d[t];
            if (dv < T) { int pos = atomicAdd(&sc[0], 1); outp[pos] = j; }
            else if (dv == T && j < HWP) { int pos = atomicAdd(&sc[1], 1); if (pos < 32) wtie[pos] = j; }
        }
        __syncthreads();
        if (tid == 0) {
            int slots = KNN - sc[0];
            int en = sc[1] < 32 ? sc[1] : 32;
            for (int q2 = 0; q2 < slots; ++q2) {
                int best = 0x7fffffff, bi = 0;
                for (int e2 = 0; e2 < en; ++e2)
                    if (wtie[e2] < best) { best = wtie[e2]; bi = e2; }
                wtie[bi] = 0x7fffffff;
                outp[sc[0] + q2] = best;
            }
        }
        __syncthreads();
    }
}

// ---------------- gather-mean: msg = mean_k m[idx]; emits fp16 split -------
__global__ void __launch_bounds__(512) gather_mean_kernel(const float* __restrict__ m,
                                                          const int* __restrict__ idx)
{
    __shared__ int sidx[8*KNN];
    int tid = threadIdx.x;
    int s0 = blockIdx.x * 8;
    sidx[tid] = idx[s0*KNN + tid];
    __syncthreads();

    int lp = tid >> 6;
    int c4 = tid & 63;
    int s  = s0 + lp;
    int base = (s / HWP) * HWP;
    const float4* m4 = reinterpret_cast<const float4*>(m);
    const int* ip = sidx + lp*KNN;

    float4 a0 = make_float4(0,0,0,0), a1 = a0, a2 = a0, a3 = a0;
    #pragma unroll
    for (int k = 0; k < KNN; k += 4) {
        int j0 = ip[k], j1 = ip[k+1], j2 = ip[k+2], j3 = ip[k+3];
        float4 v0 = m4[(size_t)(base + j0)*64 + c4];
        float4 v1 = m4[(size_t)(base + j1)*64 + c4];
        float4 v2 = m4[(size_t)(base + j2)*64 + c4];
        float4 v3 = m4[(size_t)(base + j3)*64 + c4];
        a0.x += v0.x; a0.y += v0.y; a0.z += v0.z; a0.w += v0.w;
        a1.x += v1.x; a1.y += v1.y; a1.z += v1.z; a1.w += v1.w;
        a2.x += v2.x; a2.y += v2.y; a2.z += v2.z; a2.w += v2.w;
        a3.x += v3.x; a3.y += v3.y; a3.z += v3.z; a3.w += v3.w;
    }
    const float inv = 1.0f / 64.0f;
    float4 r;
    r.x = (a0.x + a1.x + a2.x + a3.x) * inv;
    r.y = (a0.y + a1.y + a2.y + a3.y) * inv;
    r.z = (a0.z + a1.z + a2.z + a3.z) * inv;
    r.w = (a0.w + a1.w + a2.w + a3.w) * inv;

    __half hx, lx, hy, ly, hz, lz, hw, lw;
    hsplit(r.x, hx, lx); hsplit(r.y, hy, ly);
    hsplit(r.z, hz, lz); hsplit(r.w, hw, lw);
    int o = s*CDIM + c4*4;
    *(__half2*)(g_Mh + o)     = __halves2half2(hx, hy);
    *(__half2*)(g_Mh + o + 2) = __halves2half2(hz, hw);
    *(__half2*)(g_Ml + o)     = __halves2half2(lx, ly);
    *(__half2*)(g_Ml + o + 2) = __halves2half2(lz, lw);
}

// ---------------- launcher --------------------------------------------------
extern "C" void kernel_launch(void* const* d_in, const int* in_sizes, int n_in,
                              void* d_out, int out_size)
{
    const float* cnn   = (const float*)d_in[0];
    const float* pts   = (const float*)d_in[1];
    const float* mlp_w = (const float*)d_in[2];
    const float* mlp_b = (const float*)d_in[3];
    const float* rnn_w = (const float*)d_in[4];
    const float* rnn_b = (const float*)d_in[5];
    float* out = (float*)d_out;

    float *m, *tmp, *h;
    int* idx;
    cudaGetSymbolAddress((void**)&m,   g_m);
    cudaGetSymbolAddress((void**)&tmp, g_tmp);
    cudaGetSymbolAddress((void**)&h,   g_h);
    cudaGetSymbolAddress((void**)&idx, g_idx);

    cudaFuncSetAttribute(gemm1_kernel, cudaFuncAttributeMaxDynamicSharedMemorySize, GEMM_SMEM);
    cudaFuncSetAttribute(gemm3_kernel, cudaFuncAttributeMaxDynamicSharedMemorySize, GEMM_SMEM);
    cudaFuncSetAttribute(knn_kernel,   cudaFuncAttributeMaxDynamicSharedMemorySize, KNN_SMEM);

    wconv_kernel<<<768, 256>>>(mlp_w, rnn_w);
    init_kernel<<<(NBATCH*CDIM*HWP)/256, 256>>>(cnn, out);
    pad_kernel<<<96, 256>>>();
    knn_kernel<<<NBATCH*(HWP/KNN_BR), 256, KNN_SMEM>>>(pts, idx);

    for (int it = 0; it < 3; ++it) {
        gemm1_kernel<<<dim3(MPAD/128, 8), 256, GEMM_SMEM>>>(mlp_b, m, tmp);
        gather_mean_kernel<<<M_TOTAL/8, 512>>>(m, idx);
        gemm3_kernel<<<dim3(MPAD/128, 4), 256, GEMM_SMEM>>>(rnn_b, tmp, h);
    }
    final_kernel<<<(NBATCH*CDIM*HWP)/256, 256>>>(h, out);
}

// round 10
// speedup vs baseline: 1.6611x; 1.0252x over previous
#include <cuda_runtime.h>
#include <cuda_fp16.h>
#include <cstdint>

#define HWP 3600
#define NBATCH 2
#define CDIM 256
#define KNN 64
#define M_TOTAL (NBATCH*HWP)   // 7200
#define MPAD 7296              // padded rows (multiple of 128)

// ---------------- scratch (device globals; no allocation allowed) ----------
__device__ __half g_m[MPAD*CDIM];       // relu(mlp(h)) fp16
__device__ float g_tmp[MPAD*CDIM];      // h @ Wa^T fp32
__device__ float g_h[MPAD*CDIM];        // fp32 h (for final readout)
__device__ __half g_Ah[MPAD*CDIM], g_Al[MPAD*CDIM];   // h split (fp16 hi/lo)
__device__ __half g_Mh[MPAD*CDIM], g_Ml[MPAD*CDIM];   // msg split
__device__ __half g_Wmh[CDIM*CDIM];                   // mlp_w hi
__device__ __half g_Wah[CDIM*CDIM];                   // rnn_w[:, :C] hi
__device__ __half g_Wbh[CDIM*CDIM];                   // rnn_w[:, C:] hi
__device__ int   g_idx[M_TOTAL*KNN];

__device__ __forceinline__ float4 ld4(const float* p){ return *reinterpret_cast<const float4*>(p); }
__device__ __forceinline__ void st4(float* p, float4 v){ *reinterpret_cast<float4*>(p) = v; }

// fp16 hi/lo split: v ~= h + l with combined 22-bit mantissa
__device__ __forceinline__ void hsplit(float v, __half& h, __half& l){
    h = __float2half_rn(v);
    l = __float2half_rn(v - __half2float(h));
}

__device__ __forceinline__ uint32_t smem_u32(const void* p) {
    uint32_t a;
    asm("{ .reg .u64 t; cvta.to.shared.u64 t, %1; cvt.u32.u64 %0, t; }" : "=r"(a) : "l"(p));
    return a;
}

// ---------------- mma.sync helpers (suffix-neutral PTX, tensor pipe) -------
__device__ __forceinline__ void ldmat4(uint32_t r[4], uint32_t addr){
    asm volatile("ldmatrix.sync.aligned.m8n8.x4.shared.b16 {%0,%1,%2,%3}, [%4];"
        : "=r"(r[0]), "=r"(r[1]), "=r"(r[2]), "=r"(r[3]) : "r"(addr));
}
__device__ __forceinline__ void mma16816(float c[4], const uint32_t a[4],
                                         uint32_t b0, uint32_t b1){
    asm volatile("mma.sync.aligned.m16n8k16.row.col.f32.f16.f16.f32 "
        "{%0,%1,%2,%3}, {%4,%5,%6,%7}, {%8,%9}, {%0,%1,%2,%3};"
        : "+f"(c[0]), "+f"(c[1]), "+f"(c[2]), "+f"(c[3])
        : "r"(a[0]), "r"(a[1]), "r"(a[2]), "r"(a[3]), "r"(b0), "r"(b1));
}

// smem tile layout: padded stride 72 fp16 (144B = 9 x 16B -> conflict-free)
#define ASTRIDE 72
#define OFF_AH  0
#define OFF_AL  18432
#define OFF_BH  36864
#define GEMM_SMEM 46080

// ---- 128x64x256 tile: fp16 2-term split via mma.sync, fp32 accumulate -----
__device__ void tile_mma(const __half* __restrict__ Ah,
                         const __half* __restrict__ Al,
                         const __half* __restrict__ Bh,
                         int m0, float acc[2][4][4])
{
    extern __shared__ char smem[];
    const uint32_t sb = smem_u32(smem);
    const int tid = threadIdx.x;
    const int lane = tid & 31;
    const int wid = tid >> 5;
    const int wm = wid & 3;        // m32 section
    const int wn = wid >> 2;       // n32 section

    #pragma unroll
    for (int mt = 0; mt < 2; ++mt)
        #pragma unroll
        for (int nt = 0; nt < 4; ++nt)
            #pragma unroll
            for (int q = 0; q < 4; ++q) acc[mt][nt][q] = 0.f;

    const uint32_t aoff = (uint32_t)(((lane & 15)*ASTRIDE + (lane >> 4)*8) * 2);
    const uint32_t boff = (uint32_t)((((lane & 7) + ((lane >> 4) << 3))*ASTRIDE
                                      + ((lane >> 3) & 1)*8) * 2);

    #pragma unroll 1
    for (int kc = 0; kc < 4; ++kc) {
        #pragma unroll
        for (int i = 0; i < 10; ++i) {
            int v = tid + i*256;
            const uint4* src;
            uint32_t dst;
            if (v < 1024) {
                int row = v >> 3, c8 = v & 7;
                src = (const uint4*)(Ah + (m0 + row)*CDIM + kc*64 + c8*8);
                dst = OFF_AH + (uint32_t)(row*ASTRIDE + c8*8)*2;
            } else if (v < 2048) {
                int u = v - 1024, row = u >> 3, c8 = u & 7;
                src = (const uint4*)(Al + (m0 + row)*CDIM + kc*64 + c8*8);
                dst = OFF_AL + (uint32_t)(row*ASTRIDE + c8*8)*2;
            } else {
                int u = v - 2048, row = u >> 3, c8 = u & 7;
                src = (const uint4*)(Bh + row*CDIM + kc*64 + c8*8);
                dst = OFF_BH + (uint32_t)(row*ASTRIDE + c8*8)*2;
            }
            *(uint4*)(smem + dst) = *src;
        }
        __syncthreads();

        #pragma unroll
        for (int ks = 0; ks < 4; ++ks) {
            const uint32_t abase = (uint32_t)((wm*32*ASTRIDE + ks*16) * 2);
            const uint32_t bbase = (uint32_t)((wn*32*ASTRIDE + ks*16) * 2);
            const uint32_t mstep = (uint32_t)(16*ASTRIDE*2);

            uint32_t ah0[4], ah1[4], al0[4], al1[4];
            ldmat4(ah0, sb + OFF_AH + abase + aoff);
            ldmat4(ah1, sb + OFF_AH + abase + mstep + aoff);
            ldmat4(al0, sb + OFF_AL + abase + aoff);
            ldmat4(al1, sb + OFF_AL + abase + mstep + aoff);

            uint32_t bhA[4], bhB[4];
            ldmat4(bhA, sb + OFF_BH + bbase + boff);
            ldmat4(bhB, sb + OFF_BH + bbase + mstep + boff);

            mma16816(acc[0][0], ah0, bhA[0], bhA[1]);
            mma16816(acc[0][1], ah0, bhA[2], bhA[3]);
            mma16816(acc[0][2], ah0, bhB[0], bhB[1]);
            mma16816(acc[0][3], ah0, bhB[2], bhB[3]);
            mma16816(acc[1][0], ah1, bhA[0], bhA[1]);
            mma16816(acc[1][1], ah1, bhA[2], bhA[3]);
            mma16816(acc[1][2], ah1, bhB[0], bhB[1]);
            mma16816(acc[1][3], ah1, bhB[2], bhB[3]);

            mma16816(acc[0][0], al0, bhA[0], bhA[1]);
            mma16816(acc[0][1], al0, bhA[2], bhA[3]);
            mma16816(acc[0][2], al0, bhB[0], bhB[1]);
            mma16816(acc[0][3], al0, bhB[2], bhB[3]);
            mma16816(acc[1][0], al1, bhA[0], bhA[1]);
            mma16816(acc[1][1], al1, bhA[2], bhA[3]);
            mma16816(acc[1][2], al1, bhB[0], bhB[1]);
            mma16816(acc[1][3], al1, bhB[2], bhB[3]);
        }
        __syncthreads();
    }
}

// GEMM1: by 0..3 -> m = relu(h Wmlp^T + b) (fp16);  by 4..7 -> tmp = h Wa^T
__global__ void __launch_bounds__(256) gemm1_kernel(const float* __restrict__ mlp_b,
                                                    float* __restrict__ tmp_out)
{
    int m0 = blockIdx.x * 128;
    int by = blockIdx.y;
    bool is_m = by < 4;
    int d0 = (is_m ? by : by - 4) * 64;
    const __half* Bh = (is_m ? g_Wmh : g_Wah) + d0*CDIM;

    float acc[2][4][4];
    tile_mma(g_Ah, g_Al, Bh, m0, acc);

    int lane = threadIdx.x & 31, wid = threadIdx.x >> 5;
    int wm = wid & 3, wn = wid >> 2;
    int g = lane >> 2, t = lane & 3;

    #pragma unroll
    for (int mt = 0; mt < 2; ++mt) {
        #pragma unroll
        for (int nt = 0; nt < 4; ++nt) {
            int nl = wn*32 + nt*8 + t*2;
            int n = d0 + nl;
            float bx = 0.f, byv = 0.f;
            if (is_m) { bx = mlp_b[n]; byv = mlp_b[n+1]; }
            #pragma unroll
            for (int half = 0; half < 2; ++half) {
                int m = m0 + wm*32 + mt*16 + g + half*8;
                if (m >= M_TOTAL) continue;
                float vx = acc[mt][nt][half*2+0];
                float vy = acc[mt][nt][half*2+1];
                if (is_m) {
                    vx = fmaxf(vx + bx, 0.f);
                    vy = fmaxf(vy + byv, 0.f);
                    *(__half2*)(g_m + m*CDIM + n) =
                        __halves2half2(__float2half_rn(vx), __float2half_rn(vy));
                } else {
                    *(float2*)(tmp_out + m*CDIM + n) = make_float2(vx, vy);
                }
            }
        }
    }
}

// GEMM3: h' = relu(tmp + msg Wb^T + b_rnn); writes fp32 h and fp16 split
__global__ void __launch_bounds__(256) gemm3_kernel(const float* __restrict__ rnn_b,
                                                    const float* __restrict__ tmp,
                                                    float* __restrict__ h_out)
{
    int m0 = blockIdx.x * 128;
    int d0 = blockIdx.y * 64;

    float acc[2][4][4];
    tile_mma(g_Mh, g_Ml, g_Wbh + d0*CDIM, m0, acc);

    int lane = threadIdx.x & 31, wid = threadIdx.x >> 5;
    int wm = wid & 3, wn = wid >> 2;
    int g = lane >> 2, t = lane & 3;

    #pragma unroll
    for (int mt = 0; mt < 2; ++mt) {
        #pragma unroll
        for (int nt = 0; nt < 4; ++nt) {
            int n = d0 + wn*32 + nt*8 + t*2;
            float bx = rnn_b[n], byv = rnn_b[n+1];
            #pragma unroll
            for (int half = 0; half < 2; ++half) {
                int m = m0 + wm*32 + mt*16 + g + half*8;
                if (m >= M_TOTAL) continue;
                float2 tv = *(const float2*)(tmp + m*CDIM + n);
                float vx = fmaxf(acc[mt][nt][half*2+0] + tv.x + bx, 0.f);
                float vy = fmaxf(acc[mt][nt][half*2+1] + tv.y + byv, 0.f);
                *(float2*)(h_out + m*CDIM + n) = make_float2(vx, vy);
                __half hx, lx, hy, ly;
                hsplit(vx, hx, lx); hsplit(vy, hy, ly);
                *(__half2*)(g_Ah + m*CDIM + n) = __halves2half2(hx, hy);
                *(__half2*)(g_Al + m*CDIM + n) = __halves2half2(lx, ly);
            }
        }
    }
}

// ---------------- weight conversion (once per call) ------------------------
__global__ void __launch_bounds__(256) wconv_kernel(const float* __restrict__ mlp_w,
                                                    const float* __restrict__ rnn_w)
{
    int e = blockIdx.x * 256 + threadIdx.x;   // < 256*768
    if (e < CDIM*CDIM) {
        g_Wmh[e] = __float2half_rn(mlp_w[e]);
    } else {
        int u = e - CDIM*CDIM;                 // < 256*512
        int r = u >> 9, c = u & 511;
        __half h = __float2half_rn(rnn_w[u]);
        if (c < CDIM) g_Wah[r*CDIM + c] = h;
        else          g_Wbh[r*CDIM + c - CDIM] = h;
    }
}

// zero padded rows of fp16 operand arrays
__global__ void __launch_bounds__(256) pad_kernel()
{
    int e = blockIdx.x * 256 + threadIdx.x;   // < 96*256
    int o = (M_TOTAL + (e >> 8))*CDIM + (e & 255);
    g_Ah[o] = __float2half(0.f); g_Al[o] = __float2half(0.f);
    g_Mh[o] = __float2half(0.f); g_Ml[o] = __float2half(0.f);
}

// ---------------- init: out[:, :256] = cnn; Ah/Al = fp16 split of NHWC h0 --
__global__ void __launch_bounds__(256) init_kernel(const float* __restrict__ cnn,
                                                   float* __restrict__ out)
{
    int e = blockIdx.x * 256 + threadIdx.x;
    int s = e % HWP;
    int c = (e / HWP) & (CDIM-1);
    int n = e / (HWP*CDIM);
    float v = cnn[e];
    out[(n*(2*CDIM) + c)*HWP + s] = v;
    __half h, l; hsplit(v, h, l);
    int o = (n*HWP + s)*CDIM + c;
    g_Ah[o] = h; g_Al[o] = l;
}

__global__ void __launch_bounds__(256) final_kernel(const float* __restrict__ h,
                                                    float* __restrict__ out)
{
    int e = blockIdx.x * 256 + threadIdx.x;
    int s = e % HWP;
    int c = (e / HWP) & (CDIM-1);
    int n = e / (HWP*CDIM);
    out[(n*(2*CDIM) + CDIM + c)*HWP + s] = h[(n*HWP + s)*CDIM + c];
}

// ---------------- KNN v5: candidate-major phase-A, 8 rows/block ------------
#define KNN_BR 8
#define CAP 256
// dynamic smem layout (bytes)
#define KPX    0                        // float[3600]  14400
#define KPY    14400
#define KPZ    28800                    // end 43200
#define KHIST  43200                    // int[8][256]   8192
#define KCV    51392                    // u32[8][CAP]   8192
#define KCI    59584                    // int[8][CAP]   8192
#define KTIE   67776                    // int[8][32]    1024
#define KOCNT  68800                    // int[8]
#define KCCNT  68832                    // int[8]
#define KECRIT 68864                    // int[8]
#define KFLAG  68896                    // int[8]
#define KWS    68928                    // int[2][8]
#define KSC    68992                    // int[4]
#define KNN_SMEM 69120

__global__ void __launch_bounds__(256) knn_kernel(const float* __restrict__ pts,
                                                  int* __restrict__ idx_out)
{
    extern __shared__ char sm[];
    float* px = (float*)(sm + KPX);
    float* py = (float*)(sm + KPY);
    float* pz = (float*)(sm + KPZ);
    int* hist = (int*)(sm + KHIST);
    unsigned* cv = (unsigned*)(sm + KCV);
    int* ci = (int*)(sm + KCI);
    int* tiebuf = (int*)(sm + KTIE);
    int* ocnt  = (int*)(sm + KOCNT);
    int* ccnt  = (int*)(sm + KCCNT);
    int* ecrit = (int*)(sm + KECRIT);
    int* flag  = (int*)(sm + KFLAG);
    int* ws    = (int*)(sm + KWS);
    int* sc    = (int*)(sm + KSC);

    int gb = blockIdx.x;
    int n  = gb / (HWP/KNN_BR);
    int g  = gb % (HWP/KNN_BR);
    int tid = threadIdx.x;
    int lane = tid & 31, wid = tid >> 5;
    const unsigned ltm = (1u << lane) - 1u;

    const float* p = pts + n*3*HWP;
    for (int i = tid; i < HWP; i += 256) {
        px[i] = p[i];
        py[i] = p[i + HWP];
        pz[i] = p[i + 2*HWP];
    }
    #pragma unroll
    for (int i = 0; i < KNN_BR; ++i) hist[i*256 + tid] = 0;
    if (tid < KNN_BR) { ocnt[tid] = 0; ccnt[tid] = 0; flag[tid] = 0; }
    __syncthreads();                                   // B0

    // query coords in registers
    float qx[KNN_BR], qy[KNN_BR], qz[KNN_BR], qs[KNN_BR];
    #pragma unroll
    for (int r = 0; r < KNN_BR; ++r) {
        int row = g*KNN_BR + r;
        qx[r] = px[row]; qy[r] = py[row]; qz[r] = pz[row];
        qs[r] = fmaf(qz[r], qz[r], fmaf(qy[r], qy[r], qx[r]*qx[r]));
    }

    // ---- pass 1: candidate-major, build 8 histograms ----------------------
    #pragma unroll 1
    for (int t = 0; t < 15; ++t) {
        int j = t*256 + tid;
        bool v = j < HWP;
        float x = 0.f, y = 0.f, z = 0.f, sj = 0.f;
        if (v) { x = px[j]; y = py[j]; z = pz[j]; sj = fmaf(z, z, fmaf(y, y, x*x)); }
        #pragma unroll
        for (int r = 0; r < KNN_BR; ++r) {
            unsigned bits = 0x7f800000u;
            if (v) {
                float dot = fmaf(qz[r], z, fmaf(qy[r], y, qx[r]*x));
                bits = __float_as_uint(fmaxf(qs[r] + sj - 2.0f*dot, 0.0f));
            }
            unsigned e = bits >> 23;
            unsigned mask = __match_any_sync(0xffffffffu, e);
            if (lane == (unsigned)(__ffs(mask) - 1)) atomicAdd(&hist[r*256 + e], __popc(mask));
        }
    }
    __syncthreads();                                   // B1

    // ---- scan: warp w scans hist[w] ----------------------------------------
    if (wid < KNN_BR) {
        int* h8 = hist + wid*256;
        int basebin = lane*8, loc[8], ssum = 0;
        #pragma unroll
        for (int j2 = 0; j2 < 8; ++j2) { loc[j2] = h8[basebin + j2]; ssum += loc[j2]; }
        int pre = ssum;
        #pragma unroll
        for (int o = 1; o < 32; o <<= 1) {
            int v2 = __shfl_up_sync(0xffffffffu, pre, o);
            if (lane >= (unsigned)o) pre += v2;
        }
        int excl = pre - ssum;
        int ec = 0;
        if (excl < KNN && excl + ssum >= KNN) {        // unique crossing lane
            int cum = excl;
            #pragma unroll
            for (int j2 = 0; j2 < 8; ++j2) {
                if (cum + loc[j2] >= KNN) { ec = basebin + j2; break; }
                cum += loc[j2];
            }
        }
        ec = __reduce_max_sync(0xffffffffu, ec);
        if (lane == 0) ecrit[wid] = ec;
    }
    __syncthreads();                                   // B2

    int Ereg[KNN_BR];
    #pragma unroll
    for (int r = 0; r < KNN_BR; ++r) Ereg[r] = ecrit[r];

    // ---- pass 2: recompute, ballot-aggregated compaction -------------------
    #pragma unroll 1
    for (int t = 0; t < 15; ++t) {
        int j = t*256 + tid;
        bool v = j < HWP;
        float x = 0.f, y = 0.f, z = 0.f, sj = 0.f;
        if (v) { x = px[j]; y = py[j]; z = pz[j]; sj = fmaf(z, z, fmaf(y, y, x*x)); }
        #pragma unroll
        for (int r = 0; r < KNN_BR; ++r) {
            unsigned bits = 0x7f800000u;
            if (v) {
                float dot = fmaf(qz[r], z, fmaf(qy[r], y, qx[r]*x));
                bits = __float_as_uint(fmaxf(qs[r] + sj - 2.0f*dot, 0.0f));
            }
            int e = (int)(bits >> 23);
            bool win = v && e < Ereg[r];
            unsigned mw = __ballot_sync(0xffffffffu, win);
            if (mw) {
                int src = __ffs(mw) - 1;
                int base = 0;
                if (lane == (unsigned)src) base = atomicAdd(&ocnt[r], __popc(mw));
                base = __shfl_sync(0xffffffffu, base, src);
                if (win) idx_out[(n*HWP + g*KNN_BR + r)*KNN + base + __popc(mw & ltm)] = j;
            }
            bool cand = v && e == Ereg[r];
            unsigned mc = __ballot_sync(0xffffffffu, cand);
            if (mc) {
                int src = __ffs(mc) - 1;
                int base = 0;
                if (lane == (unsigned)src) base = atomicAdd(&ccnt[r], __popc(mc));
                base = __shfl_sync(0xffffffffu, base, src);
                if (cand) {
                    int pos = base + __popc(mc & ltm);
                    if (pos < CAP) { cv[r*CAP + pos] = bits; ci[r*CAP + pos] = j; }
                }
            }
        }
    }
    __syncthreads();                                   // B3

    // ---- phase B: one row per warp ------------------------------------------
    if (wid < KNN_BR) {
        int r = wid;
        int row = g*KNN_BR + r;
        int* outp = idx_out + (n*HWP + row)*KNN;
        unsigned* wcv = cv + r*CAP;
        int* wci = ci + r*CAP;
        int* wtie = tiebuf + r*32;

        int oc0 = ocnt[r], cc = ccnt[r];
        int Kp = KNN - oc0;

        if (cc > CAP) {
            if (lane == 0) flag[r] = 1;
        } else if (cc == Kp) {
            for (int i = lane; i < cc; i += 32) outp[oc0 + i] = wci[i];
        } else {
            unsigned T = ((unsigned)Ereg[r]) << 23;
            for (int bit = 22; bit >= 0; --bit) {
                unsigned cnd = T | (1u << bit);
                int cnt = 0;
                for (int i = lane; i < cc; i += 32) cnt += (wcv[i] < cnd) ? 1 : 0;
                cnt = __reduce_add_sync(0xffffffffu, cnt);
                if (cnt < Kp) T = cnd;
            }
            int oc = oc0, tc = 0;
            for (int ib = 0; ib < cc; ib += 32) {
                int i = ib + lane;
                bool v = i < cc;
                unsigned bv = v ? wcv[i] : 0xffffffffu;
                unsigned mw = __ballot_sync(0xffffffffu, v && bv < T);
                if (v && bv < T) outp[oc + __popc(mw & ltm)] = wci[i];
                oc += __popc(mw);
                unsigned mt = __ballot_sync(0xffffffffu, v && bv == T);
                if (v && bv == T) {
                    int tp = tc + __popc(mt & ltm);
                    if (tp < 32) wtie[tp] = wci[i];
                }
                tc += __popc(mt);
            }
            __syncwarp();
            if (lane == 0) {
                int slots = KNN - oc;
                int en = tc < 32 ? tc : 32;
                for (int q2 = 0; q2 < slots; ++q2) {   // lowest-index tie fill
                    int best = 0x7fffffff, bi = 0;
                    for (int e2 = 0; e2 < en; ++e2)
                        if (wtie[e2] < best) { best = wtie[e2]; bi = e2; }
                    wtie[bi] = 0x7fffffff;
                    outp[oc + q2] = best;
                }
            }
        }
    }
    __syncthreads();

    // ---- fallback: block-wide 31-bit search (rare) --------------------------
    for (int r = 0; r < KNN_BR; ++r) {
        if (!flag[r]) continue;
        int row = g*KNN_BR + r;
        float fqx = qx[r], fqy = qy[r], fqz = qz[r], fqs = qs[r];

        unsigned d[15];
        #pragma unroll
        for (int t = 0; t < 15; ++t) {
            int j = t*256 + tid;
            if (j < HWP) {
                float x = px[j], y = py[j], z = pz[j];
                float sj  = fmaf(z, z, fmaf(y, y, x*x));
                float dot = fmaf(fqz, z, fmaf(fqy, y, fqx*x));
                d[t] = __float_as_uint(fmaxf(fqs + sj - 2.0f*dot, 0.0f));
            } else {
                d[t] = 0xffffffffu;
            }
        }
        if (tid == 0) { sc[0] = 0; sc[1] = 0; }
        __syncthreads();

        unsigned T = 0;
        for (int bit = 30; bit >= 0; --bit) {
            unsigned cnd = T | (1u << bit);
            int cc2 = 0;
            #pragma unroll
            for (int t = 0; t < 15; ++t) cc2 += (d[t] < cnd) ? 1 : 0;
            cc2 = __reduce_add_sync(0xffffffffu, cc2);
            int par = bit & 1;
            if (lane == 0) ws[par*8 + wid] = cc2;
            __syncthreads();
            int tot = 0;
            #pragma unroll
            for (int w = 0; w < 8; ++w) tot += ws[par*8 + w];
            if (tot < KNN) T = cnd;
        }
        __syncthreads();

        int* outp = idx_out + (n*HWP + row)*KNN;
        int* wtie = tiebuf + r*32;
        #pragma unroll
        for (int t = 0; t < 15; ++t) {
            int j = t*256 + tid;
            unsigned dv = d[t];
            if (dv < T) { int pos = atomicAdd(&sc[0], 1); outp[pos] = j; }
            else if (dv == T && j < HWP) { int pos = atomicAdd(&sc[1], 1); if (pos < 32) wtie[pos] = j; }
        }
        __syncthreads();
        if (tid == 0) {
            int slots = KNN - sc[0];
            int en = sc[1] < 32 ? sc[1] : 32;
            for (int q2 = 0; q2 < slots; ++q2) {
                int best = 0x7fffffff, bi = 0;
                for (int e2 = 0; e2 < en; ++e2)
                    if (wtie[e2] < best) { best = wtie[e2]; bi = e2; }
                wtie[bi] = 0x7fffffff;
                outp[sc[0] + q2] = best;
            }
        }
        __syncthreads();
    }
}

// ------- gather-mean: msg = mean_k m[idx] (m fp16); emits fp16 split -------
__global__ void __launch_bounds__(512) gather_mean_kernel(const int* __restrict__ idx)
{
    __shared__ int sidx[8*KNN];
    int tid = threadIdx.x;
    int s0 = blockIdx.x * 8;
    sidx[tid] = idx[s0*KNN + tid];
    __syncthreads();

    int lp = tid >> 6;
    int c4 = tid & 63;         // 4-half column group (8 bytes)
    int s  = s0 + lp;
    int base = (s / HWP) * HWP;
    const uint2* m2 = reinterpret_cast<const uint2*>(g_m);   // 4 halves per uint2
    const int* ip = sidx + lp*KNN;

    float4 a0 = make_float4(0,0,0,0), a1 = a0, a2 = a0, a3 = a0;
    #pragma unroll
    for (int k = 0; k < KNN; k += 4) {
        int j0 = ip[k], j1 = ip[k+1], j2 = ip[k+2], j3 = ip[k+3];
        uint2 u0 = m2[(size_t)(base + j0)*64 + c4];
        uint2 u1 = m2[(size_t)(base + j1)*64 + c4];
        uint2 u2 = m2[(size_t)(base + j2)*64 + c4];
        uint2 u3 = m2[(size_t)(base + j3)*64 + c4];
        float2 p0 = __half22float2(*(__half2*)&u0.x), q0 = __half22float2(*(__half2*)&u0.y);
        float2 p1 = __half22float2(*(__half2*)&u1.x), q1 = __half22float2(*(__half2*)&u1.y);
        float2 p2 = __half22float2(*(__half2*)&u2.x), q2 = __half22float2(*(__half2*)&u2.y);
        float2 p3 = __half22float2(*(__half2*)&u3.x), q3 = __half22float2(*(__half2*)&u3.y);
        a0.x += p0.x; a0.y += p0.y; a0.z += q0.x; a0.w += q0.y;
        a1.x += p1.x; a1.y += p1.y; a1.z += q1.x; a1.w += q1.y;
        a2.x += p2.x; a2.y += p2.y; a2.z += q2.x; a2.w += q2.y;
        a3.x += p3.x; a3.y += p3.y; a3.z += q3.x; a3.w += q3.y;
    }
    const float inv = 1.0f / 64.0f;
    float4 r;
    r.x = (a0.x + a1.x + a2.x + a3.x) * inv;
    r.y = (a0.y + a1.y + a2.y + a3.y) * inv;
    r.z = (a0.z + a1.z + a2.z + a3.z) * inv;
    r.w = (a0.w + a1.w + a2.w + a3.w) * inv;

    __half hx, lx, hy, ly, hz, lz, hw, lw;
    hsplit(r.x, hx, lx); hsplit(r.y, hy, ly);
    hsplit(r.z, hz, lz); hsplit(r.w, hw, lw);
    int o = s*CDIM + c4*4;
    *(__half2*)(g_Mh + o)     = __halves2half2(hx, hy);
    *(__half2*)(g_Mh + o + 2) = __halves2half2(hz, hw);
    *(__half2*)(g_Ml + o)     = __halves2half2(lx, ly);
    *(__half2*)(g_Ml + o + 2) = __halves2half2(lz, lw);
}

// ---------------- launcher --------------------------------------------------
extern "C" void kernel_launch(void* const* d_in, const int* in_sizes, int n_in,
                              void* d_out, int out_size)
{
    const float* cnn   = (const float*)d_in[0];
    const float* pts   = (const float*)d_in[1];
    const float* mlp_w = (const float*)d_in[2];
    const float* mlp_b = (const float*)d_in[3];
    const float* rnn_w = (const float*)d_in[4];
    const float* rnn_b = (const float*)d_in[5];
    float* out = (float*)d_out;

    float *tmp, *h;
    int* idx;
    cudaGetSymbolAddress((void**)&tmp, g_tmp);
    cudaGetSymbolAddress((void**)&h,   g_h);
    cudaGetSymbolAddress((void**)&idx, g_idx);

    cudaFuncSetAttribute(gemm1_kernel, cudaFuncAttributeMaxDynamicSharedMemorySize, GEMM_SMEM);
    cudaFuncSetAttribute(gemm3_kernel, cudaFuncAttributeMaxDynamicSharedMemorySize, GEMM_SMEM);
    cudaFuncSetAttribute(knn_kernel,   cudaFuncAttributeMaxDynamicSharedMemorySize, KNN_SMEM);

    wconv_kernel<<<768, 256>>>(mlp_w, rnn_w);
    init_kernel<<<(NBATCH*CDIM*HWP)/256, 256>>>(cnn, out);
    pad_kernel<<<96, 256>>>();
    knn_kernel<<<NBATCH*(HWP/KNN_BR), 256, KNN_SMEM>>>(pts, idx);

    for (int it = 0; it < 3; ++it) {
        gemm1_kernel<<<dim3(MPAD/128, 8), 256, GEMM_SMEM>>>(mlp_b, tmp);
        gather_mean_kernel<<<M_TOTAL/8, 512>>>(idx);
        gemm3_kernel<<<dim3(MPAD/128, 4), 256, GEMM_SMEM>>>(rnn_b, tmp, h);
    }
    final_kernel<<<(NBATCH*CDIM*HWP)/256, 256>>>(h, out);
}

// round 11
// speedup vs baseline: 1.9757x; 1.1894x over previous
#include <cuda_runtime.h>
#include <cuda_fp16.h>
#include <cstdint>

#define HWP 3600
#define NBATCH 2
#define CDIM 256
#define KNN 64
#define M_TOTAL (NBATCH*HWP)   // 7200
#define MPAD 7296              // padded rows (multiple of 128)

// ---------------- scratch (device globals; no allocation allowed) ----------
__device__ __half g_m[MPAD*CDIM];       // relu(mlp(h)) fp16
__device__ float g_tmp[MPAD*CDIM];      // h @ Wa^T fp32
__device__ float g_h[MPAD*CDIM];        // fp32 h (for final readout)
__device__ __half g_Ah[MPAD*CDIM], g_Al[MPAD*CDIM];   // h split (fp16 hi/lo)
__device__ __half g_Mh[MPAD*CDIM], g_Ml[MPAD*CDIM];   // msg split
__device__ __half g_Wmh[CDIM*CDIM];                   // mlp_w hi
__device__ __half g_Wah[CDIM*CDIM];                   // rnn_w[:, :C] hi
__device__ __half g_Wbh[CDIM*CDIM];                   // rnn_w[:, C:] hi
__device__ int   g_idx[M_TOTAL*KNN];

__device__ __forceinline__ float4 ld4(const float* p){ return *reinterpret_cast<const float4*>(p); }

// fp16 hi/lo split: v ~= h + l with combined 22-bit mantissa
__device__ __forceinline__ void hsplit(float v, __half& h, __half& l){
    h = __float2half_rn(v);
    l = __float2half_rn(v - __half2float(h));
}

__device__ __forceinline__ uint32_t smem_u32(const void* p) {
    uint32_t a;
    asm("{ .reg .u64 t; cvta.to.shared.u64 t, %1; cvt.u32.u64 %0, t; }" : "=r"(a) : "l"(p));
    return a;
}

// ---------------- mma.sync helpers (suffix-neutral PTX, tensor pipe) -------
__device__ __forceinline__ void ldmat4(uint32_t r[4], uint32_t addr){
    asm volatile("ldmatrix.sync.aligned.m8n8.x4.shared.b16 {%0,%1,%2,%3}, [%4];"
        : "=r"(r[0]), "=r"(r[1]), "=r"(r[2]), "=r"(r[3]) : "r"(addr));
}
__device__ __forceinline__ void mma16816(float c[4], const uint32_t a[4],
                                         uint32_t b0, uint32_t b1){
    asm volatile("mma.sync.aligned.m16n8k16.row.col.f32.f16.f16.f32 "
        "{%0,%1,%2,%3}, {%4,%5,%6,%7}, {%8,%9}, {%0,%1,%2,%3};"
        : "+f"(c[0]), "+f"(c[1]), "+f"(c[2]), "+f"(c[3])
        : "r"(a[0]), "r"(a[1]), "r"(a[2]), "r"(a[3]), "r"(b0), "r"(b1));
}

// smem tile layout: padded stride 72 fp16 (144B = 9 x 16B -> conflict-free)
#define ASTRIDE 72
#define OFF_AH  0
#define OFF_AL  18432
#define OFF_BH  36864
#define GEMM_SMEM 46080

// ---- 128x64x256 tile: fp16 2-term split via mma.sync, fp32 accumulate -----
__device__ void tile_mma(const __half* __restrict__ Ah,
                         const __half* __restrict__ Al,
                         const __half* __restrict__ Bh,
                         int m0, float acc[2][4][4])
{
    extern __shared__ char smem[];
    const uint32_t sb = smem_u32(smem);
    const int tid = threadIdx.x;
    const int lane = tid & 31;
    const int wid = tid >> 5;
    const int wm = wid & 3;        // m32 section
    const int wn = wid >> 2;       // n32 section

    #pragma unroll
    for (int mt = 0; mt < 2; ++mt)
        #pragma unroll
        for (int nt = 0; nt < 4; ++nt)
            #pragma unroll
            for (int q = 0; q < 4; ++q) acc[mt][nt][q] = 0.f;

    const uint32_t aoff = (uint32_t)(((lane & 15)*ASTRIDE + (lane >> 4)*8) * 2);
    const uint32_t boff = (uint32_t)((((lane & 7) + ((lane >> 4) << 3))*ASTRIDE
                                      + ((lane >> 3) & 1)*8) * 2);

    #pragma unroll 1
    for (int kc = 0; kc < 4; ++kc) {
        #pragma unroll
        for (int i = 0; i < 10; ++i) {
            int v = tid + i*256;
            const uint4* src;
            uint32_t dst;
            if (v < 1024) {
                int row = v >> 3, c8 = v & 7;
                src = (const uint4*)(Ah + (m0 + row)*CDIM + kc*64 + c8*8);
                dst = OFF_AH + (uint32_t)(row*ASTRIDE + c8*8)*2;
            } else if (v < 2048) {
                int u = v - 1024, row = u >> 3, c8 = u & 7;
                src = (const uint4*)(Al + (m0 + row)*CDIM + kc*64 + c8*8);
                dst = OFF_AL + (uint32_t)(row*ASTRIDE + c8*8)*2;
            } else {
                int u = v - 2048, row = u >> 3, c8 = u & 7;
                src = (const uint4*)(Bh + row*CDIM + kc*64 + c8*8);
                dst = OFF_BH + (uint32_t)(row*ASTRIDE + c8*8)*2;
            }
            *(uint4*)(smem + dst) = *src;
        }
        __syncthreads();

        #pragma unroll
        for (int ks = 0; ks < 4; ++ks) {
            const uint32_t abase = (uint32_t)((wm*32*ASTRIDE + ks*16) * 2);
            const uint32_t bbase = (uint32_t)((wn*32*ASTRIDE + ks*16) * 2);
            const uint32_t mstep = (uint32_t)(16*ASTRIDE*2);

            uint32_t ah0[4], ah1[4], al0[4], al1[4];
            ldmat4(ah0, sb + OFF_AH + abase + aoff);
            ldmat4(ah1, sb + OFF_AH + abase + mstep + aoff);
            ldmat4(al0, sb + OFF_AL + abase + aoff);
            ldmat4(al1, sb + OFF_AL + abase + mstep + aoff);

            uint32_t bhA[4], bhB[4];
            ldmat4(bhA, sb + OFF_BH + bbase + boff);
            ldmat4(bhB, sb + OFF_BH + bbase + mstep + boff);

            mma16816(acc[0][0], ah0, bhA[0], bhA[1]);
            mma16816(acc[0][1], ah0, bhA[2], bhA[3]);
            mma16816(acc[0][2], ah0, bhB[0], bhB[1]);
            mma16816(acc[0][3], ah0, bhB[2], bhB[3]);
            mma16816(acc[1][0], ah1, bhA[0], bhA[1]);
            mma16816(acc[1][1], ah1, bhA[2], bhA[3]);
            mma16816(acc[1][2], ah1, bhB[0], bhB[1]);
            mma16816(acc[1][3], ah1, bhB[2], bhB[3]);

            mma16816(acc[0][0], al0, bhA[0], bhA[1]);
            mma16816(acc[0][1], al0, bhA[2], bhA[3]);
            mma16816(acc[0][2], al0, bhB[0], bhB[1]);
            mma16816(acc[0][3], al0, bhB[2], bhB[3]);
            mma16816(acc[1][0], al1, bhA[0], bhA[1]);
            mma16816(acc[1][1], al1, bhA[2], bhA[3]);
            mma16816(acc[1][2], al1, bhB[0], bhB[1]);
            mma16816(acc[1][3], al1, bhB[2], bhB[3]);
        }
        __syncthreads();
    }
}

// GEMM1: by 0..3 -> m = relu(h Wmlp^T + b) (fp16);  by 4..7 -> tmp = h Wa^T
__global__ void __launch_bounds__(256) gemm1_kernel(const float* __restrict__ mlp_b,
                                                    float* __restrict__ tmp_out)
{
    int m0 = blockIdx.x * 128;
    int by = blockIdx.y;
    bool is_m = by < 4;
    int d0 = (is_m ? by : by - 4) * 64;
    const __half* Bh = (is_m ? g_Wmh : g_Wah) + d0*CDIM;

    float acc[2][4][4];
    tile_mma(g_Ah, g_Al, Bh, m0, acc);

    int lane = threadIdx.x & 31, wid = threadIdx.x >> 5;
    int wm = wid & 3, wn = wid >> 2;
    int g = lane >> 2, t = lane & 3;

    #pragma unroll
    for (int mt = 0; mt < 2; ++mt) {
        #pragma unroll
        for (int nt = 0; nt < 4; ++nt) {
            int nl = wn*32 + nt*8 + t*2;
            int n = d0 + nl;
            float bx = 0.f, byv = 0.f;
            if (is_m) { bx = mlp_b[n]; byv = mlp_b[n+1]; }
            #pragma unroll
            for (int half = 0; half < 2; ++half) {
                int m = m0 + wm*32 + mt*16 + g + half*8;
                if (m >= M_TOTAL) continue;
                float vx = acc[mt][nt][half*2+0];
                float vy = acc[mt][nt][half*2+1];
                if (is_m) {
                    vx = fmaxf(vx + bx, 0.f);
                    vy = fmaxf(vy + byv, 0.f);
                    *(__half2*)(g_m + m*CDIM + n) =
                        __halves2half2(__float2half_rn(vx), __float2half_rn(vy));
                } else {
                    *(float2*)(tmp_out + m*CDIM + n) = make_float2(vx, vy);
                }
            }
        }
    }
}

// GEMM3: h' = relu(tmp + msg Wb^T + b_rnn); writes fp32 h and fp16 split
__global__ void __launch_bounds__(256) gemm3_kernel(const float* __restrict__ rnn_b,
                                                    const float* __restrict__ tmp,
                                                    float* __restrict__ h_out)
{
    int m0 = blockIdx.x * 128;
    int d0 = blockIdx.y * 64;

    float acc[2][4][4];
    tile_mma(g_Mh, g_Ml, g_Wbh + d0*CDIM, m0, acc);

    int lane = threadIdx.x & 31, wid = threadIdx.x >> 5;
    int wm = wid & 3, wn = wid >> 2;
    int g = lane >> 2, t = lane & 3;

    #pragma unroll
    for (int mt = 0; mt < 2; ++mt) {
        #pragma unroll
        for (int nt = 0; nt < 4; ++nt) {
            int n = d0 + wn*32 + nt*8 + t*2;
            float bx = rnn_b[n], byv = rnn_b[n+1];
            #pragma unroll
            for (int half = 0; half < 2; ++half) {
                int m = m0 + wm*32 + mt*16 + g + half*8;
                if (m >= M_TOTAL) continue;
                float2 tv = *(const float2*)(tmp + m*CDIM + n);
                float vx = fmaxf(acc[mt][nt][half*2+0] + tv.x + bx, 0.f);
                float vy = fmaxf(acc[mt][nt][half*2+1] + tv.y + byv, 0.f);
                *(float2*)(h_out + m*CDIM + n) = make_float2(vx, vy);
                __half hx, lx, hy, ly;
                hsplit(vx, hx, lx); hsplit(vy, hy, ly);
                *(__half2*)(g_Ah + m*CDIM + n) = __halves2half2(hx, hy);
                *(__half2*)(g_Al + m*CDIM + n) = __halves2half2(lx, ly);
            }
        }
    }
}

// ---------------- weight conversion (once per call) ------------------------
__global__ void __launch_bounds__(256) wconv_kernel(const float* __restrict__ mlp_w,
                                                    const float* __restrict__ rnn_w)
{
    int e = blockIdx.x * 256 + threadIdx.x;   // < 256*768
    if (e < CDIM*CDIM) {
        g_Wmh[e] = __float2half_rn(mlp_w[e]);
    } else {
        int u = e - CDIM*CDIM;                 // < 256*512
        int r = u >> 9, c = u & 511;
        __half h = __float2half_rn(rnn_w[u]);
        if (c < CDIM) g_Wah[r*CDIM + c] = h;
        else          g_Wbh[r*CDIM + c - CDIM] = h;
    }
}

// zero padded rows of fp16 operand arrays
__global__ void __launch_bounds__(256) pad_kernel()
{
    int e = blockIdx.x * 256 + threadIdx.x;   // < 96*256
    int o = (M_TOTAL + (e >> 8))*CDIM + (e & 255);
    g_Ah[o] = __float2half(0.f); g_Al[o] = __float2half(0.f);
    g_Mh[o] = __float2half(0.f); g_Ml[o] = __float2half(0.f);
}

// ---------------- out[:, :256] = cnn (pure coalesced float4 copy) ----------
__global__ void __launch_bounds__(256) copy_out_kernel(const float* __restrict__ cnn,
                                                       float* __restrict__ out)
{
    int e = blockIdx.x * 256 + threadIdx.x;          // float4 units, 460800 total
    int n = e / 230400;                              // 256*3600/4 per batch
    int r = e % 230400;
    ((float4*)out)[(size_t)n*460800 + r] = ((const float4*)cnn)[e];
}

// ------- cnn (n,c,s) -> Ah/Al (n,s,c) fp16 split, smem tile transpose ------
__global__ void __launch_bounds__(256) tin_kernel(const float* __restrict__ cnn)
{
    __shared__ float tile[32][65];                   // [s_l][c_l], pad 65
    int s0 = blockIdx.x * 32;
    int c0 = blockIdx.y * 64;
    int bn = blockIdx.z;
    const float* src = cnn + ((size_t)bn*CDIM + c0)*HWP + s0;

    #pragma unroll
    for (int i = 0; i < 8; ++i) {
        int flat = threadIdx.x + i*256;              // 0..2047
        int s_l = flat & 31, c_l = flat >> 5;
        float v = 0.f;
        if (s0 + s_l < HWP) v = src[(size_t)c_l*HWP + s_l];
        tile[s_l][c_l] = v;
    }
    __syncthreads();

    #pragma unroll
    for (int i = 0; i < 4; ++i) {
        int flat = threadIdx.x + i*256;              // 0..1023 (half2 units)
        int cp = flat & 31;                          // c = cp*2
        int s_l = flat >> 5;
        int s = s0 + s_l;
        if (s >= HWP) continue;
        float v0 = tile[s_l][cp*2], v1 = tile[s_l][cp*2+1];
        __half h0, l0, h1, l1;
        hsplit(v0, h0, l0); hsplit(v1, h1, l1);
        int o = (bn*HWP + s)*CDIM + c0 + cp*2;
        *(__half2*)(g_Ah + o) = __halves2half2(h0, h1);
        *(__half2*)(g_Al + o) = __halves2half2(l0, l1);
    }
}

// ------- h (n,s,c) -> out[:, 256:512] (n,c,s), smem tile transpose ---------
__global__ void __launch_bounds__(256) tout_kernel(const float* __restrict__ h,
                                                   float* __restrict__ out)
{
    __shared__ float tile[64][33];                   // [c_l][s_l], pad 33
    int s0 = blockIdx.x * 32;
    int c0 = blockIdx.y * 64;
    int bn = blockIdx.z;

    #pragma unroll
    for (int i = 0; i < 8; ++i) {
        int flat = threadIdx.x + i*256;
        int c_l = flat & 63, s_l = flat >> 6;        // s_l 0..31
        int s = s0 + s_l;
        float v = 0.f;
        if (s < HWP) v = h[((size_t)bn*HWP + s)*CDIM + c0 + c_l];
        tile[c_l][s_l] = v;
    }
    __syncthreads();

    #pragma unroll
    for (int i = 0; i < 8; ++i) {
        int flat = threadIdx.x + i*256;
        int s_l = flat & 31, c_l = flat >> 5;        // c_l 0..63
        int s = s0 + s_l;
        if (s < HWP)
            out[((size_t)bn*(2*CDIM) + CDIM + c0 + c_l)*HWP + s] = tile[c_l][s_l];
    }
}

// ---------------- KNN v5: candidate-major phase-A, 8 rows/block ------------
#define KNN_BR 8
#define CAP 256
// dynamic smem layout (bytes)
#define KPX    0                        // float[3600]  14400
#define KPY    14400
#define KPZ    28800                    // end 43200
#define KHIST  43200                    // int[8][256]   8192
#define KCV    51392                    // u32[8][CAP]   8192
#define KCI    59584                    // int[8][CAP]   8192
#define KTIE   67776                    // int[8][32]    1024
#define KOCNT  68800                    // int[8]
#define KCCNT  68832                    // int[8]
#define KECRIT 68864                    // int[8]
#define KFLAG  68896                    // int[8]
#define KWS    68928                    // int[2][8]
#define KSC    68992                    // int[4]
#define KNN_SMEM 69120

__global__ void __launch_bounds__(256) knn_kernel(const float* __restrict__ pts,
                                                  int* __restrict__ idx_out)
{
    extern __shared__ char sm[];
    float* px = (float*)(sm + KPX);
    float* py = (float*)(sm + KPY);
    float* pz = (float*)(sm + KPZ);
    int* hist = (int*)(sm + KHIST);
    unsigned* cv = (unsigned*)(sm + KCV);
    int* ci = (int*)(sm + KCI);
    int* tiebuf = (int*)(sm + KTIE);
    int* ocnt  = (int*)(sm + KOCNT);
    int* ccnt  = (int*)(sm + KCCNT);
    int* ecrit = (int*)(sm + KECRIT);
    int* flag  = (int*)(sm + KFLAG);
    int* ws    = (int*)(sm + KWS);
    int* sc    = (int*)(sm + KSC);

    int gb = blockIdx.x;
    int n  = gb / (HWP/KNN_BR);
    int g  = gb % (HWP/KNN_BR);
    int tid = threadIdx.x;
    int lane = tid & 31, wid = tid >> 5;
    const unsigned ltm = (1u << lane) - 1u;

    const float* p = pts + n*3*HWP;
    for (int i = tid; i < HWP; i += 256) {
        px[i] = p[i];
        py[i] = p[i + HWP];
        pz[i] = p[i + 2*HWP];
    }
    #pragma unroll
    for (int i = 0; i < KNN_BR; ++i) hist[i*256 + tid] = 0;
    if (tid < KNN_BR) { ocnt[tid] = 0; ccnt[tid] = 0; flag[tid] = 0; }
    __syncthreads();                                   // B0

    // query coords in registers
    float qx[KNN_BR], qy[KNN_BR], qz[KNN_BR], qs[KNN_BR];
    #pragma unroll
    for (int r = 0; r < KNN_BR; ++r) {
        int row = g*KNN_BR + r;
        qx[r] = px[row]; qy[r] = py[row]; qz[r] = pz[row];
        qs[r] = fmaf(qz[r], qz[r], fmaf(qy[r], qy[r], qx[r]*qx[r]));
    }

    // ---- pass 1: candidate-major, build 8 histograms ----------------------
    #pragma unroll 1
    for (int t = 0; t < 15; ++t) {
        int j = t*256 + tid;
        bool v = j < HWP;
        float x = 0.f, y = 0.f, z = 0.f, sj = 0.f;
        if (v) { x = px[j]; y = py[j]; z = pz[j]; sj = fmaf(z, z, fmaf(y, y, x*x)); }
        #pragma unroll
        for (int r = 0; r < KNN_BR; ++r) {
            unsigned bits = 0x7f800000u;
            if (v) {
                float dot = fmaf(qz[r], z, fmaf(qy[r], y, qx[r]*x));
                bits = __float_as_uint(fmaxf(qs[r] + sj - 2.0f*dot, 0.0f));
            }
            unsigned e = bits >> 23;
            unsigned mask = __match_any_sync(0xffffffffu, e);
            if (lane == (unsigned)(__ffs(mask) - 1)) atomicAdd(&hist[r*256 + e], __popc(mask));
        }
    }
    __syncthreads();                                   // B1

    // ---- scan: warp w scans hist[w] ----------------------------------------
    if (wid < KNN_BR) {
        int* h8 = hist + wid*256;
        int basebin = lane*8, loc[8], ssum = 0;
        #pragma unroll
        for (int j2 = 0; j2 < 8; ++j2) { loc[j2] = h8[basebin + j2]; ssum += loc[j2]; }
        int pre = ssum;
        #pragma unroll
        for (int o = 1; o < 32; o <<= 1) {
            int v2 = __shfl_up_sync(0xffffffffu, pre, o);
            if (lane >= (unsigned)o) pre += v2;
        }
        int excl = pre - ssum;
        int ec = 0;
        if (excl < KNN && excl + ssum >= KNN) {        // unique crossing lane
            int cum = excl;
            #pragma unroll
            for (int j2 = 0; j2 < 8; ++j2) {
                if (cum + loc[j2] >= KNN) { ec = basebin + j2; break; }
                cum += loc[j2];
            }
        }
        ec = __reduce_max_sync(0xffffffffu, ec);
        if (lane == 0) ecrit[wid] = ec;
    }
    __syncthreads();                                   // B2

    int Ereg[KNN_BR];
    #pragma unroll
    for (int r = 0; r < KNN_BR; ++r) Ereg[r] = ecrit[r];

    // ---- pass 2: recompute, ballot-aggregated compaction -------------------
    #pragma unroll 1
    for (int t = 0; t < 15; ++t) {
        int j = t*256 + tid;
        bool v = j < HWP;
        float x = 0.f, y = 0.f, z = 0.f, sj = 0.f;
        if (v) { x = px[j]; y = py[j]; z = pz[j]; sj = fmaf(z, z, fmaf(y, y, x*x)); }
        #pragma unroll
        for (int r = 0; r < KNN_BR; ++r) {
            unsigned bits = 0x7f800000u;
            if (v) {
                float dot = fmaf(qz[r], z, fmaf(qy[r], y, qx[r]*x));
                bits = __float_as_uint(fmaxf(qs[r] + sj - 2.0f*dot, 0.0f));
            }
            int e = (int)(bits >> 23);
            bool win = v && e < Ereg[r];
            unsigned mw = __ballot_sync(0xffffffffu, win);
            if (mw) {
                int src = __ffs(mw) - 1;
                int base = 0;
                if (lane == (unsigned)src) base = atomicAdd(&ocnt[r], __popc(mw));
                base = __shfl_sync(0xffffffffu, base, src);
                if (win) idx_out[(n*HWP + g*KNN_BR + r)*KNN + base + __popc(mw & ltm)] = j;
            }
            bool cand = v && e == Ereg[r];
            unsigned mc = __ballot_sync(0xffffffffu, cand);
            if (mc) {
                int src = __ffs(mc) - 1;
                int base = 0;
                if (lane == (unsigned)src) base = atomicAdd(&ccnt[r], __popc(mc));
                base = __shfl_sync(0xffffffffu, base, src);
                if (cand) {
                    int pos = base + __popc(mc & ltm);
                    if (pos < CAP) { cv[r*CAP + pos] = bits; ci[r*CAP + pos] = j; }
                }
            }
        }
    }
    __syncthreads();                                   // B3

    // ---- phase B: one row per warp ------------------------------------------
    if (wid < KNN_BR) {
        int r = wid;
        int row = g*KNN_BR + r;
        int* outp = idx_out + (n*HWP + row)*KNN;
        unsigned* wcv = cv + r*CAP;
        int* wci = ci + r*CAP;
        int* wtie = tiebuf + r*32;

        int oc0 = ocnt[r], cc = ccnt[r];
        int Kp = KNN - oc0;

        if (cc > CAP) {
            if (lane == 0) flag[r] = 1;
        } else if (cc == Kp) {
            for (int i = lane; i < cc; i += 32) outp[oc0 + i] = wci[i];
        } else {
            unsigned T = ((unsigned)Ereg[r]) << 23;
            for (int bit = 22; bit >= 0; --bit) {
                unsigned cnd = T | (1u << bit);
                int cnt = 0;
                for (int i = lane; i < cc; i += 32) cnt += (wcv[i] < cnd) ? 1 : 0;
                cnt = __reduce_add_sync(0xffffffffu, cnt);
                if (cnt < Kp) T = cnd;
            }
            int oc = oc0, tc = 0;
            for (int ib = 0; ib < cc; ib += 32) {
                int i = ib + lane;
                bool v = i < cc;
                unsigned bv = v ? wcv[i] : 0xffffffffu;
                unsigned mw = __ballot_sync(0xffffffffu, v && bv < T);
                if (v && bv < T) outp[oc + __popc(mw & ltm)] = wci[i];
                oc += __popc(mw);
                unsigned mt = __ballot_sync(0xffffffffu, v && bv == T);
                if (v && bv == T) {
                    int tp = tc + __popc(mt & ltm);
                    if (tp < 32) wtie[tp] = wci[i];
                }
                tc += __popc(mt);
            }
            __syncwarp();
            if (lane == 0) {
                int slots = KNN - oc;
                int en = tc < 32 ? tc : 32;
                for (int q2 = 0; q2 < slots; ++q2) {   // lowest-index tie fill
                    int best = 0x7fffffff, bi = 0;
                    for (int e2 = 0; e2 < en; ++e2)
                        if (wtie[e2] < best) { best = wtie[e2]; bi = e2; }
                    wtie[bi] = 0x7fffffff;
                    outp[oc + q2] = best;
                }
            }
        }
    }
    __syncthreads();

    // ---- fallback: block-wide 31-bit search (rare) --------------------------
    for (int r = 0; r < KNN_BR; ++r) {
        if (!flag[r]) continue;
        int row = g*KNN_BR + r;
        float fqx = qx[r], fqy = qy[r], fqz = qz[r], fqs = qs[r];

        unsigned d[15];
        #pragma unroll
        for (int t = 0; t < 15; ++t) {
            int j = t*256 + tid;
            if (j < HWP) {
                float x = px[j], y = py[j], z = pz[j];
                float sj  = fmaf(z, z, fmaf(y, y, x*x));
                float dot = fmaf(fqz, z, fmaf(fqy, y, fqx*x));
                d[t] = __float_as_uint(fmaxf(fqs + sj - 2.0f*dot, 0.0f));
            } else {
                d[t] = 0xffffffffu;
            }
        }
        if (tid == 0) { sc[0] = 0; sc[1] = 0; }
        __syncthreads();

        unsigned T = 0;
        for (int bit = 30; bit >= 0; --bit) {
            unsigned cnd = T | (1u << bit);
            int cc2 = 0;
            #pragma unroll
            for (int t = 0; t < 15; ++t) cc2 += (d[t] < cnd) ? 1 : 0;
            cc2 = __reduce_add_sync(0xffffffffu, cc2);
            int par = bit & 1;
            if (lane == 0) ws[par*8 + wid] = cc2;
            __syncthreads();
            int tot = 0;
            #pragma unroll
            for (int w = 0; w < 8; ++w) tot += ws[par*8 + w];
            if (tot < KNN) T = cnd;
        }
        __syncthreads();

        int* outp = idx_out + (n*HWP + row)*KNN;
        int* wtie = tiebuf + r*32;
        #pragma unroll
        for (int t = 0; t < 15; ++t) {
            int j = t*256 + tid;
            unsigned dv = d[t];
            if (dv < T) { int pos = atomicAdd(&sc[0], 1); outp[pos] = j; }
            else if (dv == T && j < HWP) { int pos = atomicAdd(&sc[1], 1); if (pos < 32) wtie[pos] = j; }
        }
        __syncthreads();
        if (tid == 0) {
            int slots = KNN - sc[0];
            int en = sc[1] < 32 ? sc[1] : 32;
            for (int q2 = 0; q2 < slots; ++q2) {
                int best = 0x7fffffff, bi = 0;
                for (int e2 = 0; e2 < en; ++e2)
                    if (wtie[e2] < best) { best = wtie[e2]; bi = e2; }
                wtie[bi] = 0x7fffffff;
                outp[sc[0] + q2] = best;
            }
        }
        __syncthreads();
    }
}

// ------- gather-mean v3: 16 pts/block, 32 thr/pt, 16B loads ----------------
__global__ void __launch_bounds__(512) gather_mean_kernel(const int* __restrict__ idx)
{
    __shared__ int sidx[16*KNN];
    int tid = threadIdx.x;
    int s0 = blockIdx.x * 16;
    sidx[tid]       = idx[s0*KNN + tid];
    sidx[tid + 512] = idx[s0*KNN + tid + 512];
    __syncthreads();

    int lp = tid >> 5;          // 0..15 local point
    int lane = tid & 31;        // 16B chunk (8 halves) within row
    int s = s0 + lp;
    int base = (s / HWP) * HWP;
    const uint4* m4 = reinterpret_cast<const uint4*>(g_m);   // 32 uint4 per row
    const int* ip = sidx + lp*KNN;

    float acc[8];
    #pragma unroll
    for (int i = 0; i < 8; ++i) acc[i] = 0.f;

    #pragma unroll
    for (int k = 0; k < KNN; k += 4) {
        int j0 = ip[k], j1 = ip[k+1], j2 = ip[k+2], j3 = ip[k+3];
        uint4 u0 = m4[(size_t)(base + j0)*32 + lane];
        uint4 u1 = m4[(size_t)(base + j1)*32 + lane];
        uint4 u2 = m4[(size_t)(base + j2)*32 + lane];
        uint4 u3 = m4[(size_t)(base + j3)*32 + lane];
        #pragma unroll
        for (int q = 0; q < 4; ++q) {
            uint4 u = (q == 0) ? u0 : (q == 1) ? u1 : (q == 2) ? u2 : u3;
            float2 f0 = __half22float2(*(__half2*)&u.x);
            float2 f1 = __half22float2(*(__half2*)&u.y);
            float2 f2 = __half22float2(*(__half2*)&u.z);
            float2 f3 = __half22float2(*(__half2*)&u.w);
            acc[0] += f0.x; acc[1] += f0.y; acc[2] += f1.x; acc[3] += f1.y;
            acc[4] += f2.x; acc[5] += f2.y; acc[6] += f3.x; acc[7] += f3.y;
        }
    }
    const float inv = 1.0f / 64.0f;
    __half hh[8], ll[8];
    #pragma unroll
    for (int i = 0; i < 8; ++i) hsplit(acc[i]*inv, hh[i], ll[i]);

    int o = s*CDIM + lane*8;
    __half2 mh0 = __halves2half2(hh[0], hh[1]), mh1 = __halves2half2(hh[2], hh[3]);
    __half2 mh2 = __halves2half2(hh[4], hh[5]), mh3 = __halves2half2(hh[6], hh[7]);
    __half2 ml0 = __halves2half2(ll[0], ll[1]), ml1 = __halves2half2(ll[2], ll[3]);
    __half2 ml2 = __halves2half2(ll[4], ll[5]), ml3 = __halves2half2(ll[6], ll[7]);
    uint4 sh, sl;
    sh.x = *(uint32_t*)&mh0; sh.y = *(uint32_t*)&mh1;
    sh.z = *(uint32_t*)&mh2; sh.w = *(uint32_t*)&mh3;
    sl.x = *(uint32_t*)&ml0; sl.y = *(uint32_t*)&ml1;
    sl.z = *(uint32_t*)&ml2; sl.w = *(uint32_t*)&ml3;
    *(uint4*)(g_Mh + o) = sh;
    *(uint4*)(g_Ml + o) = sl;
}

// ---------------- launcher --------------------------------------------------
extern "C" void kernel_launch(void* const* d_in, const int* in_sizes, int n_in,
                              void* d_out, int out_size)
{
    const float* cnn   = (const float*)d_in[0];
    const float* pts   = (const float*)d_in[1];
    const float* mlp_w = (const float*)d_in[2];
    const float* mlp_b = (const float*)d_in[3];
    const float* rnn_w = (const float*)d_in[4];
    const float* rnn_b = (const float*)d_in[5];
    float* out = (float*)d_out;

    float *tmp, *h;
    int* idx;
    cudaGetSymbolAddress((void**)&tmp, g_tmp);
    cudaGetSymbolAddress((void**)&h,   g_h);
    cudaGetSymbolAddress((void**)&idx, g_idx);

    cudaFuncSetAttribute(gemm1_kernel, cudaFuncAttributeMaxDynamicSharedMemorySize, GEMM_SMEM);
    cudaFuncSetAttribute(gemm3_kernel, cudaFuncAttributeMaxDynamicSharedMemorySize, GEMM_SMEM);
    cudaFuncSetAttribute(knn_kernel,   cudaFuncAttributeMaxDynamicSharedMemorySize, KNN_SMEM);

    wconv_kernel<<<768, 256>>>(mlp_w, rnn_w);
    copy_out_kernel<<<1800, 256>>>(cnn, out);
    tin_kernel<<<dim3(113, 4, 2), 256>>>(cnn);
    pad_kernel<<<96, 256>>>();
    knn_kernel<<<NBATCH*(HWP/KNN_BR), 256, KNN_SMEM>>>(pts, idx);

    for (int it = 0; it < 3; ++it) {
        gemm1_kernel<<<dim3(MPAD/128, 8), 256, GEMM_SMEM>>>(mlp_b, tmp);
        gather_mean_kernel<<<M_TOTAL/16, 512>>>(idx);
        gemm3_kernel<<<dim3(MPAD/128, 4), 256, GEMM_SMEM>>>(rnn_b, tmp, h);
    }
    tout_kernel<<<dim3(113, 4, 2), 256>>>(h, out);
}

// round 12
// speedup vs baseline: 1.9928x; 1.0087x over previous
#include <cuda_runtime.h>
#include <cuda_fp16.h>
#include <cstdint>

#define HWP 3600
#define NBATCH 2
#define CDIM 256
#define KNN 64
#define M_TOTAL (NBATCH*HWP)   // 7200
#define MPAD 7296              // padded rows (multiple of 128)

// ---------------- scratch (device globals; no allocation allowed) ----------
__device__ __half g_m[MPAD*CDIM];       // relu(mlp(h)) fp16
__device__ float g_tmp[MPAD*CDIM];      // h @ Wa^T fp32
__device__ float g_h[MPAD*CDIM];        // fp32 h (for final readout)
__device__ __half g_Ah[MPAD*CDIM], g_Al[MPAD*CDIM];   // h split (fp16 hi/lo)
__device__ __half g_Mh[MPAD*CDIM], g_Ml[MPAD*CDIM];   // msg split
__device__ __half g_Wmh[CDIM*CDIM];                   // mlp_w hi
__device__ __half g_Wah[CDIM*CDIM];                   // rnn_w[:, :C] hi
__device__ __half g_Wbh[CDIM*CDIM];                   // rnn_w[:, C:] hi
__device__ int   g_idx[M_TOTAL*KNN];

// fp16 hi/lo split: v ~= h + l with combined 22-bit mantissa
__device__ __forceinline__ void hsplit(float v, __half& h, __half& l){
    h = __float2half_rn(v);
    l = __float2half_rn(v - __half2float(h));
}

__device__ __forceinline__ uint32_t smem_u32(const void* p) {
    uint32_t a;
    asm("{ .reg .u64 t; cvta.to.shared.u64 t, %1; cvt.u32.u64 %0, t; }" : "=r"(a) : "l"(p));
    return a;
}

// ---------------- mma.sync helpers (suffix-neutral PTX, tensor pipe) -------
__device__ __forceinline__ void ldmat4(uint32_t r[4], uint32_t addr){
    asm volatile("ldmatrix.sync.aligned.m8n8.x4.shared.b16 {%0,%1,%2,%3}, [%4];"
        : "=r"(r[0]), "=r"(r[1]), "=r"(r[2]), "=r"(r[3]) : "r"(addr));
}
__device__ __forceinline__ void mma16816(float c[4], const uint32_t a[4],
                                         uint32_t b0, uint32_t b1){
    asm volatile("mma.sync.aligned.m16n8k16.row.col.f32.f16.f16.f32 "
        "{%0,%1,%2,%3}, {%4,%5,%6,%7}, {%8,%9}, {%0,%1,%2,%3};"
        : "+f"(c[0]), "+f"(c[1]), "+f"(c[2]), "+f"(c[3])
        : "r"(a[0]), "r"(a[1]), "r"(a[2]), "r"(a[3]), "r"(b0), "r"(b1));
}

// smem tile layout: padded stride 72 fp16 (144B = 9 x 16B -> conflict-free)
#define ASTRIDE 72
#define OFF_AH  0
#define OFF_AL  18432
#define OFF_BH  36864
#define GEMM_SMEM 46080

// ---- 128x64x256 tile: fp16 2-term split via mma.sync, fp32 accumulate -----
__device__ void tile_mma(const __half* __restrict__ Ah,
                         const __half* __restrict__ Al,
                         const __half* __restrict__ Bh,
                         int m0, float acc[2][4][4])
{
    extern __shared__ char smem[];
    const uint32_t sb = smem_u32(smem);
    const int tid = threadIdx.x;
    const int lane = tid & 31;
    const int wid = tid >> 5;
    const int wm = wid & 3;        // m32 section
    const int wn = wid >> 2;       // n32 section

    #pragma unroll
    for (int mt = 0; mt < 2; ++mt)
        #pragma unroll
        for (int nt = 0; nt < 4; ++nt)
            #pragma unroll
            for (int q = 0; q < 4; ++q) acc[mt][nt][q] = 0.f;

    const uint32_t aoff = (uint32_t)(((lane & 15)*ASTRIDE + (lane >> 4)*8) * 2);
    const uint32_t boff = (uint32_t)((((lane & 7) + ((lane >> 4) << 3))*ASTRIDE
                                      + ((lane >> 3) & 1)*8) * 2);

    #pragma unroll 1
    for (int kc = 0; kc < 4; ++kc) {
        #pragma unroll
        for (int i = 0; i < 10; ++i) {
            int v = tid + i*256;
            const uint4* src;
            uint32_t dst;
            if (v < 1024) {
                int row = v >> 3, c8 = v & 7;
                src = (const uint4*)(Ah + (m0 + row)*CDIM + kc*64 + c8*8);
                dst = OFF_AH + (uint32_t)(row*ASTRIDE + c8*8)*2;
            } else if (v < 2048) {
                int u = v - 1024, row = u >> 3, c8 = u & 7;
                src = (const uint4*)(Al + (m0 + row)*CDIM + kc*64 + c8*8);
                dst = OFF_AL + (uint32_t)(row*ASTRIDE + c8*8)*2;
            } else {
                int u = v - 2048, row = u >> 3, c8 = u & 7;
                src = (const uint4*)(Bh + row*CDIM + kc*64 + c8*8);
                dst = OFF_BH + (uint32_t)(row*ASTRIDE + c8*8)*2;
            }
            *(uint4*)(smem + dst) = *src;
        }
        __syncthreads();

        #pragma unroll
        for (int ks = 0; ks < 4; ++ks) {
            const uint32_t abase = (uint32_t)((wm*32*ASTRIDE + ks*16) * 2);
            const uint32_t bbase = (uint32_t)((wn*32*ASTRIDE + ks*16) * 2);
            const uint32_t mstep = (uint32_t)(16*ASTRIDE*2);

            uint32_t ah0[4], ah1[4], al0[4], al1[4];
            ldmat4(ah0, sb + OFF_AH + abase + aoff);
            ldmat4(ah1, sb + OFF_AH + abase + mstep + aoff);
            ldmat4(al0, sb + OFF_AL + abase + aoff);
            ldmat4(al1, sb + OFF_AL + abase + mstep + aoff);

            uint32_t bhA[4], bhB[4];
            ldmat4(bhA, sb + OFF_BH + bbase + boff);
            ldmat4(bhB, sb + OFF_BH + bbase + mstep + boff);

            mma16816(acc[0][0], ah0, bhA[0], bhA[1]);
            mma16816(acc[0][1], ah0, bhA[2], bhA[3]);
            mma16816(acc[0][2], ah0, bhB[0], bhB[1]);
            mma16816(acc[0][3], ah0, bhB[2], bhB[3]);
            mma16816(acc[1][0], ah1, bhA[0], bhA[1]);
            mma16816(acc[1][1], ah1, bhA[2], bhA[3]);
            mma16816(acc[1][2], ah1, bhB[0], bhB[1]);
            mma16816(acc[1][3], ah1, bhB[2], bhB[3]);

            mma16816(acc[0][0], al0, bhA[0], bhA[1]);
            mma16816(acc[0][1], al0, bhA[2], bhA[3]);
            mma16816(acc[0][2], al0, bhB[0], bhB[1]);
            mma16816(acc[0][3], al0, bhB[2], bhB[3]);
            mma16816(acc[1][0], al1, bhA[0], bhA[1]);
            mma16816(acc[1][1], al1, bhA[2], bhA[3]);
            mma16816(acc[1][2], al1, bhB[0], bhB[1]);
            mma16816(acc[1][3], al1, bhB[2], bhB[3]);
        }
        __syncthreads();
    }
}

// GEMM1: by 0..3 -> m = relu(h Wmlp^T + b) (fp16);  by 4..7 -> tmp = h Wa^T
__global__ void __launch_bounds__(256) gemm1_kernel(const float* __restrict__ mlp_b,
                                                    float* __restrict__ tmp_out)
{
    int m0 = blockIdx.x * 128;
    int by = blockIdx.y;
    bool is_m = by < 4;
    int d0 = (is_m ? by : by - 4) * 64;
    const __half* Bh = (is_m ? g_Wmh : g_Wah) + d0*CDIM;

    float acc[2][4][4];
    tile_mma(g_Ah, g_Al, Bh, m0, acc);

    int lane = threadIdx.x & 31, wid = threadIdx.x >> 5;
    int wm = wid & 3, wn = wid >> 2;
    int g = lane >> 2, t = lane & 3;

    #pragma unroll
    for (int mt = 0; mt < 2; ++mt) {
        #pragma unroll
        for (int nt = 0; nt < 4; ++nt) {
            int nl = wn*32 + nt*8 + t*2;
            int n = d0 + nl;
            float bx = 0.f, byv = 0.f;
            if (is_m) { bx = mlp_b[n]; byv = mlp_b[n+1]; }
            #pragma unroll
            for (int half = 0; half < 2; ++half) {
                int m = m0 + wm*32 + mt*16 + g + half*8;
                if (m >= M_TOTAL) continue;
                float vx = acc[mt][nt][half*2+0];
                float vy = acc[mt][nt][half*2+1];
                if (is_m) {
                    vx = fmaxf(vx + bx, 0.f);
                    vy = fmaxf(vy + byv, 0.f);
                    *(__half2*)(g_m + m*CDIM + n) =
                        __halves2half2(__float2half_rn(vx), __float2half_rn(vy));
                } else {
                    *(float2*)(tmp_out + m*CDIM + n) = make_float2(vx, vy);
                }
            }
        }
    }
}

// GEMM3: h' = relu(tmp + msg Wb^T + b_rnn); writes fp32 h and fp16 split
__global__ void __launch_bounds__(256) gemm3_kernel(const float* __restrict__ rnn_b,
                                                    const float* __restrict__ tmp,
                                                    float* __restrict__ h_out)
{
    int m0 = blockIdx.x * 128;
    int d0 = blockIdx.y * 64;

    float acc[2][4][4];
    tile_mma(g_Mh, g_Ml, g_Wbh + d0*CDIM, m0, acc);

    int lane = threadIdx.x & 31, wid = threadIdx.x >> 5;
    int wm = wid & 3, wn = wid >> 2;
    int g = lane >> 2, t = lane & 3;

    #pragma unroll
    for (int mt = 0; mt < 2; ++mt) {
        #pragma unroll
        for (int nt = 0; nt < 4; ++nt) {
            int n = d0 + wn*32 + nt*8 + t*2;
            float bx = rnn_b[n], byv = rnn_b[n+1];
            #pragma unroll
            for (int half = 0; half < 2; ++half) {
                int m = m0 + wm*32 + mt*16 + g + half*8;
                if (m >= M_TOTAL) continue;
                float2 tv = *(const float2*)(tmp + m*CDIM + n);
                float vx = fmaxf(acc[mt][nt][half*2+0] + tv.x + bx, 0.f);
                float vy = fmaxf(acc[mt][nt][half*2+1] + tv.y + byv, 0.f);
                *(float2*)(h_out + m*CDIM + n) = make_float2(vx, vy);
                __half hx, lx, hy, ly;
                hsplit(vx, hx, lx); hsplit(vy, hy, ly);
                *(__half2*)(g_Ah + m*CDIM + n) = __halves2half2(hx, hy);
                *(__half2*)(g_Al + m*CDIM + n) = __halves2half2(lx, ly);
            }
        }
    }
}

// -------- weight conversion + pad-row zeroing (once per call) --------------
__global__ void __launch_bounds__(256) wconv_kernel(const float* __restrict__ mlp_w,
                                                    const float* __restrict__ rnn_w)
{
    int e = blockIdx.x * 256 + threadIdx.x;   // < 256*768
    if (e < CDIM*CDIM) {
        g_Wmh[e] = __float2half_rn(mlp_w[e]);
    } else {
        int u = e - CDIM*CDIM;                 // < 256*512
        int r = u >> 9, c = u & 511;
        __half h = __float2half_rn(rnn_w[u]);
        if (c < CDIM) g_Wah[r*CDIM + c] = h;
        else          g_Wbh[r*CDIM + c - CDIM] = h;
    }
    if (e < (MPAD - M_TOTAL)*CDIM) {           // zero pad rows (96*256)
        int o = M_TOTAL*CDIM + e;
        g_Ah[o] = __float2half(0.f); g_Al[o] = __float2half(0.f);
        g_Mh[o] = __float2half(0.f); g_Ml[o] = __float2half(0.f);
    }
}

// -- cnn (n,c,s) -> Ah/Al (n,s,c) fp16 split + out[:, :256] copy (fused) ----
__global__ void __launch_bounds__(256) tin_kernel(const float* __restrict__ cnn,
                                                  float* __restrict__ out)
{
    __shared__ float tile[32][65];                   // [s_l][c_l], pad 65
    int s0 = blockIdx.x * 32;
    int c0 = blockIdx.y * 64;
    int bn = blockIdx.z;
    const float* src = cnn + ((size_t)bn*CDIM + c0)*HWP + s0;
    float* dst = out + ((size_t)bn*(2*CDIM) + c0)*HWP + s0;

    #pragma unroll
    for (int i = 0; i < 8; ++i) {
        int flat = threadIdx.x + i*256;              // 0..2047
        int s_l = flat & 31, c_l = flat >> 5;
        float v = 0.f;
        if (s0 + s_l < HWP) {
            v = src[(size_t)c_l*HWP + s_l];
            dst[(size_t)c_l*HWP + s_l] = v;          // out[:, :256] = cnn
        }
        tile[s_l][c_l] = v;
    }
    __syncthreads();

    #pragma unroll
    for (int i = 0; i < 4; ++i) {
        int flat = threadIdx.x + i*256;              // 0..1023 (half2 units)
        int cp = flat & 31;                          // c = cp*2
        int s_l = flat >> 5;
        int s = s0 + s_l;
        if (s >= HWP) continue;
        float v0 = tile[s_l][cp*2], v1 = tile[s_l][cp*2+1];
        __half h0, l0, h1, l1;
        hsplit(v0, h0, l0); hsplit(v1, h1, l1);
        int o = (bn*HWP + s)*CDIM + c0 + cp*2;
        *(__half2*)(g_Ah + o) = __halves2half2(h0, h1);
        *(__half2*)(g_Al + o) = __halves2half2(l0, l1);
    }
}

// ------- h (n,s,c) -> out[:, 256:512] (n,c,s), smem tile transpose ---------
__global__ void __launch_bounds__(256) tout_kernel(const float* __restrict__ h,
                                                   float* __restrict__ out)
{
    __shared__ float tile[64][33];                   // [c_l][s_l], pad 33
    int s0 = blockIdx.x * 32;
    int c0 = blockIdx.y * 64;
    int bn = blockIdx.z;

    #pragma unroll
    for (int i = 0; i < 8; ++i) {
        int flat = threadIdx.x + i*256;
        int c_l = flat & 63, s_l = flat >> 6;        // s_l 0..31
        int s = s0 + s_l;
        float v = 0.f;
        if (s < HWP) v = h[((size_t)bn*HWP + s)*CDIM + c0 + c_l];
        tile[c_l][s_l] = v;
    }
    __syncthreads();

    #pragma unroll
    for (int i = 0; i < 8; ++i) {
        int flat = threadIdx.x + i*256;
        int s_l = flat & 31, c_l = flat >> 5;        // c_l 0..63
        int s = s0 + s_l;
        if (s < HWP)
            out[((size_t)bn*(2*CDIM) + CDIM + c0 + c_l)*HWP + s] = tile[c_l][s_l];
    }
}

// ---------------- KNN v6: candidate-major, 4 rows/block, 4 blocks/SM -------
#define KNN_BR 4
#define CAP 192
// dynamic smem layout (bytes)
#define KPX    0                        // float[3600]  14400
#define KPY    14400
#define KPZ    28800                    // end 43200
#define KHIST  43200                    // int[4][256]   4096
#define KCV    47296                    // u32[4][CAP]   3072
#define KCI    50368                    // int[4][CAP]   3072
#define KTIE   53440                    // int[4][32]     512
#define KOCNT  53952                    // int[4]
#define KCCNT  53968                    // int[4]
#define KECRIT 53984                    // int[4]
#define KFLAG  54000                    // int[4]
#define KWS    54016                    // int[2][8]
#define KSC    54080                    // int[4]
#define KNN_SMEM 54144

__global__ void __launch_bounds__(256) knn_kernel(const float* __restrict__ pts,
                                                  int* __restrict__ idx_out)
{
    extern __shared__ char sm[];
    float* px = (float*)(sm + KPX);
    float* py = (float*)(sm + KPY);
    float* pz = (float*)(sm + KPZ);
    int* hist = (int*)(sm + KHIST);
    unsigned* cv = (unsigned*)(sm + KCV);
    int* ci = (int*)(sm + KCI);
    int* tiebuf = (int*)(sm + KTIE);
    int* ocnt  = (int*)(sm + KOCNT);
    int* ccnt  = (int*)(sm + KCCNT);
    int* ecrit = (int*)(sm + KECRIT);
    int* flag  = (int*)(sm + KFLAG);
    int* ws    = (int*)(sm + KWS);
    int* sc    = (int*)(sm + KSC);

    int gb = blockIdx.x;
    int n  = gb / (HWP/KNN_BR);
    int g  = gb % (HWP/KNN_BR);
    int tid = threadIdx.x;
    int lane = tid & 31, wid = tid >> 5;
    const unsigned ltm = (1u << lane) - 1u;

    const float* p = pts + n*3*HWP;
    for (int i = tid; i < HWP; i += 256) {
        px[i] = p[i];
        py[i] = p[i + HWP];
        pz[i] = p[i + 2*HWP];
    }
    #pragma unroll
    for (int i = 0; i < KNN_BR; ++i) hist[i*256 + tid] = 0;
    if (tid < KNN_BR) { ocnt[tid] = 0; ccnt[tid] = 0; flag[tid] = 0; }
    __syncthreads();                                   // B0

    // query coords in registers
    float qx[KNN_BR], qy[KNN_BR], qz[KNN_BR], qs[KNN_BR];
    #pragma unroll
    for (int r = 0; r < KNN_BR; ++r) {
        int row = g*KNN_BR + r;
        qx[r] = px[row]; qy[r] = py[row]; qz[r] = pz[row];
        qs[r] = fmaf(qz[r], qz[r], fmaf(qy[r], qy[r], qx[r]*qx[r]));
    }

    // ---- pass 1: candidate-major, build histograms -------------------------
    #pragma unroll 1
    for (int t = 0; t < 15; ++t) {
        int j = t*256 + tid;
        bool v = j < HWP;
        float x = 0.f, y = 0.f, z = 0.f, sj = 0.f;
        if (v) { x = px[j]; y = py[j]; z = pz[j]; sj = fmaf(z, z, fmaf(y, y, x*x)); }
        #pragma unroll
        for (int r = 0; r < KNN_BR; ++r) {
            unsigned bits = 0x7f800000u;
            if (v) {
                float dot = fmaf(qz[r], z, fmaf(qy[r], y, qx[r]*x));
                bits = __float_as_uint(fmaxf(qs[r] + sj - 2.0f*dot, 0.0f));
            }
            unsigned e = bits >> 23;
            unsigned mask = __match_any_sync(0xffffffffu, e);
            if (lane == (unsigned)(__ffs(mask) - 1)) atomicAdd(&hist[r*256 + e], __popc(mask));
        }
    }
    __syncthreads();                                   // B1

    // ---- scan: warp w scans hist[w] ----------------------------------------
    if (wid < KNN_BR) {
        int* h4 = hist + wid*256;
        int basebin = lane*8, loc[8], ssum = 0;
        #pragma unroll
        for (int j2 = 0; j2 < 8; ++j2) { loc[j2] = h4[basebin + j2]; ssum += loc[j2]; }
        int pre = ssum;
        #pragma unroll
        for (int o = 1; o < 32; o <<= 1) {
            int v2 = __shfl_up_sync(0xffffffffu, pre, o);
            if (lane >= (unsigned)o) pre += v2;
        }
        int excl = pre - ssum;
        int ec = 0;
        if (excl < KNN && excl + ssum >= KNN) {        // unique crossing lane
            int cum = excl;
            #pragma unroll
            for (int j2 = 0; j2 < 8; ++j2) {
                if (cum + loc[j2] >= KNN) { ec = basebin + j2; break; }
                cum += loc[j2];
            }
        }
        ec = __reduce_max_sync(0xffffffffu, ec);
        if (lane == 0) ecrit[wid] = ec;
    }
    __syncthreads();                                   // B2

    int Ereg[KNN_BR];
    #pragma unroll
    for (int r = 0; r < KNN_BR; ++r) Ereg[r] = ecrit[r];

    // ---- pass 2: recompute, ballot-aggregated compaction -------------------
    #pragma unroll 1
    for (int t = 0; t < 15; ++t) {
        int j = t*256 + tid;
        bool v = j < HWP;
        float x = 0.f, y = 0.f, z = 0.f, sj = 0.f;
        if (v) { x = px[j]; y = py[j]; z = pz[j]; sj = fmaf(z, z, fmaf(y, y, x*x)); }
        #pragma unroll
        for (int r = 0; r < KNN_BR; ++r) {
            unsigned bits = 0x7f800000u;
            if (v) {
                float dot = fmaf(qz[r], z, fmaf(qy[r], y, qx[r]*x));
                bits = __float_as_uint(fmaxf(qs[r] + sj - 2.0f*dot, 0.0f));
            }
            int e = (int)(bits >> 23);
            bool win = v && e < Ereg[r];
            unsigned mw = __ballot_sync(0xffffffffu, win);
            if (mw) {
                int src = __ffs(mw) - 1;
                int base = 0;
                if (lane == (unsigned)src) base = atomicAdd(&ocnt[r], __popc(mw));
                base = __shfl_sync(0xffffffffu, base, src);
                if (win) idx_out[(n*HWP + g*KNN_BR + r)*KNN + base + __popc(mw & ltm)] = j;
            }
            bool cand = v && e == Ereg[r];
            unsigned mc = __ballot_sync(0xffffffffu, cand);
            if (mc) {
                int src = __ffs(mc) - 1;
                int base = 0;
                if (lane == (unsigned)src) base = atomicAdd(&ccnt[r], __popc(mc));
                base = __shfl_sync(0xffffffffu, base, src);
                if (cand) {
                    int pos = base + __popc(mc & ltm);
                    if (pos < CAP) { cv[r*CAP + pos] = bits; ci[r*CAP + pos] = j; }
                }
            }
        }
    }
    __syncthreads();                                   // B3

    // ---- phase B: one row per warp (warps 0..3) ------------------------------
    if (wid < KNN_BR) {
        int r = wid;
        int row = g*KNN_BR + r;
        int* outp = idx_out + (n*HWP + row)*KNN;
        unsigned* wcv = cv + r*CAP;
        int* wci = ci + r*CAP;
        int* wtie = tiebuf + r*32;

        int oc0 = ocnt[r], cc = ccnt[r];
        int Kp = KNN - oc0;

        if (cc > CAP) {
            if (lane == 0) flag[r] = 1;
        } else if (cc == Kp) {
            for (int i = lane; i < cc; i += 32) outp[oc0 + i] = wci[i];
        } else {
            unsigned T = ((unsigned)Ereg[r]) << 23;
            for (int bit = 22; bit >= 0; --bit) {
                unsigned cnd = T | (1u << bit);
                int cnt = 0;
                for (int i = lane; i < cc; i += 32) cnt += (wcv[i] < cnd) ? 1 : 0;
                cnt = __reduce_add_sync(0xffffffffu, cnt);
                if (cnt < Kp) T = cnd;
            }
            int oc = oc0, tc = 0;
            for (int ib = 0; ib < cc; ib += 32) {
                int i = ib + lane;
                bool v = i < cc;
                unsigned bv = v ? wcv[i] : 0xffffffffu;
                unsigned mw = __ballot_sync(0xffffffffu, v && bv < T);
                if (v && bv < T) outp[oc + __popc(mw & ltm)] = wci[i];
                oc += __popc(mw);
                unsigned mt = __ballot_sync(0xffffffffu, v && bv == T);
                if (v && bv == T) {
                    int tp = tc + __popc(mt & ltm);
                    if (tp < 32) wtie[tp] = wci[i];
                }
                tc += __popc(mt);
            }
            __syncwarp();
            if (lane == 0) {
                int slots = KNN - oc;
                int en = tc < 32 ? tc : 32;
                for (int q2 = 0; q2 < slots; ++q2) {   // lowest-index tie fill
                    int best = 0x7fffffff, bi = 0;
                    for (int e2 = 0; e2 < en; ++e2)
                        if (wtie[e2] < best) { best = wtie[e2]; bi = e2; }
                    wtie[bi] = 0x7fffffff;
                    outp[oc + q2] = best;
                }
            }
        }
    }
    __syncthreads();

    // ---- fallback: block-wide 31-bit search (rare) --------------------------
    for (int r = 0; r < KNN_BR; ++r) {
        if (!flag[r]) continue;
        int row = g*KNN_BR + r;
        float fqx = qx[r], fqy = qy[r], fqz = qz[r], fqs = qs[r];

        unsigned d[15];
        #pragma unroll
        for (int t = 0; t < 15; ++t) {
            int j = t*256 + tid;
            if (j < HWP) {
                float x = px[j], y = py[j], z = pz[j];
                float sj  = fmaf(z, z, fmaf(y, y, x*x));
                float dot = fmaf(fqz, z, fmaf(fqy, y, fqx*x));
                d[t] = __float_as_uint(fmaxf(fqs + sj - 2.0f*dot, 0.0f));
            } else {
                d[t] = 0xffffffffu;
            }
        }
        if (tid == 0) { sc[0] = 0; sc[1] = 0; }
        __syncthreads();

        unsigned T = 0;
        for (int bit = 30; bit >= 0; --bit) {
            unsigned cnd = T | (1u << bit);
            int cc2 = 0;
            #pragma unroll
            for (int t = 0; t < 15; ++t) cc2 += (d[t] < cnd) ? 1 : 0;
            cc2 = __reduce_add_sync(0xffffffffu, cc2);
            int par = bit & 1;
            if (lane == 0) ws[par*8 + wid] = cc2;
            __syncthreads();
            int tot = 0;
            #pragma unroll
            for (int w = 0; w < 8; ++w) tot += ws[par*8 + w];
            if (tot < KNN) T = cnd;
        }
        __syncthreads();

        int* outp = idx_out + (n*HWP + row)*KNN;
        int* wtie = tiebuf + r*32;
        #pragma unroll
        for (int t = 0; t < 15; ++t) {
            int j = t*256 + tid;
            unsigned dv = d[t];
            if (dv < T) { int pos = atomicAdd(&sc[0], 1); outp[pos] = j; }
            else if (dv == T && j < HWP) { int pos = atomicAdd(&sc[1], 1); if (pos < 32) wtie[pos] = j; }
        }
        __syncthreads();
        if (tid == 0) {
            int slots = KNN - sc[0];
            int en = sc[1] < 32 ? sc[1] : 32;
            for (int q2 = 0; q2 < slots; ++q2) {
                int best = 0x7fffffff, bi = 0;
                for (int e2 = 0; e2 < en; ++e2)
                    if (wtie[e2] < best) { best = wtie[e2]; bi = e2; }
                wtie[bi] = 0x7fffffff;
                outp[sc[0] + q2] = best;
            }
        }
        __syncthreads();
    }
}

// ------- gather-mean v3: 16 pts/block, 32 thr/pt, 16B loads ----------------
__global__ void __launch_bounds__(512) gather_mean_kernel(const int* __restrict__ idx)
{
    __shared__ int sidx[16*KNN];
    int tid = threadIdx.x;
    int s0 = blockIdx.x * 16;
    sidx[tid]       = idx[s0*KNN + tid];
    sidx[tid + 512] = idx[s0*KNN + tid + 512];
    __syncthreads();

    int lp = tid >> 5;          // 0..15 local point
    int lane = tid & 31;        // 16B chunk (8 halves) within row
    int s = s0 + lp;
    int base = (s / HWP) * HWP;
    const uint4* m4 = reinterpret_cast<const uint4*>(g_m);   // 32 uint4 per row
    const int* ip = sidx + lp*KNN;

    float acc[8];
    #pragma unroll
    for (int i = 0; i < 8; ++i) acc[i] = 0.f;

    #pragma unroll
    for (int k = 0; k < KNN; k += 4) {
        int j0 = ip[k], j1 = ip[k+1], j2 = ip[k+2], j3 = ip[k+3];
        uint4 u0 = m4[(size_t)(base + j0)*32 + lane];
        uint4 u1 = m4[(size_t)(base + j1)*32 + lane];
        uint4 u2 = m4[(size_t)(base + j2)*32 + lane];
        uint4 u3 = m4[(size_t)(base + j3)*32 + lane];
        #pragma unroll
        for (int q = 0; q < 4; ++q) {
            uint4 u = (q == 0) ? u0 : (q == 1) ? u1 : (q == 2) ? u2 : u3;
            float2 f0 = __half22float2(*(__half2*)&u.x);
            float2 f1 = __half22float2(*(__half2*)&u.y);
            float2 f2 = __half22float2(*(__half2*)&u.z);
            float2 f3 = __half22float2(*(__half2*)&u.w);
            acc[0] += f0.x; acc[1] += f0.y; acc[2] += f1.x; acc[3] += f1.y;
            acc[4] += f2.x; acc[5] += f2.y; acc[6] += f3.x; acc[7] += f3.y;
        }
    }
    const float inv = 1.0f / 64.0f;
    __half hh[8], ll[8];
    #pragma unroll
    for (int i = 0; i < 8; ++i) hsplit(acc[i]*inv, hh[i], ll[i]);

    int o = s*CDIM + lane*8;
    __half2 mh0 = __halves2half2(hh[0], hh[1]), mh1 = __halves2half2(hh[2], hh[3]);
    __half2 mh2 = __halves2half2(hh[4], hh[5]), mh3 = __halves2half2(hh[6], hh[7]);
    __half2 ml0 = __halves2half2(ll[0], ll[1]), ml1 = __halves2half2(ll[2], ll[3]);
    __half2 ml2 = __halves2half2(ll[4], ll[5]), ml3 = __halves2half2(ll[6], ll[7]);
    uint4 sh, sl;
    sh.x = *(uint32_t*)&mh0; sh.y = *(uint32_t*)&mh1;
    sh.z = *(uint32_t*)&mh2; sh.w = *(uint32_t*)&mh3;
    sl.x = *(uint32_t*)&ml0; sl.y = *(uint32_t*)&ml1;
    sl.z = *(uint32_t*)&ml2; sl.w = *(uint32_t*)&ml3;
    *(uint4*)(g_Mh + o) = sh;
    *(uint4*)(g_Ml + o) = sl;
}

// ---------------- launcher --------------------------------------------------
extern "C" void kernel_launch(void* const* d_in, const int* in_sizes, int n_in,
                              void* d_out, int out_size)
{
    const float* cnn   = (const float*)d_in[0];
    const float* pts   = (const float*)d_in[1];
    const float* mlp_w = (const float*)d_in[2];
    const float* mlp_b = (const float*)d_in[3];
    const float* rnn_w = (const float*)d_in[4];
    const float* rnn_b = (const float*)d_in[5];
    float* out = (float*)d_out;

    float *tmp, *h;
    int* idx;
    cudaGetSymbolAddress((void**)&tmp, g_tmp);
    cudaGetSymbolAddress((void**)&h,   g_h);
    cudaGetSymbolAddress((void**)&idx, g_idx);

    cudaFuncSetAttribute(gemm1_kernel, cudaFuncAttributeMaxDynamicSharedMemorySize, GEMM_SMEM);
    cudaFuncSetAttribute(gemm3_kernel, cudaFuncAttributeMaxDynamicSharedMemorySize, GEMM_SMEM);
    cudaFuncSetAttribute(knn_kernel,   cudaFuncAttributeMaxDynamicSharedMemorySize, KNN_SMEM);

    wconv_kernel<<<768, 256>>>(mlp_w, rnn_w);
    tin_kernel<<<dim3(113, 4, 2), 256>>>(cnn, out);
    knn_kernel<<<NBATCH*(HWP/KNN_BR), 256, KNN_SMEM>>>(pts, idx);

    for (int it = 0; it < 3; ++it) {
        gemm1_kernel<<<dim3(MPAD/128, 8), 256, GEMM_SMEM>>>(mlp_b, tmp);
        gather_mean_kernel<<<M_TOTAL/16, 512>>>(idx);
        gemm3_kernel<<<dim3(MPAD/128, 4), 256, GEMM_SMEM>>>(rnn_b, tmp, h);
    }
    tout_kernel<<<dim3(113, 4, 2), 256>>>(h, out);
}